// round 4
// baseline (speedup 1.0000x reference)
#include <cuda_runtime.h>

#define E_ 28
#define H_ 4
#define HD_ 7
#define FF_ 256
#define LMAX_ 8
#define T_ 512
#define B_ 64
#define S_ 4096
#define NSPANS (B_ * T_)

// ---- shared memory layout (floats) ----
#define OFF_WQKV 0          // 84*28 = 2352
#define OFF_BQKV 2352       // 84
#define OFF_WO   2436       // 28*28 = 784
#define OFF_BO   3220       // 28
#define OFF_G1   3248       // 28
#define OFF_B1L  3276       // 28
#define OFF_W1   3304       // 256*28 = 7168
#define OFF_B1   10472      // 256
#define OFF_W2T  10728      // 256*28 = 7168  (TRANSPOSED: row f = 28 contiguous floats)
#define OFF_B2   17896      // 28
#define OFF_G2   17924      // 28
#define OFF_B2L  17952      // 28
#define OFF_PAD  17980      // 28
#define OFF_SCR  18008
#define SCR_PER_WARP 672    // A[224] | Kb[224] | Vb[224]
#define SMEM_FLOATS (OFF_SCR + 8 * SCR_PER_WARP)   // 23384
#define SMEM_BYTES  (SMEM_FLOATS * 4)              // 93536

__device__ __forceinline__ void cp_f4(float* dst, const float* src, int nfloats) {
    const int n4 = nfloats >> 2;
    for (int i = threadIdx.x; i < n4; i += blockDim.x)
        reinterpret_cast<float4*>(dst)[i] = reinterpret_cast<const float4*>(src)[i];
}

// dot of 28-elem register vector x with 28-elem smem row w (float4-vectorized weight loads)
__device__ __forceinline__ float dot28r(const float* x, const float* w) {
    const float4* w4 = reinterpret_cast<const float4*>(w);
    float acc = 0.0f;
#pragma unroll
    for (int j = 0; j < 7; j++) {
        float4 b = w4[j];
        acc = fmaf(x[4 * j + 0], b.x, acc);
        acc = fmaf(x[4 * j + 1], b.y, acc);
        acc = fmaf(x[4 * j + 2], b.z, acc);
        acc = fmaf(x[4 * j + 3], b.w, acc);
    }
    return acc;
}

__global__ __launch_bounds__(256, 2)
void span_transformer_kernel(
    const float* __restrict__ emb,
    const int*   __restrict__ span_lengths,
    const int*   __restrict__ num_spans,
    const float* __restrict__ in_proj_w, const float* __restrict__ in_proj_b,
    const float* __restrict__ out_proj_w, const float* __restrict__ out_proj_b,
    const float* __restrict__ ln1_g, const float* __restrict__ ln1_b,
    const float* __restrict__ lin1_w, const float* __restrict__ lin1_b,
    const float* __restrict__ lin2_w, const float* __restrict__ lin2_b,
    const float* __restrict__ ln2_g, const float* __restrict__ ln2_b,
    const float* __restrict__ pad_token,
    float* __restrict__ outp)
{
    extern __shared__ float sm[];

    // ---- cooperative weight staging ----
    cp_f4(sm + OFF_WQKV, in_proj_w, 2352);
    cp_f4(sm + OFF_BQKV, in_proj_b, 84);
    cp_f4(sm + OFF_WO,   out_proj_w, 784);
    cp_f4(sm + OFF_BO,   out_proj_b, 28);
    cp_f4(sm + OFF_G1,   ln1_g, 28);
    cp_f4(sm + OFF_B1L,  ln1_b, 28);
    cp_f4(sm + OFF_W1,   lin1_w, 7168);
    cp_f4(sm + OFF_B1,   lin1_b, 256);
    // lin2_w is [28][256]; stage TRANSPOSED so column f becomes a contiguous
    // 28-float (112B, 16B-aligned) row.
    for (int i = threadIdx.x; i < 7168; i += blockDim.x) {
        int e = i >> 8;        // source row    (0..27)
        int f = i & 255;       // source column (0..255)
        sm[OFF_W2T + f * 28 + e] = lin2_w[i];
    }
    cp_f4(sm + OFF_B2,   lin2_b, 28);
    cp_f4(sm + OFF_G2,   ln2_g, 28);
    cp_f4(sm + OFF_B2L,  ln2_b, 28);
    cp_f4(sm + OFF_PAD,  pad_token, 28);
    __syncthreads();

    const int warp = threadIdx.x >> 5;
    const int lane = threadIdx.x & 31;
    const int l = lane & 7;      // token within span (layout A)
    const int h = lane >> 3;     // head / E-slice index (layout A)
    const int e0 = h * 7;        // start of this thread's E-slice

    // layout B (FFN): 8 f-groups x 4 token-slots, 2 tokens/thread
    const int fg  = lane & 7;
    const int tk2 = lane >> 3;   // tokens tk2 and tk2+4

    float* A  = sm + OFF_SCR + warp * SCR_PER_WARP;  // x row-major [8][28] (then xn)
    float* Kb = A + 224;                             // k [8][28] (then ao)
    float* Vb = A + 448;                             // v [8][28]

    const int warps_total = gridDim.x * 8;
    for (int span = blockIdx.x * 8 + warp; span < NSPANS; span += warps_total) {
        const int b = span >> 9;
        const int t = span & (T_ - 1);

        // ---- load x: span covers 224 contiguous floats of emb ----
        {
            const float4* src = reinterpret_cast<const float4*>(emb + b * (S_ * E_) + t * 224);
            float4* A4 = reinterpret_cast<float4*>(A);
            A4[lane] = src[lane];
            if (lane < 24) A4[lane + 32] = src[lane + 32];
        }
        __syncwarp();

        // ---- QKV projection (each thread: its head-slice of q,k,v for its token) ----
        float xr[28];
        {
            const float4* r4 = reinterpret_cast<const float4*>(A + l * 28);
#pragma unroll
            for (int j = 0; j < 7; j++) {
                float4 v = r4[j];
                xr[4 * j] = v.x; xr[4 * j + 1] = v.y; xr[4 * j + 2] = v.z; xr[4 * j + 3] = v.w;
            }
        }
        float q[7];
#pragma unroll
        for (int d = 0; d < 7; d++) {
            const int rq = e0 + d;
            q[d]        = sm[OFF_BQKV + rq]      + dot28r(xr, sm + OFF_WQKV + rq * 28);
            float kk    = sm[OFF_BQKV + 28 + rq] + dot28r(xr, sm + OFF_WQKV + (28 + rq) * 28);
            float vv    = sm[OFF_BQKV + 56 + rq] + dot28r(xr, sm + OFF_WQKV + (56 + rq) * 28);
            Kb[l * 28 + rq] = kk;
            Vb[l * 28 + rq] = vv;
        }
        __syncwarp();

        // ---- attention within span (8x8, per head = per thread slice) ----
        const int len = span_lengths[b * T_ + t];
        float s[8];
#pragma unroll
        for (int kk = 0; kk < 8; kk++) {
            const float* kr = Kb + kk * 28 + e0;
            float acc = 0.0f;
#pragma unroll
            for (int d = 0; d < 7; d++) acc = fmaf(q[d], kr[d], acc);
            s[kk] = (kk < len) ? acc * 0.3779644730092272f : -1e9f;
        }
        float mx = s[0];
#pragma unroll
        for (int kk = 1; kk < 8; kk++) mx = fmaxf(mx, s[kk]);
        float p[8], psum = 0.0f;
#pragma unroll
        for (int kk = 0; kk < 8; kk++) { p[kk] = __expf(s[kk] - mx); psum += p[kk]; }
        const float pinv = 1.0f / psum;

        float ao[7];
#pragma unroll
        for (int d = 0; d < 7; d++) {
            float acc = 0.0f;
#pragma unroll
            for (int kk = 0; kk < 8; kk++) acc = fmaf(p[kk], Vb[kk * 28 + e0 + d], acc);
            ao[d] = acc * pinv;
        }
        __syncwarp();   // all score/AV reads of Kb done before overwrite
#pragma unroll
        for (int d = 0; d < 7; d++) Kb[l * 28 + e0 + d] = ao[d];
        __syncwarp();

        // ---- out projection + residual + LN1 ----
        float aor[28];
        {
            const float4* r4 = reinterpret_cast<const float4*>(Kb + l * 28);
#pragma unroll
            for (int j = 0; j < 7; j++) {
                float4 v = r4[j];
                aor[4 * j] = v.x; aor[4 * j + 1] = v.y; aor[4 * j + 2] = v.z; aor[4 * j + 3] = v.w;
            }
        }
        float y[7];
#pragma unroll
        for (int d = 0; d < 7; d++) {
            const int ep = e0 + d;
            float o = sm[OFF_BO + ep] + dot28r(aor, sm + OFF_WO + ep * 28);
            y[d] = A[l * 28 + ep] + o;
        }
        float s1 = 0.0f;
#pragma unroll
        for (int d = 0; d < 7; d++) s1 += y[d];
        s1 += __shfl_xor_sync(0xffffffffu, s1, 8);
        s1 += __shfl_xor_sync(0xffffffffu, s1, 16);
        const float mu1 = s1 * (1.0f / 28.0f);
        float s2 = 0.0f;
#pragma unroll
        for (int d = 0; d < 7; d++) { float dd = y[d] - mu1; s2 += dd * dd; }
        s2 += __shfl_xor_sync(0xffffffffu, s2, 8);
        s2 += __shfl_xor_sync(0xffffffffu, s2, 16);
        const float rs1 = rsqrtf(s2 * (1.0f / 28.0f) + 1e-5f);
#pragma unroll
        for (int d = 0; d < 7; d++) {
            const int ep = e0 + d;
            A[l * 28 + ep] = (y[d] - mu1) * rs1 * sm[OFF_G1 + ep] + sm[OFF_B1L + ep];
        }
        __syncwarp();

        // ==== FFN in layout B: thread (fg, tk2) handles f = 8i+fg for tokens tk2, tk2+4 ====
        // Each W row LDS.128 now has 8 distinct rows across the warp -> 128B/wavefront,
        // and is amortized over 2 tokens.
        float xa[28], xb[28];
        {
            const float4* ra = reinterpret_cast<const float4*>(A + tk2 * 28);
            const float4* rb = reinterpret_cast<const float4*>(A + (tk2 + 4) * 28);
#pragma unroll
            for (int j = 0; j < 7; j++) {
                float4 va = ra[j], vb = rb[j];
                xa[4 * j] = va.x; xa[4 * j + 1] = va.y; xa[4 * j + 2] = va.z; xa[4 * j + 3] = va.w;
                xb[4 * j] = vb.x; xb[4 * j + 1] = vb.y; xb[4 * j + 2] = vb.z; xb[4 * j + 3] = vb.w;
            }
        }
        float ffa[28], ffb[28];
#pragma unroll
        for (int ep = 0; ep < 28; ep++) { ffa[ep] = 0.0f; ffb[ep] = 0.0f; }
#pragma unroll 4
        for (int i = 0; i < 32; i++) {
            const int f = 8 * i + fg;
            const float4* w1r = reinterpret_cast<const float4*>(sm + OFF_W1 + f * 28);
            const float bias = sm[OFF_B1 + f];
            float a1a = bias, a1b = bias;
#pragma unroll
            for (int j = 0; j < 7; j++) {
                float4 w = w1r[j];
                a1a = fmaf(xa[4 * j + 0], w.x, a1a); a1b = fmaf(xb[4 * j + 0], w.x, a1b);
                a1a = fmaf(xa[4 * j + 1], w.y, a1a); a1b = fmaf(xb[4 * j + 1], w.y, a1b);
                a1a = fmaf(xa[4 * j + 2], w.z, a1a); a1b = fmaf(xb[4 * j + 2], w.z, a1b);
                a1a = fmaf(xa[4 * j + 3], w.w, a1a); a1b = fmaf(xb[4 * j + 3], w.w, a1b);
            }
            a1a = fmaxf(a1a, 0.0f);
            a1b = fmaxf(a1b, 0.0f);
            const float4* w2r = reinterpret_cast<const float4*>(sm + OFF_W2T + f * 28);
#pragma unroll
            for (int j = 0; j < 7; j++) {
                float4 w = w2r[j];
                ffa[4 * j + 0] = fmaf(a1a, w.x, ffa[4 * j + 0]); ffb[4 * j + 0] = fmaf(a1b, w.x, ffb[4 * j + 0]);
                ffa[4 * j + 1] = fmaf(a1a, w.y, ffa[4 * j + 1]); ffb[4 * j + 1] = fmaf(a1b, w.y, ffb[4 * j + 1]);
                ffa[4 * j + 2] = fmaf(a1a, w.z, ffa[4 * j + 2]); ffb[4 * j + 2] = fmaf(a1b, w.z, ffb[4 * j + 2]);
                ffa[4 * j + 3] = fmaf(a1a, w.w, ffa[4 * j + 3]); ffb[4 * j + 3] = fmaf(a1b, w.w, ffb[4 * j + 3]);
            }
        }
        // reduce partial ff over the 8 f-groups (xor over lane bits 0..2)
#pragma unroll
        for (int ep = 0; ep < 28; ep++) {
            float va = ffa[ep], vb = ffb[ep];
            va += __shfl_xor_sync(0xffffffffu, va, 1);
            vb += __shfl_xor_sync(0xffffffffu, vb, 1);
            va += __shfl_xor_sync(0xffffffffu, va, 2);
            vb += __shfl_xor_sync(0xffffffffu, vb, 2);
            va += __shfl_xor_sync(0xffffffffu, va, 4);
            vb += __shfl_xor_sync(0xffffffffu, vb, 4);
            const float b2 = sm[OFF_B2 + ep];
            ffa[ep] = va + b2;
            ffb[ep] = vb + b2;
        }

        // ---- residual2 + LN2 for tokens ta=tk2, tb=tk2+4 (redundant across fg) ----
        float mua = 0.0f, mub = 0.0f;
#pragma unroll
        for (int ep = 0; ep < 28; ep++) {
            ffa[ep] += xa[ep]; mua += ffa[ep];
            ffb[ep] += xb[ep]; mub += ffb[ep];
        }
        mua *= (1.0f / 28.0f); mub *= (1.0f / 28.0f);
        float va2 = 0.0f, vb2 = 0.0f;
#pragma unroll
        for (int ep = 0; ep < 28; ep++) {
            float da = ffa[ep] - mua; va2 += da * da;
            float db = ffb[ep] - mub; vb2 += db * db;
        }
        const float rsa = rsqrtf(va2 * (1.0f / 28.0f) + 1e-5f);
        const float rsb = rsqrtf(vb2 * (1.0f / 28.0f) + 1e-5f);

        // ---- masked mean-pool: tokens tk2, tk2+4 in-thread, then reduce over tk2 ----
        const float ma = (tk2 < len)     ? 1.0f : 0.0f;
        const float mb = (tk2 + 4 < len) ? 1.0f : 0.0f;
        float po[28];
#pragma unroll
        for (int ep = 0; ep < 28; ep++) {
            const float g2 = sm[OFF_G2 + ep], b2l = sm[OFF_B2L + ep];
            float x2a = (ffa[ep] - mua) * rsa * g2 + b2l;
            float x2b = (ffb[ep] - mub) * rsb * g2 + b2l;
            po[ep] = x2a * ma + x2b * mb;
        }
#pragma unroll
        for (int ep = 0; ep < 28; ep++) {
            float v = po[ep];
            v += __shfl_xor_sync(0xffffffffu, v, 8);
            v += __shfl_xor_sync(0xffffffffu, v, 16);
            po[ep] = v;
        }
        const float invlen = 1.0f / (float)len;

        // ---- output: pooled (valid) or pad_token ----
        const int ns = num_spans[b];
        float* orow = outp + span * 28;
        __syncwarp();  // FFN reads of A complete before reuse as staging
        if (t < ns) {
            if (lane == 0) {
                float4* A4 = reinterpret_cast<float4*>(A);
#pragma unroll
                for (int j = 0; j < 7; j++) {
                    float4 v;
                    v.x = po[4 * j] * invlen;
                    v.y = po[4 * j + 1] * invlen;
                    v.z = po[4 * j + 2] * invlen;
                    v.w = po[4 * j + 3] * invlen;
                    A4[j] = v;
                }
            }
            __syncwarp();
            if (lane < 7)
                reinterpret_cast<float4*>(orow)[lane] = reinterpret_cast<float4*>(A)[lane];
        } else {
            if (lane < 7)
                reinterpret_cast<float4*>(orow)[lane] =
                    reinterpret_cast<const float4*>(sm + OFF_PAD)[lane];
        }
        __syncwarp();   // A reused next iteration
    }
}

extern "C" void kernel_launch(void* const* d_in, const int* in_sizes, int n_in,
                              void* d_out, int out_size) {
    const float* emb          = (const float*)d_in[0];
    const int*   span_lengths = (const int*)  d_in[1];
    const int*   num_spans    = (const int*)  d_in[2];
    const float* in_proj_w    = (const float*)d_in[3];
    const float* in_proj_b    = (const float*)d_in[4];
    const float* out_proj_w   = (const float*)d_in[5];
    const float* out_proj_b   = (const float*)d_in[6];
    const float* ln1_g        = (const float*)d_in[7];
    const float* ln1_b        = (const float*)d_in[8];
    const float* lin1_w       = (const float*)d_in[9];
    const float* lin1_b       = (const float*)d_in[10];
    const float* lin2_w       = (const float*)d_in[11];
    const float* lin2_b       = (const float*)d_in[12];
    const float* ln2_g        = (const float*)d_in[13];
    const float* ln2_b        = (const float*)d_in[14];
    const float* pad_token    = (const float*)d_in[15];
    float* outp = (float*)d_out;

    cudaFuncSetAttribute(span_transformer_kernel,
                         cudaFuncAttributeMaxDynamicSharedMemorySize, SMEM_BYTES);

    span_transformer_kernel<<<296, 256, SMEM_BYTES>>>(
        emb, span_lengths, num_spans,
        in_proj_w, in_proj_b, out_proj_w, out_proj_b,
        ln1_g, ln1_b, lin1_w, lin1_b, lin2_w, lin2_b,
        ln2_g, ln2_b, pad_token, outp);
}

// round 5
// speedup vs baseline: 1.1199x; 1.1199x over previous
#include <cuda_runtime.h>

#define E_ 28
#define T_ 512
#define NSPANS 32768

// ---- shared layout (floats) ----
#define OFF_WQKV 0
#define OFF_BQKV 2352
#define OFF_WO   2436
#define OFF_BO   3220
#define OFF_G1   3248
#define OFF_B1L  3276
#define OFF_W1   3304
#define OFF_B1   10472
#define OFF_W2T  10728
#define OFF_B2   17896
#define OFF_G2   17924
#define OFF_B2L  17952
#define OFF_PAD  17980
#define OFF_LEN  18008   // int[64]
#define OFF_VAL  18072   // int[64]
#define OFF_SCR  18136   // 8 warps x 672
#define OFF_XN   23512   // 512 tokens x 28
#define SMEM_FLOATS (OFF_XN + 512 * 28)        // 37848
#define SMEM_BYTES  (SMEM_FLOATS * 4)          // 151392

__device__ __forceinline__ void cp_f4(float* dst, const float* src, int nfloats) {
    const int n4 = nfloats >> 2;
    for (int i = threadIdx.x; i < n4; i += blockDim.x)
        reinterpret_cast<float4*>(dst)[i] = reinterpret_cast<const float4*>(src)[i];
}

__device__ __forceinline__ float dot28r(const float* x, const float* w) {
    const float4* w4 = reinterpret_cast<const float4*>(w);
    float acc = 0.0f;
#pragma unroll
    for (int j = 0; j < 7; j++) {
        float4 b = w4[j];
        acc = fmaf(x[4 * j + 0], b.x, acc);
        acc = fmaf(x[4 * j + 1], b.y, acc);
        acc = fmaf(x[4 * j + 2], b.z, acc);
        acc = fmaf(x[4 * j + 3], b.w, acc);
    }
    return acc;
}

__global__ __launch_bounds__(256, 1)
void span_transformer_kernel(
    const float* __restrict__ emb,
    const int*   __restrict__ span_lengths,
    const int*   __restrict__ num_spans,
    const float* __restrict__ in_proj_w, const float* __restrict__ in_proj_b,
    const float* __restrict__ out_proj_w, const float* __restrict__ out_proj_b,
    const float* __restrict__ ln1_g, const float* __restrict__ ln1_b,
    const float* __restrict__ lin1_w, const float* __restrict__ lin1_b,
    const float* __restrict__ lin2_w, const float* __restrict__ lin2_b,
    const float* __restrict__ ln2_g, const float* __restrict__ ln2_b,
    const float* __restrict__ pad_token,
    float* __restrict__ outp)
{
    extern __shared__ float sm[];

    // ---- weight staging ----
    cp_f4(sm + OFF_WQKV, in_proj_w, 2352);
    cp_f4(sm + OFF_BQKV, in_proj_b, 84);
    cp_f4(sm + OFF_WO,   out_proj_w, 784);
    cp_f4(sm + OFF_BO,   out_proj_b, 28);
    cp_f4(sm + OFF_G1,   ln1_g, 28);
    cp_f4(sm + OFF_B1L,  ln1_b, 28);
    cp_f4(sm + OFF_W1,   lin1_w, 7168);
    cp_f4(sm + OFF_B1,   lin1_b, 256);
    for (int i = threadIdx.x; i < 7168; i += blockDim.x) {
        int e = i >> 8, f = i & 255;
        sm[OFF_W2T + f * 28 + e] = lin2_w[i];   // transposed
    }
    cp_f4(sm + OFF_B2,   lin2_b, 28);
    cp_f4(sm + OFF_G2,   ln2_g, 28);
    cp_f4(sm + OFF_B2L,  ln2_b, 28);
    cp_f4(sm + OFF_PAD,  pad_token, 28);
    __syncthreads();

    const int warp = threadIdx.x >> 5;
    const int lane = threadIdx.x & 31;
    const int l  = lane & 7;
    const int h  = lane >> 3;
    const int e0 = h * 7;
    const int g  = blockIdx.x;          // group of 64 spans

    int* lens = reinterpret_cast<int*>(sm + OFF_LEN);
    int* vld  = reinterpret_cast<int*>(sm + OFF_VAL);
    float* A  = sm + OFF_SCR + warp * 672;
    float* Kb = A + 224;
    float* Vb = A + 448;

    // ================= PHASE 1: QKV / attn / proj / LN1  (warp = span) =================
    for (int j = 0; j < 8; j++) {
        const int sl   = warp * 8 + j;
        const int span = g * 64 + sl;
        const int b    = span >> 9;
        const int t    = span & (T_ - 1);

        {
            const float4* src = reinterpret_cast<const float4*>(emb + span * 224);
            float4* A4 = reinterpret_cast<float4*>(A);
            A4[lane] = src[lane];
            if (lane < 24) A4[lane + 32] = src[lane + 32];
        }
        __syncwarp();

        float xr[28];
        {
            const float4* r4 = reinterpret_cast<const float4*>(A + l * 28);
#pragma unroll
            for (int j2 = 0; j2 < 7; j2++) {
                float4 v = r4[j2];
                xr[4 * j2] = v.x; xr[4 * j2 + 1] = v.y; xr[4 * j2 + 2] = v.z; xr[4 * j2 + 3] = v.w;
            }
        }
        float q[7];
#pragma unroll
        for (int d = 0; d < 7; d++) {
            const int rq = e0 + d;
            q[d]     = sm[OFF_BQKV + rq]      + dot28r(xr, sm + OFF_WQKV + rq * 28);
            float kk = sm[OFF_BQKV + 28 + rq] + dot28r(xr, sm + OFF_WQKV + (28 + rq) * 28);
            float vv = sm[OFF_BQKV + 56 + rq] + dot28r(xr, sm + OFF_WQKV + (56 + rq) * 28);
            Kb[l * 28 + rq] = kk;
            Vb[l * 28 + rq] = vv;
        }
        __syncwarp();

        const int len = span_lengths[span];
        float s[8];
#pragma unroll
        for (int kk = 0; kk < 8; kk++) {
            const float* kr = Kb + kk * 28 + e0;
            float acc = 0.0f;
#pragma unroll
            for (int d = 0; d < 7; d++) acc = fmaf(q[d], kr[d], acc);
            s[kk] = (kk < len) ? acc * 0.3779644730092272f : -1e9f;
        }
        float mx = s[0];
#pragma unroll
        for (int kk = 1; kk < 8; kk++) mx = fmaxf(mx, s[kk]);
        float p[8], psum = 0.0f;
#pragma unroll
        for (int kk = 0; kk < 8; kk++) { p[kk] = __expf(s[kk] - mx); psum += p[kk]; }
        const float pinv = 1.0f / psum;
        float ao[7];
#pragma unroll
        for (int d = 0; d < 7; d++) {
            float acc = 0.0f;
#pragma unroll
            for (int kk = 0; kk < 8; kk++) acc = fmaf(p[kk], Vb[kk * 28 + e0 + d], acc);
            ao[d] = acc * pinv;
        }
        __syncwarp();
#pragma unroll
        for (int d = 0; d < 7; d++) Kb[l * 28 + e0 + d] = ao[d];
        __syncwarp();

        float aor[28];
        {
            const float4* r4 = reinterpret_cast<const float4*>(Kb + l * 28);
#pragma unroll
            for (int j2 = 0; j2 < 7; j2++) {
                float4 v = r4[j2];
                aor[4 * j2] = v.x; aor[4 * j2 + 1] = v.y; aor[4 * j2 + 2] = v.z; aor[4 * j2 + 3] = v.w;
            }
        }
        float y[7];
#pragma unroll
        for (int d = 0; d < 7; d++) {
            const int ep = e0 + d;
            float o = sm[OFF_BO + ep] + dot28r(aor, sm + OFF_WO + ep * 28);
            y[d] = A[l * 28 + ep] + o;
        }
        float s1 = 0.0f;
#pragma unroll
        for (int d = 0; d < 7; d++) s1 += y[d];
        s1 += __shfl_xor_sync(0xffffffffu, s1, 8);
        s1 += __shfl_xor_sync(0xffffffffu, s1, 16);
        const float mu1 = s1 * (1.0f / 28.0f);
        float s2 = 0.0f;
#pragma unroll
        for (int d = 0; d < 7; d++) { float dd = y[d] - mu1; s2 += dd * dd; }
        s2 += __shfl_xor_sync(0xffffffffu, s2, 8);
        s2 += __shfl_xor_sync(0xffffffffu, s2, 16);
        const float rs1 = rsqrtf(s2 * (1.0f / 28.0f) + 1e-5f);

        const int row = sl * 8 + l;
#pragma unroll
        for (int d = 0; d < 7; d++) {
            const int ep = e0 + d;
            sm[OFF_XN + row * 28 + ep] = (y[d] - mu1) * rs1 * sm[OFF_G1 + ep] + sm[OFF_B1L + ep];
        }
        if (lane == 0) {
            lens[sl] = len;
            vld[sl]  = (t < num_spans[b]) ? 1 : 0;
        }
        __syncwarp();
    }
    __syncthreads();

    // ================= PHASE 2: FFN, 2 whole tokens per thread =================
    // warp w owns tokens [64w, 64w+64); thread: tA = 64w+lane, tB = tA+32.
    const int tA = warp * 64 + lane;
    const int tB = tA + 32;
    float xA[28], xB[28];
    {
        const float4* ra = reinterpret_cast<const float4*>(sm + OFF_XN + tA * 28);
        const float4* rb = reinterpret_cast<const float4*>(sm + OFF_XN + tB * 28);
#pragma unroll
        for (int j = 0; j < 7; j++) {
            float4 va = ra[j], vb = rb[j];
            xA[4 * j] = va.x; xA[4 * j + 1] = va.y; xA[4 * j + 2] = va.z; xA[4 * j + 3] = va.w;
            xB[4 * j] = vb.x; xB[4 * j + 1] = vb.y; xB[4 * j + 2] = vb.z; xB[4 * j + 3] = vb.w;
        }
    }
    float fA[28], fB[28];
#pragma unroll
    for (int e = 0; e < 28; e++) { fA[e] = 0.0f; fB[e] = 0.0f; }

#pragma unroll 2
    for (int f = 0; f < 256; f++) {
        // uniform broadcast loads: all lanes read the same row -> 1 wavefront per LDS.128
        const float4* w1r = reinterpret_cast<const float4*>(sm + OFF_W1 + f * 28);
        float aa = sm[OFF_B1 + f], ab = aa;
#pragma unroll
        for (int j = 0; j < 7; j++) {
            float4 w = w1r[j];
            aa = fmaf(xA[4 * j + 0], w.x, aa); ab = fmaf(xB[4 * j + 0], w.x, ab);
            aa = fmaf(xA[4 * j + 1], w.y, aa); ab = fmaf(xB[4 * j + 1], w.y, ab);
            aa = fmaf(xA[4 * j + 2], w.z, aa); ab = fmaf(xB[4 * j + 2], w.z, ab);
            aa = fmaf(xA[4 * j + 3], w.w, aa); ab = fmaf(xB[4 * j + 3], w.w, ab);
        }
        aa = fmaxf(aa, 0.0f);
        ab = fmaxf(ab, 0.0f);
        const float4* w2r = reinterpret_cast<const float4*>(sm + OFF_W2T + f * 28);
#pragma unroll
        for (int j = 0; j < 7; j++) {
            float4 w = w2r[j];
            fA[4 * j + 0] = fmaf(aa, w.x, fA[4 * j + 0]); fB[4 * j + 0] = fmaf(ab, w.x, fB[4 * j + 0]);
            fA[4 * j + 1] = fmaf(aa, w.y, fA[4 * j + 1]); fB[4 * j + 1] = fmaf(ab, w.y, fB[4 * j + 1]);
            fA[4 * j + 2] = fmaf(aa, w.z, fA[4 * j + 2]); fB[4 * j + 2] = fmaf(ab, w.z, fB[4 * j + 2]);
            fA[4 * j + 3] = fmaf(aa, w.w, fA[4 * j + 3]); fB[4 * j + 3] = fmaf(ab, w.w, fB[4 * j + 3]);
        }
    }

    // ---- +b2, residual, LN2 (fully in-thread), masked pool over lane%8 ----
    const int slA = tA >> 3, slB = tB >> 3;
    const int lenA = lens[slA], lenB = lens[slB];
    float muA = 0.0f, muB = 0.0f;
#pragma unroll
    for (int e = 0; e < 28; e++) {
        const float b2 = sm[OFF_B2 + e];
        fA[e] += b2 + xA[e]; muA += fA[e];
        fB[e] += b2 + xB[e]; muB += fB[e];
    }
    muA *= (1.0f / 28.0f); muB *= (1.0f / 28.0f);
    float vA = 0.0f, vB = 0.0f;
#pragma unroll
    for (int e = 0; e < 28; e++) {
        float da = fA[e] - muA; vA += da * da;
        float db = fB[e] - muB; vB += db * db;
    }
    const float rsA = rsqrtf(vA * (1.0f / 28.0f) + 1e-5f);
    const float rsB = rsqrtf(vB * (1.0f / 28.0f) + 1e-5f);
    const float mA = (l < lenA) ? 1.0f : 0.0f;
    const float mB = (l < lenB) ? 1.0f : 0.0f;
    float pA[28], pB[28];
#pragma unroll
    for (int e = 0; e < 28; e++) {
        const float g2 = sm[OFF_G2 + e], b2l = sm[OFF_B2L + e];
        pA[e] = ((fA[e] - muA) * rsA * g2 + b2l) * mA;
        pB[e] = ((fB[e] - muB) * rsB * g2 + b2l) * mB;
    }
#pragma unroll
    for (int e = 0; e < 28; e++) {
        float a = pA[e], b = pB[e];
        a += __shfl_xor_sync(0xffffffffu, a, 1);
        b += __shfl_xor_sync(0xffffffffu, b, 1);
        a += __shfl_xor_sync(0xffffffffu, a, 2);
        b += __shfl_xor_sync(0xffffffffu, b, 2);
        a += __shfl_xor_sync(0xffffffffu, a, 4);
        b += __shfl_xor_sync(0xffffffffu, b, 4);
        pA[e] = a; pB[e] = b;
    }

    if (l == 0) {
        const float ilA = 1.0f / (float)lenA;
        const float ilB = 1.0f / (float)lenB;
        float4* rowA = reinterpret_cast<float4*>(outp + (g * 64 + slA) * 28);
        float4* rowB = reinterpret_cast<float4*>(outp + (g * 64 + slB) * 28);
        if (vld[slA]) {
#pragma unroll
            for (int j = 0; j < 7; j++)
                rowA[j] = make_float4(pA[4 * j] * ilA, pA[4 * j + 1] * ilA,
                                      pA[4 * j + 2] * ilA, pA[4 * j + 3] * ilA);
        } else {
#pragma unroll
            for (int j = 0; j < 7; j++)
                rowA[j] = make_float4(sm[OFF_PAD + 4 * j], sm[OFF_PAD + 4 * j + 1],
                                      sm[OFF_PAD + 4 * j + 2], sm[OFF_PAD + 4 * j + 3]);
        }
        if (vld[slB]) {
#pragma unroll
            for (int j = 0; j < 7; j++)
                rowB[j] = make_float4(pB[4 * j] * ilB, pB[4 * j + 1] * ilB,
                                      pB[4 * j + 2] * ilB, pB[4 * j + 3] * ilB);
        } else {
#pragma unroll
            for (int j = 0; j < 7; j++)
                rowB[j] = make_float4(sm[OFF_PAD + 4 * j], sm[OFF_PAD + 4 * j + 1],
                                      sm[OFF_PAD + 4 * j + 2], sm[OFF_PAD + 4 * j + 3]);
        }
    }
}

extern "C" void kernel_launch(void* const* d_in, const int* in_sizes, int n_in,
                              void* d_out, int out_size) {
    const float* emb          = (const float*)d_in[0];
    const int*   span_lengths = (const int*)  d_in[1];
    const int*   num_spans    = (const int*)  d_in[2];
    const float* in_proj_w    = (const float*)d_in[3];
    const float* in_proj_b    = (const float*)d_in[4];
    const float* out_proj_w   = (const float*)d_in[5];
    const float* out_proj_b   = (const float*)d_in[6];
    const float* ln1_g        = (const float*)d_in[7];
    const float* ln1_b        = (const float*)d_in[8];
    const float* lin1_w       = (const float*)d_in[9];
    const float* lin1_b       = (const float*)d_in[10];
    const float* lin2_w       = (const float*)d_in[11];
    const float* lin2_b       = (const float*)d_in[12];
    const float* ln2_g        = (const float*)d_in[13];
    const float* ln2_b        = (const float*)d_in[14];
    const float* pad_token    = (const float*)d_in[15];
    float* outp = (float*)d_out;

    cudaFuncSetAttribute(span_transformer_kernel,
                         cudaFuncAttributeMaxDynamicSharedMemorySize, SMEM_BYTES);

    span_transformer_kernel<<<NSPANS / 64, 256, SMEM_BYTES>>>(
        emb, span_lengths, num_spans,
        in_proj_w, in_proj_b, out_proj_w, out_proj_b,
        ln1_g, ln1_b, lin1_w, lin1_b, lin2_w, lin2_b,
        ln2_g, ln2_b, pad_token, outp);
}

// round 8
// speedup vs baseline: 2.0312x; 1.8137x over previous
#include <cuda_runtime.h>
#include <cuda_bf16.h>
#include <cstdint>

#define T_ 512
#define NG 1024            // groups of 32 spans (256 tokens per block-group)

// ---------------- smem layout ----------------
#define F_WQKV 0
#define F_BQKV 2352
#define F_WO   2436
#define F_BO   3220
#define F_G1   3248
#define F_B1L  3276
#define F_B1   3304
#define F_B2   3560       // padded to 32 (pads zero)
#define F_G2   3592
#define F_B2L  3624
#define F_PAD  3656
#define I_LEN  3684       // int[32]
#define I_VAL  3716       // int[32]
#define F_SCR  3748       // 8 warps x 672
#define F_XN   9124       // 256 tokens x 28 fp32
#define XH_B   65280      // X  hi  [256 tok][40 halves]
#define XL_B   85760
#define W1H_B  106240     // W1 hi  [256 f][40 halves]
#define W1L_B  126720
#define W2H_B  147200     // W2 hi  [32 e][264 halves]
#define W2L_B  164096
#define SMEM_END_B 180992

__device__ __forceinline__ void mma_bf16(float* d, uint32_t a0, uint32_t a1,
                                         uint32_t a2, uint32_t a3,
                                         uint32_t b0, uint32_t b1) {
    asm volatile(
        "mma.sync.aligned.m16n8k16.row.col.f32.bf16.bf16.f32 "
        "{%0,%1,%2,%3}, {%4,%5,%6,%7}, {%8,%9}, {%0,%1,%2,%3};"
        : "+f"(d[0]), "+f"(d[1]), "+f"(d[2]), "+f"(d[3])
        : "r"(a0), "r"(a1), "r"(a2), "r"(a3), "r"(b0), "r"(b1));
}
__device__ __forceinline__ uint32_t pack_bf2(__nv_bfloat16 lo, __nv_bfloat16 hi) {
    __nv_bfloat162 t(lo, hi);
    return *reinterpret_cast<uint32_t*>(&t);
}
__device__ __forceinline__ void split_bf16(float v, __nv_bfloat16& hi, float& lo) {
    hi = __float2bfloat16(v);
    lo = v - __bfloat162float(hi);
}

__device__ __forceinline__ float dot28r(const float* x, const float* w) {
    const float4* w4 = reinterpret_cast<const float4*>(w);
    float acc = 0.0f;
#pragma unroll
    for (int j = 0; j < 7; j++) {
        float4 b = w4[j];
        acc = fmaf(x[4 * j], b.x, acc);
        acc = fmaf(x[4 * j + 1], b.y, acc);
        acc = fmaf(x[4 * j + 2], b.z, acc);
        acc = fmaf(x[4 * j + 3], b.w, acc);
    }
    return acc;
}

__global__ __launch_bounds__(256, 1)
void span_mma_kernel(
    const float* __restrict__ emb,
    const int*   __restrict__ span_lengths,
    const int*   __restrict__ num_spans,
    const float* __restrict__ in_proj_w, const float* __restrict__ in_proj_b,
    const float* __restrict__ out_proj_w, const float* __restrict__ out_proj_b,
    const float* __restrict__ ln1_g, const float* __restrict__ ln1_b,
    const float* __restrict__ lin1_w, const float* __restrict__ lin1_b,
    const float* __restrict__ lin2_w, const float* __restrict__ lin2_b,
    const float* __restrict__ ln2_g, const float* __restrict__ ln2_b,
    const float* __restrict__ pad_token,
    float* __restrict__ outp)
{
    extern __shared__ char smc[];
    float* smf = reinterpret_cast<float*>(smc);
    const int tid = threadIdx.x, warp = tid >> 5, lane = tid & 31;

    {
        int4 z = make_int4(0, 0, 0, 0);
        int4* d = reinterpret_cast<int4*>(smc + XH_B);
        for (int i = tid; i < (SMEM_END_B - XH_B) / 16; i += 256) d[i] = z;
    }
    for (int i = tid; i < 2352; i += 256) smf[F_WQKV + i] = in_proj_w[i];
    for (int i = tid; i < 84;  i += 256) smf[F_BQKV + i] = in_proj_b[i];
    for (int i = tid; i < 784; i += 256) smf[F_WO + i]   = out_proj_w[i];
    for (int i = tid; i < 256; i += 256) smf[F_B1 + i]   = lin1_b[i];
    if (tid < 32) {
        smf[F_B2 + tid]  = (tid < 28) ? lin2_b[tid] : 0.0f;
        smf[F_G2 + tid]  = (tid < 28) ? ln2_g[tid]  : 0.0f;
        smf[F_B2L + tid] = (tid < 28) ? ln2_b[tid]  : 0.0f;
    }
    if (tid < 28) {
        smf[F_BO + tid]  = out_proj_b[tid];
        smf[F_G1 + tid]  = ln1_g[tid];
        smf[F_B1L + tid] = ln1_b[tid];
        smf[F_PAD + tid] = pad_token[tid];
    }
    __syncthreads();
    for (int i = tid; i < 7168; i += 256) {
        int f = i / 28, e = i % 28;
        __nv_bfloat16 hh; float lf; split_bf16(lin1_w[i], hh, lf);
        *reinterpret_cast<__nv_bfloat16*>(smc + W1H_B + (f * 40 + e) * 2) = hh;
        *reinterpret_cast<__nv_bfloat16*>(smc + W1L_B + (f * 40 + e) * 2) = __float2bfloat16(lf);
    }
    for (int i = tid; i < 7168; i += 256) {
        int e = i / 256, f = i % 256;
        __nv_bfloat16 hh; float lf; split_bf16(lin2_w[i], hh, lf);
        *reinterpret_cast<__nv_bfloat16*>(smc + W2H_B + (e * 264 + f) * 2) = hh;
        *reinterpret_cast<__nv_bfloat16*>(smc + W2L_B + (e * 264 + f) * 2) = __float2bfloat16(lf);
    }
    __syncthreads();

    const uint32_t* XHw  = reinterpret_cast<const uint32_t*>(smc + XH_B);
    const uint32_t* XLw  = reinterpret_cast<const uint32_t*>(smc + XL_B);
    const uint32_t* W1Hw = reinterpret_cast<const uint32_t*>(smc + W1H_B);
    const uint32_t* W1Lw = reinterpret_cast<const uint32_t*>(smc + W1L_B);
    const uint32_t* W2Hw = reinterpret_cast<const uint32_t*>(smc + W2H_B);
    const uint32_t* W2Lw = reinterpret_cast<const uint32_t*>(smc + W2L_B);
    int* lens = reinterpret_cast<int*>(smf + I_LEN);
    int* vld  = reinterpret_cast<int*>(smf + I_VAL);

    const int l = lane & 7, h = lane >> 3, e0h = h * 7;
    const int gq = lane >> 2, tq = lane & 3;
    float* A  = smf + F_SCR + warp * 672;
    float* Kb = A + 224;
    float* Vb = A + 448;

    for (int g = blockIdx.x; g < NG; g += gridDim.x) {
        // ---------------- PHASE 1 ----------------
        for (int j = 0; j < 4; j++) {
            const int sl = warp * 4 + j;
            const int span = g * 32 + sl;
            const int b = span >> 9, t = span & (T_ - 1);
            {
                const float4* src = reinterpret_cast<const float4*>(emb + span * 224);
                float4* A4 = reinterpret_cast<float4*>(A);
                A4[lane] = src[lane];
                if (lane < 24) A4[lane + 32] = src[lane + 32];
            }
            __syncwarp();
            float xr[28];
            {
                const float4* r4 = reinterpret_cast<const float4*>(A + l * 28);
#pragma unroll
                for (int j2 = 0; j2 < 7; j2++) {
                    float4 v = r4[j2];
                    xr[4 * j2] = v.x; xr[4 * j2 + 1] = v.y; xr[4 * j2 + 2] = v.z; xr[4 * j2 + 3] = v.w;
                }
            }
            float q[7];
#pragma unroll
            for (int d = 0; d < 7; d++) {
                const int rq = e0h + d;
                q[d]     = smf[F_BQKV + rq]      + dot28r(xr, smf + F_WQKV + rq * 28);
                float kk = smf[F_BQKV + 28 + rq] + dot28r(xr, smf + F_WQKV + (28 + rq) * 28);
                float vv = smf[F_BQKV + 56 + rq] + dot28r(xr, smf + F_WQKV + (56 + rq) * 28);
                Kb[l * 28 + rq] = kk;
                Vb[l * 28 + rq] = vv;
            }
            __syncwarp();
            const int len = span_lengths[span];
            float s[8];
#pragma unroll
            for (int kk = 0; kk < 8; kk++) {
                const float* kr = Kb + kk * 28 + e0h;
                float acc = 0.0f;
#pragma unroll
                for (int d = 0; d < 7; d++) acc = fmaf(q[d], kr[d], acc);
                s[kk] = (kk < len) ? acc * 0.3779644730092272f : -1e9f;
            }
            float mx = s[0];
#pragma unroll
            for (int kk = 1; kk < 8; kk++) mx = fmaxf(mx, s[kk]);
            float p[8], ps = 0.0f;
#pragma unroll
            for (int kk = 0; kk < 8; kk++) { p[kk] = __expf(s[kk] - mx); ps += p[kk]; }
            const float pinv = 1.0f / ps;
            float ao[7];
#pragma unroll
            for (int d = 0; d < 7; d++) {
                float acc = 0.0f;
#pragma unroll
                for (int kk = 0; kk < 8; kk++) acc = fmaf(p[kk], Vb[kk * 28 + e0h + d], acc);
                ao[d] = acc * pinv;
            }
            __syncwarp();
#pragma unroll
            for (int d = 0; d < 7; d++) Kb[l * 28 + e0h + d] = ao[d];
            __syncwarp();
            float aor[28];
            {
                const float4* r4 = reinterpret_cast<const float4*>(Kb + l * 28);
#pragma unroll
                for (int j2 = 0; j2 < 7; j2++) {
                    float4 v = r4[j2];
                    aor[4 * j2] = v.x; aor[4 * j2 + 1] = v.y; aor[4 * j2 + 2] = v.z; aor[4 * j2 + 3] = v.w;
                }
            }
            float y[7];
#pragma unroll
            for (int d = 0; d < 7; d++) {
                const int ep = e0h + d;
                y[d] = A[l * 28 + ep] + smf[F_BO + ep] + dot28r(aor, smf + F_WO + ep * 28);
            }
            float s1 = 0.0f;
#pragma unroll
            for (int d = 0; d < 7; d++) s1 += y[d];
            s1 += __shfl_xor_sync(0xffffffffu, s1, 8);
            s1 += __shfl_xor_sync(0xffffffffu, s1, 16);
            const float mu1 = s1 * (1.0f / 28.0f);
            float s2 = 0.0f;
#pragma unroll
            for (int d = 0; d < 7; d++) { float dd = y[d] - mu1; s2 += dd * dd; }
            s2 += __shfl_xor_sync(0xffffffffu, s2, 8);
            s2 += __shfl_xor_sync(0xffffffffu, s2, 16);
            const float rs1 = rsqrtf(s2 * (1.0f / 28.0f) + 1e-5f);
            const int row = sl * 8 + l;
#pragma unroll
            for (int d = 0; d < 7; d++) {
                const int ep = e0h + d;
                float v = (y[d] - mu1) * rs1 * smf[F_G1 + ep] + smf[F_B1L + ep];
                smf[F_XN + row * 28 + ep] = v;
                __nv_bfloat16 hh; float lf; split_bf16(v, hh, lf);
                *reinterpret_cast<__nv_bfloat16*>(smc + XH_B + (row * 40 + ep) * 2) = hh;
                *reinterpret_cast<__nv_bfloat16*>(smc + XL_B + (row * 40 + ep) * 2) = __float2bfloat16(lf);
            }
            if (lane == 0) { lens[sl] = len; vld[sl] = (t < num_spans[b]) ? 1 : 0; }
            __syncwarp();
        }
        __syncwarp();

        // ---------------- PHASE 2: FFN via mma.sync ----------------
        const int m0 = warp * 32;
        uint32_t ah[2][2][4], al[2][2][4];
#pragma unroll
        for (int mt = 0; mt < 2; mt++)
#pragma unroll
            for (int kt = 0; kt < 2; kt++) {
                const int w0 = (m0 + mt * 16 + gq) * 20 + kt * 8 + tq;
                ah[mt][kt][0] = XHw[w0];       ah[mt][kt][1] = XHw[w0 + 160];
                ah[mt][kt][2] = XHw[w0 + 4];   ah[mt][kt][3] = XHw[w0 + 164];
                al[mt][kt][0] = XLw[w0];       al[mt][kt][1] = XLw[w0 + 160];
                al[mt][kt][2] = XLw[w0 + 4];   al[mt][kt][3] = XLw[w0 + 164];
            }

        float d2[2][4][4];
#pragma unroll
        for (int mt = 0; mt < 2; mt++)
#pragma unroll
            for (int nt = 0; nt < 4; nt++)
#pragma unroll
                for (int r = 0; r < 4; r++) d2[mt][nt][r] = 0.0f;

        for (int fc = 0; fc < 16; fc++) {
            float d1[2][2][4];
#pragma unroll
            for (int mt = 0; mt < 2; mt++)
#pragma unroll
                for (int nt = 0; nt < 2; nt++)
#pragma unroll
                    for (int r = 0; r < 4; r++) d1[mt][nt][r] = 0.0f;
#pragma unroll
            for (int kt = 0; kt < 2; kt++)
#pragma unroll
                for (int nt = 0; nt < 2; nt++) {
                    const int w = (fc * 16 + nt * 8 + gq) * 20 + kt * 8 + tq;
                    const uint32_t b0h = W1Hw[w], b1h = W1Hw[w + 4];
                    const uint32_t b0l = W1Lw[w], b1l = W1Lw[w + 4];
#pragma unroll
                    for (int mt = 0; mt < 2; mt++) {
                        mma_bf16(d1[mt][nt], ah[mt][kt][0], ah[mt][kt][1], ah[mt][kt][2], ah[mt][kt][3], b0h, b1h);
                        mma_bf16(d1[mt][nt], al[mt][kt][0], al[mt][kt][1], al[mt][kt][2], al[mt][kt][3], b0h, b1h);
                        mma_bf16(d1[mt][nt], ah[mt][kt][0], ah[mt][kt][1], ah[mt][kt][2], ah[mt][kt][3], b0l, b1l);
                    }
                }
            uint32_t a2h[2][4], a2l[2][4];
#pragma unroll
            for (int mt = 0; mt < 2; mt++)
#pragma unroll
                for (int nt = 0; nt < 2; nt++) {
                    const int fe = fc * 16 + nt * 8 + 2 * tq;
                    const float bz0 = smf[F_B1 + fe], bz1 = smf[F_B1 + fe + 1];
                    float h0 = fmaxf(d1[mt][nt][0] + bz0, 0.0f);
                    float h1 = fmaxf(d1[mt][nt][1] + bz1, 0.0f);
                    float h2 = fmaxf(d1[mt][nt][2] + bz0, 0.0f);
                    float h3 = fmaxf(d1[mt][nt][3] + bz1, 0.0f);
                    __nv_bfloat16 q0, q1, q2, q3; float l0, l1, l2, l3;
                    split_bf16(h0, q0, l0); split_bf16(h1, q1, l1);
                    split_bf16(h2, q2, l2); split_bf16(h3, q3, l3);
                    a2h[mt][nt * 2 + 0] = pack_bf2(q0, q1);   // rows g,   k-pair (c0,c1)
                    a2h[mt][nt * 2 + 1] = pack_bf2(q2, q3);   // rows g+8       (c2,c3)
                    a2l[mt][nt * 2 + 0] = pack_bf2(__float2bfloat16(l0), __float2bfloat16(l1));
                    a2l[mt][nt * 2 + 1] = pack_bf2(__float2bfloat16(l2), __float2bfloat16(l3));
                }
#pragma unroll
            for (int nt2 = 0; nt2 < 4; nt2++) {
                const int w2 = (nt2 * 8 + gq) * 132 + fc * 8 + tq;
                const uint32_t b0h = W2Hw[w2], b1h = W2Hw[w2 + 4];
                const uint32_t b0l = W2Lw[w2], b1l = W2Lw[w2 + 4];
#pragma unroll
                for (int mt = 0; mt < 2; mt++) {
                    mma_bf16(d2[mt][nt2], a2h[mt][0], a2h[mt][1], a2h[mt][2], a2h[mt][3], b0h, b1h);
                    mma_bf16(d2[mt][nt2], a2l[mt][0], a2l[mt][1], a2l[mt][2], a2l[mt][3], b0h, b1h);
                    mma_bf16(d2[mt][nt2], a2h[mt][0], a2h[mt][1], a2h[mt][2], a2h[mt][3], b0l, b1l);
                }
            }
        }

        // ---------------- EPILOGUE ----------------
#pragma unroll
        for (int mt = 0; mt < 2; mt++) {
            const int baseTok = m0 + mt * 16;
            const int tokA = baseTok + gq, tokB = tokA + 8;
            const int slA = warp * 4 + mt * 2, slB = slA + 1;
            float vA[8], vB[8];
            float sA = 0.0f, qA = 0.0f, sB = 0.0f, qB = 0.0f;
#pragma unroll
            for (int nt = 0; nt < 4; nt++) {
                const int e0 = nt * 8 + 2 * tq;
                const bool ok = (nt < 3) || (tq < 2);
                float xnA0 = ok ? smf[F_XN + tokA * 28 + e0] : 0.0f;
                float xnA1 = ok ? smf[F_XN + tokA * 28 + e0 + 1] : 0.0f;
                float xnB0 = ok ? smf[F_XN + tokB * 28 + e0] : 0.0f;
                float xnB1 = ok ? smf[F_XN + tokB * 28 + e0 + 1] : 0.0f;
                const float b20 = smf[F_B2 + e0], b21 = smf[F_B2 + e0 + 1];
                float a0 = ok ? (d2[mt][nt][0] + b20 + xnA0) : 0.0f;
                float a1 = ok ? (d2[mt][nt][1] + b21 + xnA1) : 0.0f;
                float b0 = ok ? (d2[mt][nt][2] + b20 + xnB0) : 0.0f;
                float b1 = ok ? (d2[mt][nt][3] + b21 + xnB1) : 0.0f;
                vA[nt * 2] = a0; vA[nt * 2 + 1] = a1;
                vB[nt * 2] = b0; vB[nt * 2 + 1] = b1;
                sA += a0 + a1; qA += a0 * a0 + a1 * a1;
                sB += b0 + b1; qB += b0 * b0 + b1 * b1;
            }
            sA += __shfl_xor_sync(0xffffffffu, sA, 1); qA += __shfl_xor_sync(0xffffffffu, qA, 1);
            sA += __shfl_xor_sync(0xffffffffu, sA, 2); qA += __shfl_xor_sync(0xffffffffu, qA, 2);
            sB += __shfl_xor_sync(0xffffffffu, sB, 1); qB += __shfl_xor_sync(0xffffffffu, qB, 1);
            sB += __shfl_xor_sync(0xffffffffu, sB, 2); qB += __shfl_xor_sync(0xffffffffu, qB, 2);
            const float muA = sA * (1.0f / 28.0f), muB = sB * (1.0f / 28.0f);
            const float rsA = rsqrtf(fmaxf(qA * (1.0f / 28.0f) - muA * muA, 0.0f) + 1e-5f);
            const float rsB = rsqrtf(fmaxf(qB * (1.0f / 28.0f) - muB * muB, 0.0f) + 1e-5f);
            const int lenA = lens[slA], lenB = lens[slB];
            const float mA = ((tokA & 7) < lenA) ? 1.0f : 0.0f;
            const float mB = ((tokB & 7) < lenB) ? 1.0f : 0.0f;
            float pA[8], pB[8];
#pragma unroll
            for (int nt = 0; nt < 4; nt++) {
                const int e0 = nt * 8 + 2 * tq;
                const bool ok = (nt < 3) || (tq < 2);
                const float g20 = smf[F_G2 + e0], g21 = smf[F_G2 + e0 + 1];
                const float bl0 = smf[F_B2L + e0], bl1 = smf[F_B2L + e0 + 1];
                pA[nt * 2]     = ok ? ((vA[nt * 2]     - muA) * rsA * g20 + bl0) * mA : 0.0f;
                pA[nt * 2 + 1] = ok ? ((vA[nt * 2 + 1] - muA) * rsA * g21 + bl1) * mA : 0.0f;
                pB[nt * 2]     = ok ? ((vB[nt * 2]     - muB) * rsB * g20 + bl0) * mB : 0.0f;
                pB[nt * 2 + 1] = ok ? ((vB[nt * 2 + 1] - muB) * rsB * g21 + bl1) * mB : 0.0f;
            }
#pragma unroll
            for (int i = 0; i < 8; i++) {
                float a = pA[i], b = pB[i];
                a += __shfl_xor_sync(0xffffffffu, a, 4);  b += __shfl_xor_sync(0xffffffffu, b, 4);
                a += __shfl_xor_sync(0xffffffffu, a, 8);  b += __shfl_xor_sync(0xffffffffu, b, 8);
                a += __shfl_xor_sync(0xffffffffu, a, 16); b += __shfl_xor_sync(0xffffffffu, b, 16);
                pA[i] = a; pB[i] = b;
            }
            if (lane < 4) {
                const float ilA = 1.0f / (float)lenA, ilB = 1.0f / (float)lenB;
                const int spA = g * 32 + slA, spB = g * 32 + slB;
                const int okA = vld[slA], okB = vld[slB];
#pragma unroll
                for (int nt = 0; nt < 4; nt++) {
                    const int e0 = nt * 8 + 2 * tq;
                    if ((nt < 3) || (tq < 2)) {
                        outp[spA * 28 + e0]     = okA ? pA[nt * 2] * ilA     : smf[F_PAD + e0];
                        outp[spA * 28 + e0 + 1] = okA ? pA[nt * 2 + 1] * ilA : smf[F_PAD + e0 + 1];
                        outp[spB * 28 + e0]     = okB ? pB[nt * 2] * ilB     : smf[F_PAD + e0];
                        outp[spB * 28 + e0 + 1] = okB ? pB[nt * 2 + 1] * ilB : smf[F_PAD + e0 + 1];
                    }
                }
            }
        }
        __syncwarp();
    }
}

extern "C" void kernel_launch(void* const* d_in, const int* in_sizes, int n_in,
                              void* d_out, int out_size) {
    const float* emb          = (const float*)d_in[0];
    const int*   span_lengths = (const int*)  d_in[1];
    const int*   num_spans    = (const int*)  d_in[2];
    const float* in_proj_w    = (const float*)d_in[3];
    const float* in_proj_b    = (const float*)d_in[4];
    const float* out_proj_w   = (const float*)d_in[5];
    const float* out_proj_b   = (const float*)d_in[6];
    const float* ln1_g        = (const float*)d_in[7];
    const float* ln1_b        = (const float*)d_in[8];
    const float* lin1_w       = (const float*)d_in[9];
    const float* lin1_b       = (const float*)d_in[10];
    const float* lin2_w       = (const float*)d_in[11];
    const float* lin2_b       = (const float*)d_in[12];
    const float* ln2_g        = (const float*)d_in[13];
    const float* ln2_b        = (const float*)d_in[14];
    const float* pad_token    = (const float*)d_in[15];
    float* outp = (float*)d_out;

    cudaFuncSetAttribute(span_mma_kernel,
                         cudaFuncAttributeMaxDynamicSharedMemorySize, SMEM_END_B);

    span_mma_kernel<<<148, 256, SMEM_END_B>>>(
        emb, span_lengths, num_spans,
        in_proj_w, in_proj_b, out_proj_w, out_proj_b,
        ln1_g, ln1_b, lin1_w, lin1_b, lin2_w, lin2_b,
        ln2_g, ln2_b, pad_token, outp);
}

// round 9
// speedup vs baseline: 2.1414x; 1.0543x over previous
#include <cuda_runtime.h>
#include <cuda_bf16.h>
#include <cstdint>

#define T_ 512
#define NG 1024            // groups of 32 spans (256 tokens per block-group)

// ---------------- smem layout ----------------
#define F_WQKV 0
#define F_BQKV 2352
#define F_WO   2436
#define F_BO   3220
#define F_G1   3248
#define F_B1L  3276
#define F_B1   3304
#define F_B2   3560       // padded to 32 (pads zero)
#define F_G2   3592
#define F_B2L  3624
#define F_PAD  3656
#define I_LEN  3684       // int[32]
#define I_VAL  3716       // int[32]
#define F_SCR  3748       // 16 warps x 672
#define F_XN   14500      // 256 tokens x 28 fp32
#define XH_B   86672      // X  hi  [256 tok][40 halves]
#define XL_B   107152
#define W1H_B  127632     // W1 hi  [256 f][40 halves]
#define W1L_B  148112
#define W2H_B  168592     // W2 hi  [32 e][264 halves]
#define W2L_B  185488
#define SMEM_END_B 202384

__device__ __forceinline__ void mma_bf16(float* d, uint32_t a0, uint32_t a1,
                                         uint32_t a2, uint32_t a3,
                                         uint32_t b0, uint32_t b1) {
    asm volatile(
        "mma.sync.aligned.m16n8k16.row.col.f32.bf16.bf16.f32 "
        "{%0,%1,%2,%3}, {%4,%5,%6,%7}, {%8,%9}, {%0,%1,%2,%3};"
        : "+f"(d[0]), "+f"(d[1]), "+f"(d[2]), "+f"(d[3])
        : "r"(a0), "r"(a1), "r"(a2), "r"(a3), "r"(b0), "r"(b1));
}
__device__ __forceinline__ uint32_t pack_bf2(__nv_bfloat16 lo, __nv_bfloat16 hi) {
    __nv_bfloat162 t(lo, hi);
    return *reinterpret_cast<uint32_t*>(&t);
}
__device__ __forceinline__ void split_bf16(float v, __nv_bfloat16& hi, float& lo) {
    hi = __float2bfloat16(v);
    lo = v - __bfloat162float(hi);
}

__device__ __forceinline__ float dot28r(const float* x, const float* w) {
    const float4* w4 = reinterpret_cast<const float4*>(w);
    float acc = 0.0f;
#pragma unroll
    for (int j = 0; j < 7; j++) {
        float4 b = w4[j];
        acc = fmaf(x[4 * j], b.x, acc);
        acc = fmaf(x[4 * j + 1], b.y, acc);
        acc = fmaf(x[4 * j + 2], b.z, acc);
        acc = fmaf(x[4 * j + 3], b.w, acc);
    }
    return acc;
}

__global__ __launch_bounds__(512, 1)
void span_mma_kernel(
    const float* __restrict__ emb,
    const int*   __restrict__ span_lengths,
    const int*   __restrict__ num_spans,
    const float* __restrict__ in_proj_w, const float* __restrict__ in_proj_b,
    const float* __restrict__ out_proj_w, const float* __restrict__ out_proj_b,
    const float* __restrict__ ln1_g, const float* __restrict__ ln1_b,
    const float* __restrict__ lin1_w, const float* __restrict__ lin1_b,
    const float* __restrict__ lin2_w, const float* __restrict__ lin2_b,
    const float* __restrict__ ln2_g, const float* __restrict__ ln2_b,
    const float* __restrict__ pad_token,
    float* __restrict__ outp)
{
    extern __shared__ char smc[];
    float* smf = reinterpret_cast<float*>(smc);
    const int tid = threadIdx.x, warp = tid >> 5, lane = tid & 31;

    {
        int4 z = make_int4(0, 0, 0, 0);
        int4* d = reinterpret_cast<int4*>(smc + XH_B);
        for (int i = tid; i < (SMEM_END_B - XH_B) / 16; i += 512) d[i] = z;
    }
    for (int i = tid; i < 2352; i += 512) smf[F_WQKV + i] = in_proj_w[i];
    for (int i = tid; i < 84;  i += 512) smf[F_BQKV + i] = in_proj_b[i];
    for (int i = tid; i < 784; i += 512) smf[F_WO + i]   = out_proj_w[i];
    if (tid < 256) smf[F_B1 + tid] = lin1_b[tid];
    if (tid < 32) {
        smf[F_B2 + tid]  = (tid < 28) ? lin2_b[tid] : 0.0f;
        smf[F_G2 + tid]  = (tid < 28) ? ln2_g[tid]  : 0.0f;
        smf[F_B2L + tid] = (tid < 28) ? ln2_b[tid]  : 0.0f;
    }
    if (tid < 28) {
        smf[F_BO + tid]  = out_proj_b[tid];
        smf[F_G1 + tid]  = ln1_g[tid];
        smf[F_B1L + tid] = ln1_b[tid];
        smf[F_PAD + tid] = pad_token[tid];
    }
    __syncthreads();
    for (int i = tid; i < 7168; i += 512) {
        int f = i / 28, e = i % 28;
        __nv_bfloat16 hh; float lf; split_bf16(lin1_w[i], hh, lf);
        *reinterpret_cast<__nv_bfloat16*>(smc + W1H_B + (f * 40 + e) * 2) = hh;
        *reinterpret_cast<__nv_bfloat16*>(smc + W1L_B + (f * 40 + e) * 2) = __float2bfloat16(lf);
    }
    for (int i = tid; i < 7168; i += 512) {
        int e = i / 256, f = i % 256;
        __nv_bfloat16 hh; float lf; split_bf16(lin2_w[i], hh, lf);
        *reinterpret_cast<__nv_bfloat16*>(smc + W2H_B + (e * 264 + f) * 2) = hh;
        *reinterpret_cast<__nv_bfloat16*>(smc + W2L_B + (e * 264 + f) * 2) = __float2bfloat16(lf);
    }
    __syncthreads();

    const uint32_t* XHw  = reinterpret_cast<const uint32_t*>(smc + XH_B);
    const uint32_t* XLw  = reinterpret_cast<const uint32_t*>(smc + XL_B);
    const uint32_t* W1Hw = reinterpret_cast<const uint32_t*>(smc + W1H_B);
    const uint32_t* W1Lw = reinterpret_cast<const uint32_t*>(smc + W1L_B);
    const uint32_t* W2Hw = reinterpret_cast<const uint32_t*>(smc + W2H_B);
    const uint32_t* W2Lw = reinterpret_cast<const uint32_t*>(smc + W2L_B);
    int* lens = reinterpret_cast<int*>(smf + I_LEN);
    int* vld  = reinterpret_cast<int*>(smf + I_VAL);

    const int l = lane & 7, h = lane >> 3, e0h = h * 7;
    const int gq = lane >> 2, tq = lane & 3;
    float* A  = smf + F_SCR + warp * 672;
    float* Kb = A + 224;
    float* Vb = A + 448;

    for (int g = blockIdx.x; g < NG; g += gridDim.x) {
        // ---------------- PHASE 1: 2 spans per warp ----------------
        for (int j = 0; j < 2; j++) {
            const int sl = warp * 2 + j;
            const int span = g * 32 + sl;
            const int b = span >> 9, t = span & (T_ - 1);
            {
                const float4* src = reinterpret_cast<const float4*>(emb + span * 224);
                float4* A4 = reinterpret_cast<float4*>(A);
                A4[lane] = src[lane];
                if (lane < 24) A4[lane + 32] = src[lane + 32];
            }
            __syncwarp();
            float xr[28];
            {
                const float4* r4 = reinterpret_cast<const float4*>(A + l * 28);
#pragma unroll
                for (int j2 = 0; j2 < 7; j2++) {
                    float4 v = r4[j2];
                    xr[4 * j2] = v.x; xr[4 * j2 + 1] = v.y; xr[4 * j2 + 2] = v.z; xr[4 * j2 + 3] = v.w;
                }
            }
            float q[7];
#pragma unroll
            for (int d = 0; d < 7; d++) {
                const int rq = e0h + d;
                q[d]     = smf[F_BQKV + rq]      + dot28r(xr, smf + F_WQKV + rq * 28);
                float kk = smf[F_BQKV + 28 + rq] + dot28r(xr, smf + F_WQKV + (28 + rq) * 28);
                float vv = smf[F_BQKV + 56 + rq] + dot28r(xr, smf + F_WQKV + (56 + rq) * 28);
                Kb[l * 28 + rq] = kk;
                Vb[l * 28 + rq] = vv;
            }
            __syncwarp();
            const int len = span_lengths[span];
            float s[8];
#pragma unroll
            for (int kk = 0; kk < 8; kk++) {
                const float* kr = Kb + kk * 28 + e0h;
                float acc = 0.0f;
#pragma unroll
                for (int d = 0; d < 7; d++) acc = fmaf(q[d], kr[d], acc);
                s[kk] = (kk < len) ? acc * 0.3779644730092272f : -1e9f;
            }
            float mx = s[0];
#pragma unroll
            for (int kk = 1; kk < 8; kk++) mx = fmaxf(mx, s[kk]);
            float p[8], ps = 0.0f;
#pragma unroll
            for (int kk = 0; kk < 8; kk++) { p[kk] = __expf(s[kk] - mx); ps += p[kk]; }
            const float pinv = 1.0f / ps;
            float ao[7];
#pragma unroll
            for (int d = 0; d < 7; d++) {
                float acc = 0.0f;
#pragma unroll
                for (int kk = 0; kk < 8; kk++) acc = fmaf(p[kk], Vb[kk * 28 + e0h + d], acc);
                ao[d] = acc * pinv;
            }
            __syncwarp();
#pragma unroll
            for (int d = 0; d < 7; d++) Kb[l * 28 + e0h + d] = ao[d];
            __syncwarp();
            float aor[28];
            {
                const float4* r4 = reinterpret_cast<const float4*>(Kb + l * 28);
#pragma unroll
                for (int j2 = 0; j2 < 7; j2++) {
                    float4 v = r4[j2];
                    aor[4 * j2] = v.x; aor[4 * j2 + 1] = v.y; aor[4 * j2 + 2] = v.z; aor[4 * j2 + 3] = v.w;
                }
            }
            float y[7];
#pragma unroll
            for (int d = 0; d < 7; d++) {
                const int ep = e0h + d;
                y[d] = A[l * 28 + ep] + smf[F_BO + ep] + dot28r(aor, smf + F_WO + ep * 28);
            }
            float s1 = 0.0f;
#pragma unroll
            for (int d = 0; d < 7; d++) s1 += y[d];
            s1 += __shfl_xor_sync(0xffffffffu, s1, 8);
            s1 += __shfl_xor_sync(0xffffffffu, s1, 16);
            const float mu1 = s1 * (1.0f / 28.0f);
            float s2 = 0.0f;
#pragma unroll
            for (int d = 0; d < 7; d++) { float dd = y[d] - mu1; s2 += dd * dd; }
            s2 += __shfl_xor_sync(0xffffffffu, s2, 8);
            s2 += __shfl_xor_sync(0xffffffffu, s2, 16);
            const float rs1 = rsqrtf(s2 * (1.0f / 28.0f) + 1e-5f);
            const int row = sl * 8 + l;
#pragma unroll
            for (int d = 0; d < 7; d++) {
                const int ep = e0h + d;
                float v = (y[d] - mu1) * rs1 * smf[F_G1 + ep] + smf[F_B1L + ep];
                smf[F_XN + row * 28 + ep] = v;
                __nv_bfloat16 hh; float lf; split_bf16(v, hh, lf);
                *reinterpret_cast<__nv_bfloat16*>(smc + XH_B + (row * 40 + ep) * 2) = hh;
                *reinterpret_cast<__nv_bfloat16*>(smc + XL_B + (row * 40 + ep) * 2) = __float2bfloat16(lf);
            }
            if (lane == 0) { lens[sl] = len; vld[sl] = (t < num_spans[b]) ? 1 : 0; }
            __syncwarp();
        }
        __syncwarp();

        // ---------------- PHASE 2: FFN via mma.sync (16 tokens per warp) ----------------
        const int m0 = warp * 16;
        uint32_t ah[2][4], al[2][4];
#pragma unroll
        for (int kt = 0; kt < 2; kt++) {
            const int w0 = (m0 + gq) * 20 + kt * 8 + tq;
            ah[kt][0] = XHw[w0];       ah[kt][1] = XHw[w0 + 160];
            ah[kt][2] = XHw[w0 + 4];   ah[kt][3] = XHw[w0 + 164];
            al[kt][0] = XLw[w0];       al[kt][1] = XLw[w0 + 160];
            al[kt][2] = XLw[w0 + 4];   al[kt][3] = XLw[w0 + 164];
        }

        float d2[4][4];
#pragma unroll
        for (int nt = 0; nt < 4; nt++)
#pragma unroll
            for (int r = 0; r < 4; r++) d2[nt][r] = 0.0f;

        for (int fc = 0; fc < 16; fc++) {
            float d1[2][4];
#pragma unroll
            for (int nt = 0; nt < 2; nt++)
#pragma unroll
                for (int r = 0; r < 4; r++) d1[nt][r] = 0.0f;
#pragma unroll
            for (int kt = 0; kt < 2; kt++)
#pragma unroll
                for (int nt = 0; nt < 2; nt++) {
                    const int w = (fc * 16 + nt * 8 + gq) * 20 + kt * 8 + tq;
                    const uint32_t b0h = W1Hw[w], b1h = W1Hw[w + 4];
                    const uint32_t b0l = W1Lw[w], b1l = W1Lw[w + 4];
                    mma_bf16(d1[nt], ah[kt][0], ah[kt][1], ah[kt][2], ah[kt][3], b0h, b1h);
                    mma_bf16(d1[nt], al[kt][0], al[kt][1], al[kt][2], al[kt][3], b0h, b1h);
                    mma_bf16(d1[nt], ah[kt][0], ah[kt][1], ah[kt][2], ah[kt][3], b0l, b1l);
                }
            uint32_t a2h[4], a2l[4];
#pragma unroll
            for (int nt = 0; nt < 2; nt++) {
                const int fe = fc * 16 + nt * 8 + 2 * tq;
                const float bz0 = smf[F_B1 + fe], bz1 = smf[F_B1 + fe + 1];
                float h0 = fmaxf(d1[nt][0] + bz0, 0.0f);
                float h1 = fmaxf(d1[nt][1] + bz1, 0.0f);
                float h2 = fmaxf(d1[nt][2] + bz0, 0.0f);
                float h3 = fmaxf(d1[nt][3] + bz1, 0.0f);
                __nv_bfloat16 q0, q1, q2, q3; float l0, l1, l2, l3;
                split_bf16(h0, q0, l0); split_bf16(h1, q1, l1);
                split_bf16(h2, q2, l2); split_bf16(h3, q3, l3);
                a2h[nt * 2 + 0] = pack_bf2(q0, q1);
                a2h[nt * 2 + 1] = pack_bf2(q2, q3);
                a2l[nt * 2 + 0] = pack_bf2(__float2bfloat16(l0), __float2bfloat16(l1));
                a2l[nt * 2 + 1] = pack_bf2(__float2bfloat16(l2), __float2bfloat16(l3));
            }
#pragma unroll
            for (int nt2 = 0; nt2 < 4; nt2++) {
                const int w2 = (nt2 * 8 + gq) * 132 + fc * 8 + tq;
                const uint32_t b0h = W2Hw[w2], b1h = W2Hw[w2 + 4];
                const uint32_t b0l = W2Lw[w2], b1l = W2Lw[w2 + 4];
                mma_bf16(d2[nt2], a2h[0], a2h[1], a2h[2], a2h[3], b0h, b1h);
                mma_bf16(d2[nt2], a2l[0], a2l[1], a2l[2], a2l[3], b0h, b1h);
                mma_bf16(d2[nt2], a2h[0], a2h[1], a2h[2], a2h[3], b0l, b1l);
            }
        }

        // ---------------- EPILOGUE ----------------
        {
            const int tokA = m0 + gq, tokB = tokA + 8;
            const int slA = warp * 2, slB = slA + 1;
            float vA[8], vB[8];
            float sA = 0.0f, qA = 0.0f, sB = 0.0f, qB = 0.0f;
#pragma unroll
            for (int nt = 0; nt < 4; nt++) {
                const int e0 = nt * 8 + 2 * tq;
                const bool ok = (nt < 3) || (tq < 2);
                float xnA0 = ok ? smf[F_XN + tokA * 28 + e0] : 0.0f;
                float xnA1 = ok ? smf[F_XN + tokA * 28 + e0 + 1] : 0.0f;
                float xnB0 = ok ? smf[F_XN + tokB * 28 + e0] : 0.0f;
                float xnB1 = ok ? smf[F_XN + tokB * 28 + e0 + 1] : 0.0f;
                const float b20 = smf[F_B2 + e0], b21 = smf[F_B2 + e0 + 1];
                float a0 = ok ? (d2[nt][0] + b20 + xnA0) : 0.0f;
                float a1 = ok ? (d2[nt][1] + b21 + xnA1) : 0.0f;
                float b0 = ok ? (d2[nt][2] + b20 + xnB0) : 0.0f;
                float b1 = ok ? (d2[nt][3] + b21 + xnB1) : 0.0f;
                vA[nt * 2] = a0; vA[nt * 2 + 1] = a1;
                vB[nt * 2] = b0; vB[nt * 2 + 1] = b1;
                sA += a0 + a1; qA += a0 * a0 + a1 * a1;
                sB += b0 + b1; qB += b0 * b0 + b1 * b1;
            }
            sA += __shfl_xor_sync(0xffffffffu, sA, 1); qA += __shfl_xor_sync(0xffffffffu, qA, 1);
            sA += __shfl_xor_sync(0xffffffffu, sA, 2); qA += __shfl_xor_sync(0xffffffffu, qA, 2);
            sB += __shfl_xor_sync(0xffffffffu, sB, 1); qB += __shfl_xor_sync(0xffffffffu, qB, 1);
            sB += __shfl_xor_sync(0xffffffffu, sB, 2); qB += __shfl_xor_sync(0xffffffffu, qB, 2);
            const float muA = sA * (1.0f / 28.0f), muB = sB * (1.0f / 28.0f);
            const float rsA = rsqrtf(fmaxf(qA * (1.0f / 28.0f) - muA * muA, 0.0f) + 1e-5f);
            const float rsB = rsqrtf(fmaxf(qB * (1.0f / 28.0f) - muB * muB, 0.0f) + 1e-5f);
            const int lenA = lens[slA], lenB = lens[slB];
            const float mA = ((tokA & 7) < lenA) ? 1.0f : 0.0f;
            const float mB = ((tokB & 7) < lenB) ? 1.0f : 0.0f;
            float pA[8], pB[8];
#pragma unroll
            for (int nt = 0; nt < 4; nt++) {
                const int e0 = nt * 8 + 2 * tq;
                const bool ok = (nt < 3) || (tq < 2);
                const float g20 = smf[F_G2 + e0], g21 = smf[F_G2 + e0 + 1];
                const float bl0 = smf[F_B2L + e0], bl1 = smf[F_B2L + e0 + 1];
                pA[nt * 2]     = ok ? ((vA[nt * 2]     - muA) * rsA * g20 + bl0) * mA : 0.0f;
                pA[nt * 2 + 1] = ok ? ((vA[nt * 2 + 1] - muA) * rsA * g21 + bl1) * mA : 0.0f;
                pB[nt * 2]     = ok ? ((vB[nt * 2]     - muB) * rsB * g20 + bl0) * mB : 0.0f;
                pB[nt * 2 + 1] = ok ? ((vB[nt * 2 + 1] - muB) * rsB * g21 + bl1) * mB : 0.0f;
            }
#pragma unroll
            for (int i = 0; i < 8; i++) {
                float a = pA[i], b = pB[i];
                a += __shfl_xor_sync(0xffffffffu, a, 4);  b += __shfl_xor_sync(0xffffffffu, b, 4);
                a += __shfl_xor_sync(0xffffffffu, a, 8);  b += __shfl_xor_sync(0xffffffffu, b, 8);
                a += __shfl_xor_sync(0xffffffffu, a, 16); b += __shfl_xor_sync(0xffffffffu, b, 16);
                pA[i] = a; pB[i] = b;
            }
            if (lane < 4) {
                const float ilA = 1.0f / (float)lenA, ilB = 1.0f / (float)lenB;
                const int spA = g * 32 + slA, spB = g * 32 + slB;
                const int okA = vld[slA], okB = vld[slB];
#pragma unroll
                for (int nt = 0; nt < 4; nt++) {
                    const int e0 = nt * 8 + 2 * tq;
                    if ((nt < 3) || (tq < 2)) {
                        outp[spA * 28 + e0]     = okA ? pA[nt * 2] * ilA     : smf[F_PAD + e0];
                        outp[spA * 28 + e0 + 1] = okA ? pA[nt * 2 + 1] * ilA : smf[F_PAD + e0 + 1];
                        outp[spB * 28 + e0]     = okB ? pB[nt * 2] * ilB     : smf[F_PAD + e0];
                        outp[spB * 28 + e0 + 1] = okB ? pB[nt * 2 + 1] * ilB : smf[F_PAD + e0 + 1];
                    }
                }
            }
        }
        __syncwarp();
    }
}

extern "C" void kernel_launch(void* const* d_in, const int* in_sizes, int n_in,
                              void* d_out, int out_size) {
    const float* emb          = (const float*)d_in[0];
    const int*   span_lengths = (const int*)  d_in[1];
    const int*   num_spans    = (const int*)  d_in[2];
    const float* in_proj_w    = (const float*)d_in[3];
    const float* in_proj_b    = (const float*)d_in[4];
    const float* out_proj_w   = (const float*)d_in[5];
    const float* out_proj_b   = (const float*)d_in[6];
    const float* ln1_g        = (const float*)d_in[7];
    const float* ln1_b        = (const float*)d_in[8];
    const float* lin1_w       = (const float*)d_in[9];
    const float* lin1_b       = (const float*)d_in[10];
    const float* lin2_w       = (const float*)d_in[11];
    const float* lin2_b       = (const float*)d_in[12];
    const float* ln2_g        = (const float*)d_in[13];
    const float* ln2_b        = (const float*)d_in[14];
    const float* pad_token    = (const float*)d_in[15];
    float* outp = (float*)d_out;

    cudaFuncSetAttribute(span_mma_kernel,
                         cudaFuncAttributeMaxDynamicSharedMemorySize, SMEM_END_B);

    span_mma_kernel<<<148, 512, SMEM_END_B>>>(
        emb, span_lengths, num_spans,
        in_proj_w, in_proj_b, out_proj_w, out_proj_b,
        ln1_g, ln1_b, lin1_w, lin1_b, lin2_w, lin2_b,
        ln2_g, ln2_b, pad_token, outp);
}

// round 10
// speedup vs baseline: 2.1866x; 1.0211x over previous
#include <cuda_runtime.h>
#include <cuda_bf16.h>
#include <cstdint>

#define T_ 512
#define NG 1024            // groups of 32 spans (256 tokens per block-group)

// ---------------- smem layout ----------------
#define F_WQKV 0
#define F_BQKV 2352
#define F_WO   2436
#define F_BO   3220
#define F_G1   3248
#define F_B1L  3276
#define F_B1   3304
#define F_B2   3560       // padded to 32 (pads zero)
#define F_G2   3592
#define F_B2L  3624
#define F_PAD  3656
#define I_LEN  3684       // int[32]
#define I_VAL  3716       // int[32]
#define F_SCR  3748       // 16 warps x 800 floats: A[224] | Kb[8*36] | Vb[8*36]
// byte offsets (16B aligned)
#define XH_B   66192      // X hi  [256 tok][40 halves]
#define XL_B   86672
#define W1H_B  107152     // W1 hi [256 f][40 halves]
#define W1L_B  127632
#define W2H_B  148112     // W2 hi [32 e][264 halves]
#define W2L_B  165008
#define SMEM_END_B 181904

__device__ __forceinline__ void mma_bf16(float* d, uint32_t a0, uint32_t a1,
                                         uint32_t a2, uint32_t a3,
                                         uint32_t b0, uint32_t b1) {
    asm volatile(
        "mma.sync.aligned.m16n8k16.row.col.f32.bf16.bf16.f32 "
        "{%0,%1,%2,%3}, {%4,%5,%6,%7}, {%8,%9}, {%0,%1,%2,%3};"
        : "+f"(d[0]), "+f"(d[1]), "+f"(d[2]), "+f"(d[3])
        : "r"(a0), "r"(a1), "r"(a2), "r"(a3), "r"(b0), "r"(b1));
}
__device__ __forceinline__ uint32_t pack_bf2(__nv_bfloat16 lo, __nv_bfloat16 hi) {
    __nv_bfloat162 t(lo, hi);
    return *reinterpret_cast<uint32_t*>(&t);
}
__device__ __forceinline__ void split_bf16(float v, __nv_bfloat16& hi, float& lo) {
    hi = __float2bfloat16(v);
    lo = v - __bfloat162float(hi);
}
__device__ __forceinline__ float dot28r(const float* x, const float* w) {
    const float4* w4 = reinterpret_cast<const float4*>(w);
    float acc = 0.0f;
#pragma unroll
    for (int j = 0; j < 7; j++) {
        float4 b = w4[j];
        acc = fmaf(x[4 * j], b.x, acc);
        acc = fmaf(x[4 * j + 1], b.y, acc);
        acc = fmaf(x[4 * j + 2], b.z, acc);
        acc = fmaf(x[4 * j + 3], b.w, acc);
    }
    return acc;
}

__global__ __launch_bounds__(512, 1)
void span_mma_kernel(
    const float* __restrict__ emb,
    const int*   __restrict__ span_lengths,
    const int*   __restrict__ num_spans,
    const float* __restrict__ in_proj_w, const float* __restrict__ in_proj_b,
    const float* __restrict__ out_proj_w, const float* __restrict__ out_proj_b,
    const float* __restrict__ ln1_g, const float* __restrict__ ln1_b,
    const float* __restrict__ lin1_w, const float* __restrict__ lin1_b,
    const float* __restrict__ lin2_w, const float* __restrict__ lin2_b,
    const float* __restrict__ ln2_g, const float* __restrict__ ln2_b,
    const float* __restrict__ pad_token,
    float* __restrict__ outp)
{
    extern __shared__ char smc[];
    float* smf = reinterpret_cast<float*>(smc);
    const int tid = threadIdx.x, warp = tid >> 5, lane = tid & 31;

    {
        int4 z = make_int4(0, 0, 0, 0);
        int4* d = reinterpret_cast<int4*>(smc + XH_B);
        for (int i = tid; i < (SMEM_END_B - XH_B) / 16; i += 512) d[i] = z;
    }
    for (int i = tid; i < 2352; i += 512) smf[F_WQKV + i] = in_proj_w[i];
    for (int i = tid; i < 84;  i += 512) smf[F_BQKV + i] = in_proj_b[i];
    for (int i = tid; i < 784; i += 512) smf[F_WO + i]   = out_proj_w[i];
    if (tid < 256) smf[F_B1 + tid] = lin1_b[tid];
    if (tid < 32) {
        smf[F_B2 + tid]  = (tid < 28) ? lin2_b[tid] : 0.0f;
        smf[F_G2 + tid]  = (tid < 28) ? ln2_g[tid]  : 0.0f;
        smf[F_B2L + tid] = (tid < 28) ? ln2_b[tid]  : 0.0f;
    }
    if (tid < 28) {
        smf[F_BO + tid]  = out_proj_b[tid];
        smf[F_G1 + tid]  = ln1_g[tid];
        smf[F_B1L + tid] = ln1_b[tid];
        smf[F_PAD + tid] = pad_token[tid];
    }
    __syncthreads();
    for (int i = tid; i < 7168; i += 512) {
        int f = i / 28, e = i % 28;
        __nv_bfloat16 hh; float lf; split_bf16(lin1_w[i], hh, lf);
        *reinterpret_cast<__nv_bfloat16*>(smc + W1H_B + (f * 40 + e) * 2) = hh;
        *reinterpret_cast<__nv_bfloat16*>(smc + W1L_B + (f * 40 + e) * 2) = __float2bfloat16(lf);
    }
    for (int i = tid; i < 7168; i += 512) {
        int e = i / 256, f = i % 256;
        __nv_bfloat16 hh; float lf; split_bf16(lin2_w[i], hh, lf);
        *reinterpret_cast<__nv_bfloat16*>(smc + W2H_B + (e * 264 + f) * 2) = hh;
        *reinterpret_cast<__nv_bfloat16*>(smc + W2L_B + (e * 264 + f) * 2) = __float2bfloat16(lf);
    }
    __syncthreads();

    const uint32_t* XHw  = reinterpret_cast<const uint32_t*>(smc + XH_B);
    const uint32_t* XLw  = reinterpret_cast<const uint32_t*>(smc + XL_B);
    const uint32_t* W1Hw = reinterpret_cast<const uint32_t*>(smc + W1H_B);
    const uint32_t* W1Lw = reinterpret_cast<const uint32_t*>(smc + W1L_B);
    const uint32_t* W2Hw = reinterpret_cast<const uint32_t*>(smc + W2H_B);
    const uint32_t* W2Lw = reinterpret_cast<const uint32_t*>(smc + W2L_B);
    int* lens = reinterpret_cast<int*>(smf + I_LEN);
    int* vld  = reinterpret_cast<int*>(smf + I_VAL);

    const int l = lane & 7, h = lane >> 3, e0h = h * 7;
    const int gq = lane >> 2, tq = lane & 3;
    float* A  = smf + F_SCR + warp * 800;
    float* Kb = A + 224;    // [8 tok][36], head slices 8-aligned
    float* Vb = A + 512;    // [8 tok][36]

    for (int g = blockIdx.x; g < NG; g += gridDim.x) {
        // ---------------- PHASE 1: 2 spans per warp ----------------
        for (int j = 0; j < 2; j++) {
            const int sl = warp * 2 + j;
            const int span = g * 32 + sl;
            const int b = span >> 9, t = span & (T_ - 1);
            {
                const float4* src = reinterpret_cast<const float4*>(emb + span * 224);
                float4* A4 = reinterpret_cast<float4*>(A);
                A4[lane] = src[lane];
                if (lane < 24) A4[lane + 32] = src[lane + 32];
            }
            __syncwarp();
            float xr[28];
            {
                const float4* r4 = reinterpret_cast<const float4*>(A + l * 28);
#pragma unroll
                for (int j2 = 0; j2 < 7; j2++) {
                    float4 v = r4[j2];
                    xr[4 * j2] = v.x; xr[4 * j2 + 1] = v.y; xr[4 * j2 + 2] = v.z; xr[4 * j2 + 3] = v.w;
                }
            }
            float q[7];
#pragma unroll
            for (int d = 0; d < 7; d++) {
                const int rq = e0h + d;
                q[d]     = smf[F_BQKV + rq]      + dot28r(xr, smf + F_WQKV + rq * 28);
                float kk = smf[F_BQKV + 28 + rq] + dot28r(xr, smf + F_WQKV + (28 + rq) * 28);
                float vv = smf[F_BQKV + 56 + rq] + dot28r(xr, smf + F_WQKV + (56 + rq) * 28);
                Kb[l * 36 + h * 8 + d] = kk;   // bank 4l+8h+d: conflict-free
                Vb[l * 36 + h * 8 + d] = vv;
            }
            __syncwarp();
            const int len = span_lengths[span];
            float s[8];
#pragma unroll
            for (int kk = 0; kk < 8; kk++) {
                const float4 ka = *reinterpret_cast<const float4*>(Kb + kk * 36 + h * 8);
                const float4 kb = *reinterpret_cast<const float4*>(Kb + kk * 36 + h * 8 + 4);
                float acc = q[0] * ka.x + q[1] * ka.y + q[2] * ka.z + q[3] * ka.w
                          + q[4] * kb.x + q[5] * kb.y + q[6] * kb.z;
                s[kk] = (kk < len) ? acc * 0.3779644730092272f : -1e9f;
            }
            float mx = s[0];
#pragma unroll
            for (int kk = 1; kk < 8; kk++) mx = fmaxf(mx, s[kk]);
            float p[8], ps = 0.0f;
#pragma unroll
            for (int kk = 0; kk < 8; kk++) { p[kk] = __expf(s[kk] - mx); ps += p[kk]; }
            const float pinv = 1.0f / ps;
            float ao[7];
#pragma unroll
            for (int d = 0; d < 7; d++) ao[d] = 0.0f;
#pragma unroll
            for (int kk = 0; kk < 8; kk++) {
                const float4 va = *reinterpret_cast<const float4*>(Vb + kk * 36 + h * 8);
                const float4 vb = *reinterpret_cast<const float4*>(Vb + kk * 36 + h * 8 + 4);
                ao[0] = fmaf(p[kk], va.x, ao[0]); ao[1] = fmaf(p[kk], va.y, ao[1]);
                ao[2] = fmaf(p[kk], va.z, ao[2]); ao[3] = fmaf(p[kk], va.w, ao[3]);
                ao[4] = fmaf(p[kk], vb.x, ao[4]); ao[5] = fmaf(p[kk], vb.y, ao[5]);
                ao[6] = fmaf(p[kk], vb.z, ao[6]);
            }
            __syncwarp();   // all K reads done before overwrite with ao
#pragma unroll
            for (int d = 0; d < 7; d++) Kb[l * 36 + h * 8 + d] = ao[d] * pinv;
            __syncwarp();

            // full ao row for token l (slots 7,15,23,31 garbage, unused)
            float ar[32];
#pragma unroll
            for (int hh = 0; hh < 4; hh++) {
                const float4 a = *reinterpret_cast<const float4*>(Kb + l * 36 + hh * 8);
                const float4 b2 = *reinterpret_cast<const float4*>(Kb + l * 36 + hh * 8 + 4);
                ar[hh * 8 + 0] = a.x;  ar[hh * 8 + 1] = a.y;  ar[hh * 8 + 2] = a.z;  ar[hh * 8 + 3] = a.w;
                ar[hh * 8 + 4] = b2.x; ar[hh * 8 + 5] = b2.y; ar[hh * 8 + 6] = b2.z; ar[hh * 8 + 7] = 0.0f;
            }
            float y[7];
#pragma unroll
            for (int d = 0; d < 7; d++) {
                const int ep = e0h + d;
                const float4* w4 = reinterpret_cast<const float4*>(smf + F_WO + ep * 28);
                float wr[28];
#pragma unroll
                for (int j2 = 0; j2 < 7; j2++) {
                    float4 w = w4[j2];
                    wr[4 * j2] = w.x; wr[4 * j2 + 1] = w.y; wr[4 * j2 + 2] = w.z; wr[4 * j2 + 3] = w.w;
                }
                float o = 0.0f;
#pragma unroll
                for (int hh = 0; hh < 4; hh++)
#pragma unroll
                    for (int dd = 0; dd < 7; dd++)
                        o = fmaf(ar[hh * 8 + dd], wr[hh * 7 + dd], o);
                y[d] = A[l * 28 + ep] + smf[F_BO + ep] + o;
            }
            float s1 = 0.0f;
#pragma unroll
            for (int d = 0; d < 7; d++) s1 += y[d];
            s1 += __shfl_xor_sync(0xffffffffu, s1, 8);
            s1 += __shfl_xor_sync(0xffffffffu, s1, 16);
            const float mu1 = s1 * (1.0f / 28.0f);
            float s2 = 0.0f;
#pragma unroll
            for (int d = 0; d < 7; d++) { float dd = y[d] - mu1; s2 += dd * dd; }
            s2 += __shfl_xor_sync(0xffffffffu, s2, 8);
            s2 += __shfl_xor_sync(0xffffffffu, s2, 16);
            const float rs1 = rsqrtf(s2 * (1.0f / 28.0f) + 1e-5f);
            const int row = sl * 8 + l;
#pragma unroll
            for (int d = 0; d < 7; d++) {
                const int ep = e0h + d;
                float v = (y[d] - mu1) * rs1 * smf[F_G1 + ep] + smf[F_B1L + ep];
                __nv_bfloat16 hh; float lf; split_bf16(v, hh, lf);
                *reinterpret_cast<__nv_bfloat16*>(smc + XH_B + (row * 40 + ep) * 2) = hh;
                *reinterpret_cast<__nv_bfloat16*>(smc + XL_B + (row * 40 + ep) * 2) = __float2bfloat16(lf);
            }
            if (lane == 0) { lens[sl] = len; vld[sl] = (t < num_spans[b]) ? 1 : 0; }
            __syncwarp();
        }
        __syncwarp();

        // ---------------- PHASE 2: FFN via mma.sync (16 tokens per warp) ----------------
        const int m0 = warp * 16;
        uint32_t ah[2][4], al[2][4];
#pragma unroll
        for (int kt = 0; kt < 2; kt++) {
            const int w0 = (m0 + gq) * 20 + kt * 8 + tq;
            ah[kt][0] = XHw[w0];       ah[kt][1] = XHw[w0 + 160];
            ah[kt][2] = XHw[w0 + 4];   ah[kt][3] = XHw[w0 + 164];
            al[kt][0] = XLw[w0];       al[kt][1] = XLw[w0 + 160];
            al[kt][2] = XLw[w0 + 4];   al[kt][3] = XLw[w0 + 164];
        }

        float d2[4][4];
#pragma unroll
        for (int nt = 0; nt < 4; nt++)
#pragma unroll
            for (int r = 0; r < 4; r++) d2[nt][r] = 0.0f;

        for (int fc = 0; fc < 16; fc++) {
            float d1[2][4];
#pragma unroll
            for (int nt = 0; nt < 2; nt++)
#pragma unroll
                for (int r = 0; r < 4; r++) d1[nt][r] = 0.0f;
#pragma unroll
            for (int kt = 0; kt < 2; kt++)
#pragma unroll
                for (int nt = 0; nt < 2; nt++) {
                    const int w = (fc * 16 + nt * 8 + gq) * 20 + kt * 8 + tq;
                    const uint32_t b0h = W1Hw[w], b1h = W1Hw[w + 4];
                    const uint32_t b0l = W1Lw[w], b1l = W1Lw[w + 4];
                    mma_bf16(d1[nt], ah[kt][0], ah[kt][1], ah[kt][2], ah[kt][3], b0h, b1h);
                    mma_bf16(d1[nt], al[kt][0], al[kt][1], al[kt][2], al[kt][3], b0h, b1h);
                    mma_bf16(d1[nt], ah[kt][0], ah[kt][1], ah[kt][2], ah[kt][3], b0l, b1l);
                }
            uint32_t a2h[4], a2l[4];
#pragma unroll
            for (int nt = 0; nt < 2; nt++) {
                const int fe = fc * 16 + nt * 8 + 2 * tq;
                const float bz0 = smf[F_B1 + fe], bz1 = smf[F_B1 + fe + 1];
                float h0 = fmaxf(d1[nt][0] + bz0, 0.0f);
                float h1 = fmaxf(d1[nt][1] + bz1, 0.0f);
                float h2 = fmaxf(d1[nt][2] + bz0, 0.0f);
                float h3 = fmaxf(d1[nt][3] + bz1, 0.0f);
                __nv_bfloat16 q0, q1, q2, q3; float l0, l1, l2, l3;
                split_bf16(h0, q0, l0); split_bf16(h1, q1, l1);
                split_bf16(h2, q2, l2); split_bf16(h3, q3, l3);
                a2h[nt * 2 + 0] = pack_bf2(q0, q1);
                a2h[nt * 2 + 1] = pack_bf2(q2, q3);
                a2l[nt * 2 + 0] = pack_bf2(__float2bfloat16(l0), __float2bfloat16(l1));
                a2l[nt * 2 + 1] = pack_bf2(__float2bfloat16(l2), __float2bfloat16(l3));
            }
#pragma unroll
            for (int nt2 = 0; nt2 < 4; nt2++) {
                const int w2 = (nt2 * 8 + gq) * 132 + fc * 8 + tq;
                const uint32_t b0h = W2Hw[w2], b1h = W2Hw[w2 + 4];
                const uint32_t b0l = W2Lw[w2], b1l = W2Lw[w2 + 4];
                mma_bf16(d2[nt2], a2h[0], a2h[1], a2h[2], a2h[3], b0h, b1h);
                mma_bf16(d2[nt2], a2l[0], a2l[1], a2l[2], a2l[3], b0h, b1h);
                mma_bf16(d2[nt2], a2h[0], a2h[1], a2h[2], a2h[3], b0l, b1l);
            }
        }

        // ---------------- EPILOGUE: one span at a time (low reg pressure) -------------
#pragma unroll
        for (int sp2 = 0; sp2 < 2; sp2++) {
            const int tok = m0 + gq + sp2 * 8;
            const int sl = warp * 2 + sp2;
            const int c0 = sp2 * 2;           // d2 component pair for this span
            float v[8];
            float ssum = 0.0f, sq = 0.0f;
#pragma unroll
            for (int nt = 0; nt < 4; nt++) {
                const int e0 = nt * 8 + 2 * tq;
                const bool ok = (nt < 3) || (tq < 2);
                // xn = hi + lo from bf16 tiles (2^-16 accurate)
                const uint32_t uh = XHw[tok * 20 + nt * 4 + tq];
                const uint32_t ul = XLw[tok * 20 + nt * 4 + tq];
                const __nv_bfloat162 bh = *reinterpret_cast<const __nv_bfloat162*>(&uh);
                const __nv_bfloat162 bl = *reinterpret_cast<const __nv_bfloat162*>(&ul);
                const float xn0 = __bfloat162float(bh.x) + __bfloat162float(bl.x);
                const float xn1 = __bfloat162float(bh.y) + __bfloat162float(bl.y);
                float a0 = ok ? (d2[nt][c0]     + smf[F_B2 + e0]     + xn0) : 0.0f;
                float a1 = ok ? (d2[nt][c0 + 1] + smf[F_B2 + e0 + 1] + xn1) : 0.0f;
                v[nt * 2] = a0; v[nt * 2 + 1] = a1;
                ssum += a0 + a1; sq += a0 * a0 + a1 * a1;
            }
            ssum += __shfl_xor_sync(0xffffffffu, ssum, 1); sq += __shfl_xor_sync(0xffffffffu, sq, 1);
            ssum += __shfl_xor_sync(0xffffffffu, ssum, 2); sq += __shfl_xor_sync(0xffffffffu, sq, 2);
            const float mu = ssum * (1.0f / 28.0f);
            const float rs = rsqrtf(fmaxf(sq * (1.0f / 28.0f) - mu * mu, 0.0f) + 1e-5f);
            const int len = lens[sl];
            const float m = (gq < len) ? 1.0f : 0.0f;
            float pz[8];
#pragma unroll
            for (int nt = 0; nt < 4; nt++) {
                const int e0 = nt * 8 + 2 * tq;
                const bool ok = (nt < 3) || (tq < 2);
                pz[nt * 2]     = ok ? ((v[nt * 2]     - mu) * rs * smf[F_G2 + e0]     + smf[F_B2L + e0])     * m : 0.0f;
                pz[nt * 2 + 1] = ok ? ((v[nt * 2 + 1] - mu) * rs * smf[F_G2 + e0 + 1] + smf[F_B2L + e0 + 1]) * m : 0.0f;
            }
#pragma unroll
            for (int i = 0; i < 8; i++) {
                float a = pz[i];
                a += __shfl_xor_sync(0xffffffffu, a, 4);
                a += __shfl_xor_sync(0xffffffffu, a, 8);
                a += __shfl_xor_sync(0xffffffffu, a, 16);
                pz[i] = a;
            }
            if (lane < 4) {
                const float il = 1.0f / (float)len;
                const int sp = g * 32 + sl;
                const int okv = vld[sl];
#pragma unroll
                for (int nt = 0; nt < 4; nt++) {
                    const int e0 = nt * 8 + 2 * tq;
                    if ((nt < 3) || (tq < 2)) {
                        outp[sp * 28 + e0]     = okv ? pz[nt * 2] * il     : smf[F_PAD + e0];
                        outp[sp * 28 + e0 + 1] = okv ? pz[nt * 2 + 1] * il : smf[F_PAD + e0 + 1];
                    }
                }
            }
        }
        __syncwarp();
    }
}

extern "C" void kernel_launch(void* const* d_in, const int* in_sizes, int n_in,
                              void* d_out, int out_size) {
    const float* emb          = (const float*)d_in[0];
    const int*   span_lengths = (const int*)  d_in[1];
    const int*   num_spans    = (const int*)  d_in[2];
    const float* in_proj_w    = (const float*)d_in[3];
    const float* in_proj_b    = (const float*)d_in[4];
    const float* out_proj_w   = (const float*)d_in[5];
    const float* out_proj_b   = (const float*)d_in[6];
    const float* ln1_g        = (const float*)d_in[7];
    const float* ln1_b        = (const float*)d_in[8];
    const float* lin1_w       = (const float*)d_in[9];
    const float* lin1_b       = (const float*)d_in[10];
    const float* lin2_w       = (const float*)d_in[11];
    const float* lin2_b       = (const float*)d_in[12];
    const float* ln2_g        = (const float*)d_in[13];
    const float* ln2_b        = (const float*)d_in[14];
    const float* pad_token    = (const float*)d_in[15];
    float* outp = (float*)d_out;

    cudaFuncSetAttribute(span_mma_kernel,
                         cudaFuncAttributeMaxDynamicSharedMemorySize, SMEM_END_B);

    span_mma_kernel<<<148, 512, SMEM_END_B>>>(
        emb, span_lengths, num_spans,
        in_proj_w, in_proj_b, out_proj_w, out_proj_b,
        ln1_g, ln1_b, lin1_w, lin1_b, lin2_w, lin2_b,
        ln2_g, ln2_b, pad_token, outp);
}

// round 11
// speedup vs baseline: 2.4047x; 1.0997x over previous
#include <cuda_runtime.h>
#include <cuda_bf16.h>
#include <cstdint>

#define T_ 512
#define NG 1024            // groups of 32 spans (256 tokens per block-group)

// ---------------- smem layout ----------------
// float indices
#define F_BQKV 0          // 84
#define F_WO   84         // 784
#define F_BO   868
#define F_G1   896
#define F_B1L  924
#define F_B1   952        // 256
#define F_B2   1208       // 32 (pad zero)
#define F_G2   1240
#define F_B2L  1272
#define F_PAD  1304
#define I_LEN  1332       // int[32]
#define I_VAL  1364       // int[32]
// byte offsets (16B aligned)
#define XH_B   5632       // X hi  [256 tok][36 halves]   (emb-split, then xn-split)
#define XL_B   24064
#define W1H_B  42496      // W1 hi [256 f][36 halves]
#define W1L_B  60928
#define W2H_B  79360      // W2 hi [32 e][264 halves]
#define W2L_B  96256
#define WQH_B  113152     // Wqkv hi [88 r][36 halves]
#define WQL_B  119488
#define SCR_B  125824     // 16 warps x 1600 floats  (QKV scratch [16 tok][100])
#define SCRF   31456
#define SMEM_END_B 228224

__device__ __forceinline__ void mma_bf16(float* d, uint32_t a0, uint32_t a1,
                                         uint32_t a2, uint32_t a3,
                                         uint32_t b0, uint32_t b1) {
    asm volatile(
        "mma.sync.aligned.m16n8k16.row.col.f32.bf16.bf16.f32 "
        "{%0,%1,%2,%3}, {%4,%5,%6,%7}, {%8,%9}, {%0,%1,%2,%3};"
        : "+f"(d[0]), "+f"(d[1]), "+f"(d[2]), "+f"(d[3])
        : "r"(a0), "r"(a1), "r"(a2), "r"(a3), "r"(b0), "r"(b1));
}
__device__ __forceinline__ uint32_t pack_bf2(__nv_bfloat16 lo, __nv_bfloat16 hi) {
    __nv_bfloat162 t(lo, hi);
    return *reinterpret_cast<uint32_t*>(&t);
}
__device__ __forceinline__ void split_bf16(float v, __nv_bfloat16& hi, float& lo) {
    hi = __float2bfloat16(v);
    lo = v - __bfloat162float(hi);
}

__global__ __launch_bounds__(512, 1)
void span_mma_kernel(
    const float* __restrict__ emb,
    const int*   __restrict__ span_lengths,
    const int*   __restrict__ num_spans,
    const float* __restrict__ in_proj_w, const float* __restrict__ in_proj_b,
    const float* __restrict__ out_proj_w, const float* __restrict__ out_proj_b,
    const float* __restrict__ ln1_g, const float* __restrict__ ln1_b,
    const float* __restrict__ lin1_w, const float* __restrict__ lin1_b,
    const float* __restrict__ lin2_w, const float* __restrict__ lin2_b,
    const float* __restrict__ ln2_g, const float* __restrict__ ln2_b,
    const float* __restrict__ pad_token,
    float* __restrict__ outp)
{
    extern __shared__ char smc[];
    float* smf = reinterpret_cast<float*>(smc);
    const int tid = threadIdx.x, warp = tid >> 5, lane = tid & 31;

    // zero all bf16 tile regions (pads must be 0)
    {
        int4 z = make_int4(0, 0, 0, 0);
        int4* d = reinterpret_cast<int4*>(smc + XH_B);
        for (int i = tid; i < (SCR_B - XH_B) / 16; i += 512) d[i] = z;
    }
    for (int i = tid; i < 84;  i += 512) smf[F_BQKV + i] = in_proj_b[i];
    for (int i = tid; i < 784; i += 512) smf[F_WO + i]   = out_proj_w[i];
    if (tid < 256) smf[F_B1 + tid] = lin1_b[tid];
    if (tid < 32) {
        smf[F_B2 + tid]  = (tid < 28) ? lin2_b[tid] : 0.0f;
        smf[F_G2 + tid]  = (tid < 28) ? ln2_g[tid]  : 0.0f;
        smf[F_B2L + tid] = (tid < 28) ? ln2_b[tid]  : 0.0f;
    }
    if (tid < 28) {
        smf[F_BO + tid]  = out_proj_b[tid];
        smf[F_G1 + tid]  = ln1_g[tid];
        smf[F_B1L + tid] = ln1_b[tid];
        smf[F_PAD + tid] = pad_token[tid];
    }
    __syncthreads();
    for (int i = tid; i < 7168; i += 512) {        // W1 [256 f][28 e] -> stride 36
        int f = i / 28, e = i % 28;
        __nv_bfloat16 hh; float lf; split_bf16(lin1_w[i], hh, lf);
        *reinterpret_cast<__nv_bfloat16*>(smc + W1H_B + (f * 36 + e) * 2) = hh;
        *reinterpret_cast<__nv_bfloat16*>(smc + W1L_B + (f * 36 + e) * 2) = __float2bfloat16(lf);
    }
    for (int i = tid; i < 2352; i += 512) {        // Wqkv [84 r][28 e] -> stride 36
        int r = i / 28, e = i % 28;
        __nv_bfloat16 hh; float lf; split_bf16(in_proj_w[i], hh, lf);
        *reinterpret_cast<__nv_bfloat16*>(smc + WQH_B + (r * 36 + e) * 2) = hh;
        *reinterpret_cast<__nv_bfloat16*>(smc + WQL_B + (r * 36 + e) * 2) = __float2bfloat16(lf);
    }
    for (int i = tid; i < 7168; i += 512) {        // W2 [28 e][256 f] -> stride 264
        int e = i / 256, f = i % 256;
        __nv_bfloat16 hh; float lf; split_bf16(lin2_w[i], hh, lf);
        *reinterpret_cast<__nv_bfloat16*>(smc + W2H_B + (e * 264 + f) * 2) = hh;
        *reinterpret_cast<__nv_bfloat16*>(smc + W2L_B + (e * 264 + f) * 2) = __float2bfloat16(lf);
    }
    __syncthreads();

    uint32_t* XHw  = reinterpret_cast<uint32_t*>(smc + XH_B);
    uint32_t* XLw  = reinterpret_cast<uint32_t*>(smc + XL_B);
    const uint32_t* W1Hw = reinterpret_cast<const uint32_t*>(smc + W1H_B);
    const uint32_t* W1Lw = reinterpret_cast<const uint32_t*>(smc + W1L_B);
    const uint32_t* W2Hw = reinterpret_cast<const uint32_t*>(smc + W2H_B);
    const uint32_t* W2Lw = reinterpret_cast<const uint32_t*>(smc + W2L_B);
    const uint32_t* WQHw = reinterpret_cast<const uint32_t*>(smc + WQH_B);
    const uint32_t* WQLw = reinterpret_cast<const uint32_t*>(smc + WQL_B);
    int* lens = reinterpret_cast<int*>(smf + I_LEN);
    int* vld  = reinterpret_cast<int*>(smf + I_VAL);

    const int l = lane & 7, h = lane >> 3, e0h = h * 7;
    const int gq = lane >> 2, tq = lane & 3;
    const int m0 = warp * 16;
    float* QW = smf + SCRF + warp * 1600;   // [16 tok][100]: Q@0, K@32, V@64 (+h*8+d)

    for (int g = blockIdx.x; g < NG; g += gridDim.x) {
        // ---- (a) emb -> XE bf16 hi/lo tiles (warp-private 16 tokens = 448 floats) ----
        {
            const float2* esrc = reinterpret_cast<const float2*>(emb + (g * 32 + warp * 2) * 224);
#pragma unroll
            for (int k2 = 0; k2 < 7; k2++) {
                const int idx2 = lane + k2 * 32;
                float2 v = esrc[idx2];
                const int fi = idx2 * 2;
                const int tok = fi / 28, e = fi % 28;
                __nv_bfloat16 h0, h1; float l0, l1;
                split_bf16(v.x, h0, l0);
                split_bf16(v.y, h1, l1);
                const int word = (m0 + tok) * 18 + e / 2;
                XHw[word] = pack_bf2(h0, h1);
                XLw[word] = pack_bf2(__float2bfloat16(l0), __float2bfloat16(l1));
            }
        }
        __syncwarp();

        // ---- (b) GEMM_QKV: [16 x 32] x Wqkv^T[88 x 32] via mma.sync ----
        {
            uint32_t ah[2][4], al[2][4];
#pragma unroll
            for (int kt = 0; kt < 2; kt++) {
                const int w0 = (m0 + gq) * 18 + kt * 8 + tq;
                ah[kt][0] = XHw[w0];       ah[kt][1] = XHw[w0 + 144];
                ah[kt][2] = XHw[w0 + 4];   ah[kt][3] = XHw[w0 + 148];
                al[kt][0] = XLw[w0];       al[kt][1] = XLw[w0 + 144];
                al[kt][2] = XLw[w0 + 4];   al[kt][3] = XLw[w0 + 148];
            }
#pragma unroll
            for (int nq = 0; nq < 11; nq++) {
                float d[4] = {0.0f, 0.0f, 0.0f, 0.0f};
#pragma unroll
                for (int kt = 0; kt < 2; kt++) {
                    const int w = (nq * 8 + gq) * 18 + kt * 8 + tq;
                    const uint32_t b0h = WQHw[w], b1h = WQHw[w + 4];
                    const uint32_t b0l = WQLw[w], b1l = WQLw[w + 4];
                    mma_bf16(d, ah[kt][0], ah[kt][1], ah[kt][2], ah[kt][3], b0h, b1h);
                    mma_bf16(d, al[kt][0], al[kt][1], al[kt][2], al[kt][3], b0h, b1h);
                    mma_bf16(d, ah[kt][0], ah[kt][1], ah[kt][2], ah[kt][3], b0l, b1l);
                }
                const int c0 = nq * 8 + 2 * tq;
                if (c0 < 84) {
                    const int qk = c0 / 28, r = c0 % 28;
                    const int off = qk * 32 + (r / 7) * 8 + (r % 7);
                    const float bz = smf[F_BQKV + c0];
                    QW[gq * 100 + off]       = d[0] + bz;
                    QW[(gq + 8) * 100 + off] = d[2] + bz;
                }
                const int c1 = c0 + 1;
                if (c1 < 84) {
                    const int qk = c1 / 28, r = c1 % 28;
                    const int off = qk * 32 + (r / 7) * 8 + (r % 7);
                    const float bz = smf[F_BQKV + c1];
                    QW[gq * 100 + off]       = d[1] + bz;
                    QW[(gq + 8) * 100 + off] = d[3] + bz;
                }
            }
        }
        __syncwarp();

        // ---- (c) per-span attention + out-proj + LN1 (scalar) ----
        for (int j = 0; j < 2; j++) {
            const int sl = warp * 2 + j;
            const int span = g * 32 + sl;
            const int b = span >> 9, t = span & (T_ - 1);
            const int tok = j * 8 + l;
            const int len = span_lengths[span];

            float q[7];
            {
                const float4 qa = *reinterpret_cast<const float4*>(QW + tok * 100 + h * 8);
                const float4 qb = *reinterpret_cast<const float4*>(QW + tok * 100 + h * 8 + 4);
                q[0] = qa.x; q[1] = qa.y; q[2] = qa.z; q[3] = qa.w;
                q[4] = qb.x; q[5] = qb.y; q[6] = qb.z;
            }
            float s[8];
#pragma unroll
            for (int kk = 0; kk < 8; kk++) {
                const float4 ka = *reinterpret_cast<const float4*>(QW + (j * 8 + kk) * 100 + 32 + h * 8);
                const float4 kb = *reinterpret_cast<const float4*>(QW + (j * 8 + kk) * 100 + 32 + h * 8 + 4);
                float acc = q[0] * ka.x + q[1] * ka.y + q[2] * ka.z + q[3] * ka.w
                          + q[4] * kb.x + q[5] * kb.y + q[6] * kb.z;
                s[kk] = (kk < len) ? acc * 0.3779644730092272f : -1e9f;
            }
            float mx = s[0];
#pragma unroll
            for (int kk = 1; kk < 8; kk++) mx = fmaxf(mx, s[kk]);
            float p[8], ps = 0.0f;
#pragma unroll
            for (int kk = 0; kk < 8; kk++) { p[kk] = __expf(s[kk] - mx); ps += p[kk]; }
            const float pinv = 1.0f / ps;
            float ao[7];
#pragma unroll
            for (int d = 0; d < 7; d++) ao[d] = 0.0f;
#pragma unroll
            for (int kk = 0; kk < 8; kk++) {
                const float4 va = *reinterpret_cast<const float4*>(QW + (j * 8 + kk) * 100 + 64 + h * 8);
                const float4 vb = *reinterpret_cast<const float4*>(QW + (j * 8 + kk) * 100 + 64 + h * 8 + 4);
                ao[0] = fmaf(p[kk], va.x, ao[0]); ao[1] = fmaf(p[kk], va.y, ao[1]);
                ao[2] = fmaf(p[kk], va.z, ao[2]); ao[3] = fmaf(p[kk], va.w, ao[3]);
                ao[4] = fmaf(p[kk], vb.x, ao[4]); ao[5] = fmaf(p[kk], vb.y, ao[5]);
                ao[6] = fmaf(p[kk], vb.z, ao[6]);
            }
#pragma unroll
            for (int d = 0; d < 7; d++) QW[tok * 100 + h * 8 + d] = ao[d] * pinv;  // overwrite own Q slice
            __syncwarp();   // cross-thread ao reads below

            float ar[32];
#pragma unroll
            for (int hh = 0; hh < 4; hh++) {
                const float4 a = *reinterpret_cast<const float4*>(QW + tok * 100 + hh * 8);
                const float4 b2 = *reinterpret_cast<const float4*>(QW + tok * 100 + hh * 8 + 4);
                ar[hh * 8 + 0] = a.x;  ar[hh * 8 + 1] = a.y;  ar[hh * 8 + 2] = a.z;  ar[hh * 8 + 3] = a.w;
                ar[hh * 8 + 4] = b2.x; ar[hh * 8 + 5] = b2.y; ar[hh * 8 + 6] = b2.z; ar[hh * 8 + 7] = 0.0f;
            }
            const float* erow = emb + span * 224 + l * 28;
            float y[7];
#pragma unroll
            for (int d = 0; d < 7; d++) {
                const int ep = e0h + d;
                const float4* w4 = reinterpret_cast<const float4*>(smf + F_WO + ep * 28);
                float wr[28];
#pragma unroll
                for (int j2 = 0; j2 < 7; j2++) {
                    float4 w = w4[j2];
                    wr[4 * j2] = w.x; wr[4 * j2 + 1] = w.y; wr[4 * j2 + 2] = w.z; wr[4 * j2 + 3] = w.w;
                }
                float o = 0.0f;
#pragma unroll
                for (int hh = 0; hh < 4; hh++)
#pragma unroll
                    for (int dd = 0; dd < 7; dd++)
                        o = fmaf(ar[hh * 8 + dd], wr[hh * 7 + dd], o);
                y[d] = erow[ep] + smf[F_BO + ep] + o;
            }
            float s1 = 0.0f;
#pragma unroll
            for (int d = 0; d < 7; d++) s1 += y[d];
            s1 += __shfl_xor_sync(0xffffffffu, s1, 8);
            s1 += __shfl_xor_sync(0xffffffffu, s1, 16);
            const float mu1 = s1 * (1.0f / 28.0f);
            float s2 = 0.0f;
#pragma unroll
            for (int d = 0; d < 7; d++) { float dd = y[d] - mu1; s2 += dd * dd; }
            s2 += __shfl_xor_sync(0xffffffffu, s2, 8);
            s2 += __shfl_xor_sync(0xffffffffu, s2, 16);
            const float rs1 = rsqrtf(s2 * (1.0f / 28.0f) + 1e-5f);
            const int row = m0 + tok;
#pragma unroll
            for (int d = 0; d < 7; d++) {
                const int ep = e0h + d;
                float v = (y[d] - mu1) * rs1 * smf[F_G1 + ep] + smf[F_B1L + ep];
                __nv_bfloat16 hh; float lf; split_bf16(v, hh, lf);
                *reinterpret_cast<__nv_bfloat16*>(smc + XH_B + (row * 36 + ep) * 2) = hh;
                *reinterpret_cast<__nv_bfloat16*>(smc + XL_B + (row * 36 + ep) * 2) = __float2bfloat16(lf);
            }
            if (lane == 0) { lens[sl] = len; vld[sl] = (t < num_spans[b]) ? 1 : 0; }
            __syncwarp();
        }
        __syncwarp();

        // ---------------- PHASE 2: FFN via mma.sync (16 tokens per warp) ----------------
        uint32_t ah[2][4], al[2][4];
#pragma unroll
        for (int kt = 0; kt < 2; kt++) {
            const int w0 = (m0 + gq) * 18 + kt * 8 + tq;
            ah[kt][0] = XHw[w0];       ah[kt][1] = XHw[w0 + 144];
            ah[kt][2] = XHw[w0 + 4];   ah[kt][3] = XHw[w0 + 148];
            al[kt][0] = XLw[w0];       al[kt][1] = XLw[w0 + 144];
            al[kt][2] = XLw[w0 + 4];   al[kt][3] = XLw[w0 + 148];
        }

        float d2[4][4];
#pragma unroll
        for (int nt = 0; nt < 4; nt++)
#pragma unroll
            for (int r = 0; r < 4; r++) d2[nt][r] = 0.0f;

        for (int fc = 0; fc < 16; fc++) {
            float d1[2][4];
#pragma unroll
            for (int nt = 0; nt < 2; nt++)
#pragma unroll
                for (int r = 0; r < 4; r++) d1[nt][r] = 0.0f;
#pragma unroll
            for (int kt = 0; kt < 2; kt++)
#pragma unroll
                for (int nt = 0; nt < 2; nt++) {
                    const int w = (fc * 16 + nt * 8 + gq) * 18 + kt * 8 + tq;
                    const uint32_t b0h = W1Hw[w], b1h = W1Hw[w + 4];
                    const uint32_t b0l = W1Lw[w], b1l = W1Lw[w + 4];
                    mma_bf16(d1[nt], ah[kt][0], ah[kt][1], ah[kt][2], ah[kt][3], b0h, b1h);
                    mma_bf16(d1[nt], al[kt][0], al[kt][1], al[kt][2], al[kt][3], b0h, b1h);
                    mma_bf16(d1[nt], ah[kt][0], ah[kt][1], ah[kt][2], ah[kt][3], b0l, b1l);
                }
            uint32_t a2h[4], a2l[4];
#pragma unroll
            for (int nt = 0; nt < 2; nt++) {
                const int fe = fc * 16 + nt * 8 + 2 * tq;
                const float bz0 = smf[F_B1 + fe], bz1 = smf[F_B1 + fe + 1];
                float h0 = fmaxf(d1[nt][0] + bz0, 0.0f);
                float h1 = fmaxf(d1[nt][1] + bz1, 0.0f);
                float h2 = fmaxf(d1[nt][2] + bz0, 0.0f);
                float h3 = fmaxf(d1[nt][3] + bz1, 0.0f);
                __nv_bfloat16 q0, q1, q2, q3; float l0, l1, l2, l3;
                split_bf16(h0, q0, l0); split_bf16(h1, q1, l1);
                split_bf16(h2, q2, l2); split_bf16(h3, q3, l3);
                a2h[nt * 2 + 0] = pack_bf2(q0, q1);
                a2h[nt * 2 + 1] = pack_bf2(q2, q3);
                a2l[nt * 2 + 0] = pack_bf2(__float2bfloat16(l0), __float2bfloat16(l1));
                a2l[nt * 2 + 1] = pack_bf2(__float2bfloat16(l2), __float2bfloat16(l3));
            }
#pragma unroll
            for (int nt2 = 0; nt2 < 4; nt2++) {
                const int w2 = (nt2 * 8 + gq) * 132 + fc * 8 + tq;
                const uint32_t b0h = W2Hw[w2], b1h = W2Hw[w2 + 4];
                const uint32_t b0l = W2Lw[w2], b1l = W2Lw[w2 + 4];
                mma_bf16(d2[nt2], a2h[0], a2h[1], a2h[2], a2h[3], b0h, b1h);
                mma_bf16(d2[nt2], a2l[0], a2l[1], a2l[2], a2l[3], b0h, b1h);
                mma_bf16(d2[nt2], a2h[0], a2h[1], a2h[2], a2h[3], b0l, b1l);
            }
        }

        // ---------------- EPILOGUE: one span at a time ----------------
#pragma unroll
        for (int sp2 = 0; sp2 < 2; sp2++) {
            const int tok = m0 + gq + sp2 * 8;
            const int sl = warp * 2 + sp2;
            const int c0 = sp2 * 2;
            float v[8];
            float ssum = 0.0f, sq = 0.0f;
#pragma unroll
            for (int nt = 0; nt < 4; nt++) {
                const int e0 = nt * 8 + 2 * tq;
                const bool ok = (nt < 3) || (tq < 2);
                const uint32_t uh = XHw[tok * 18 + nt * 4 + tq];
                const uint32_t ul = XLw[tok * 18 + nt * 4 + tq];
                const __nv_bfloat162 bh = *reinterpret_cast<const __nv_bfloat162*>(&uh);
                const __nv_bfloat162 bl = *reinterpret_cast<const __nv_bfloat162*>(&ul);
                const float xn0 = __bfloat162float(bh.x) + __bfloat162float(bl.x);
                const float xn1 = __bfloat162float(bh.y) + __bfloat162float(bl.y);
                float a0 = ok ? (d2[nt][c0]     + smf[F_B2 + e0]     + xn0) : 0.0f;
                float a1 = ok ? (d2[nt][c0 + 1] + smf[F_B2 + e0 + 1] + xn1) : 0.0f;
                v[nt * 2] = a0; v[nt * 2 + 1] = a1;
                ssum += a0 + a1; sq += a0 * a0 + a1 * a1;
            }
            ssum += __shfl_xor_sync(0xffffffffu, ssum, 1); sq += __shfl_xor_sync(0xffffffffu, sq, 1);
            ssum += __shfl_xor_sync(0xffffffffu, ssum, 2); sq += __shfl_xor_sync(0xffffffffu, sq, 2);
            const float mu = ssum * (1.0f / 28.0f);
            const float rs = rsqrtf(fmaxf(sq * (1.0f / 28.0f) - mu * mu, 0.0f) + 1e-5f);
            const int len = lens[sl];
            const float m = (gq < len) ? 1.0f : 0.0f;
            float pz[8];
#pragma unroll
            for (int nt = 0; nt < 4; nt++) {
                const int e0 = nt * 8 + 2 * tq;
                const bool ok = (nt < 3) || (tq < 2);
                pz[nt * 2]     = ok ? ((v[nt * 2]     - mu) * rs * smf[F_G2 + e0]     + smf[F_B2L + e0])     * m : 0.0f;
                pz[nt * 2 + 1] = ok ? ((v[nt * 2 + 1] - mu) * rs * smf[F_G2 + e0 + 1] + smf[F_B2L + e0 + 1]) * m : 0.0f;
            }
#pragma unroll
            for (int i = 0; i < 8; i++) {
                float a = pz[i];
                a += __shfl_xor_sync(0xffffffffu, a, 4);
                a += __shfl_xor_sync(0xffffffffu, a, 8);
                a += __shfl_xor_sync(0xffffffffu, a, 16);
                pz[i] = a;
            }
            if (lane < 4) {
                const float il = 1.0f / (float)len;
                const int sp = g * 32 + sl;
                const int okv = vld[sl];
#pragma unroll
                for (int nt = 0; nt < 4; nt++) {
                    const int e0 = nt * 8 + 2 * tq;
                    if ((nt < 3) || (tq < 2)) {
                        outp[sp * 28 + e0]     = okv ? pz[nt * 2] * il     : smf[F_PAD + e0];
                        outp[sp * 28 + e0 + 1] = okv ? pz[nt * 2 + 1] * il : smf[F_PAD + e0 + 1];
                    }
                }
            }
        }
        __syncwarp();
    }
}

extern "C" void kernel_launch(void* const* d_in, const int* in_sizes, int n_in,
                              void* d_out, int out_size) {
    const float* emb          = (const float*)d_in[0];
    const int*   span_lengths = (const int*)  d_in[1];
    const int*   num_spans    = (const int*)  d_in[2];
    const float* in_proj_w    = (const float*)d_in[3];
    const float* in_proj_b    = (const float*)d_in[4];
    const float* out_proj_w   = (const float*)d_in[5];
    const float* out_proj_b   = (const float*)d_in[6];
    const float* ln1_g        = (const float*)d_in[7];
    const float* ln1_b        = (const float*)d_in[8];
    const float* lin1_w       = (const float*)d_in[9];
    const float* lin1_b       = (const float*)d_in[10];
    const float* lin2_w       = (const float*)d_in[11];
    const float* lin2_b       = (const float*)d_in[12];
    const float* ln2_g        = (const float*)d_in[13];
    const float* ln2_b        = (const float*)d_in[14];
    const float* pad_token    = (const float*)d_in[15];
    float* outp = (float*)d_out;

    cudaFuncSetAttribute(span_mma_kernel,
                         cudaFuncAttributeMaxDynamicSharedMemorySize, SMEM_END_B);

    span_mma_kernel<<<148, 512, SMEM_END_B>>>(
        emb, span_lengths, num_spans,
        in_proj_w, in_proj_b, out_proj_w, out_proj_b,
        ln1_g, ln1_b, lin1_w, lin1_b, lin2_w, lin2_b,
        ln2_g, ln2_b, pad_token, outp);
}

// round 13
// speedup vs baseline: 2.6593x; 1.1059x over previous
#include <cuda_runtime.h>
#include <cuda_bf16.h>
#include <cstdint>

#define T_ 512
#define NG 1024            // groups of 32 spans (256 tokens per block-group)

// ---------------- smem layout ----------------
// float indices
#define F_BQKV 0          // 84
#define F_BO   84
#define F_G1   112
#define F_B1L  140
#define F_B1   168        // 256
#define F_B2   424        // 32 (pad zero)
#define F_G2   456
#define F_B2L  488
#define F_PAD  520
#define I_LEN  548        // int[32]
#define I_VAL  580        // int[32]
// byte offsets (16B aligned)
#define XH_B   2560       // X hi  [256 tok][36 halves]  (emb-split, then xn-split)
#define XL_B   20992
#define W1H_B  39424      // W1 hi [256 f][36 halves]
#define W1L_B  57856
#define W2H_B  76288      // W2 hi [32 e][264 halves]
#define W2L_B  93184
#define WQH_B  110080     // Wqkv hi [88 r][36 halves]
#define WQL_B  116416
#define WOH_B  122752     // Wout hi [32 r][36 halves]
#define WOL_B  125056
#define SCR_B  127360     // 16 warps x 1600 floats (QKV scratch [16 tok][100])
#define SCRF   31840
#define SMEM_END_B 229760

__device__ __forceinline__ void mma_bf16(float* d, uint32_t a0, uint32_t a1,
                                         uint32_t a2, uint32_t a3,
                                         uint32_t b0, uint32_t b1) {
    asm volatile(
        "mma.sync.aligned.m16n8k16.row.col.f32.bf16.bf16.f32 "
        "{%0,%1,%2,%3}, {%4,%5,%6,%7}, {%8,%9}, {%0,%1,%2,%3};"
        : "+f"(d[0]), "+f"(d[1]), "+f"(d[2]), "+f"(d[3])
        : "r"(a0), "r"(a1), "r"(a2), "r"(a3), "r"(b0), "r"(b1));
}
__device__ __forceinline__ uint32_t pack_bf2(__nv_bfloat16 lo, __nv_bfloat16 hi) {
    __nv_bfloat162 t(lo, hi);
    return *reinterpret_cast<uint32_t*>(&t);
}
__device__ __forceinline__ void split_bf16(float v, __nv_bfloat16& hi, float& lo) {
    hi = __float2bfloat16(v);
    lo = v - __bfloat162float(hi);
}

__global__ __launch_bounds__(512, 1)
void span_mma_kernel(
    const float* __restrict__ emb,
    const int*   __restrict__ span_lengths,
    const int*   __restrict__ num_spans,
    const float* __restrict__ in_proj_w, const float* __restrict__ in_proj_b,
    const float* __restrict__ out_proj_w, const float* __restrict__ out_proj_b,
    const float* __restrict__ ln1_g, const float* __restrict__ ln1_b,
    const float* __restrict__ lin1_w, const float* __restrict__ lin1_b,
    const float* __restrict__ lin2_w, const float* __restrict__ lin2_b,
    const float* __restrict__ ln2_g, const float* __restrict__ ln2_b,
    const float* __restrict__ pad_token,
    float* __restrict__ outp)
{
    extern __shared__ char smc[];
    float* smf = reinterpret_cast<float*>(smc);
    const int tid = threadIdx.x, warp = tid >> 5, lane = tid & 31;

    // zero all bf16 tile regions (pads must be 0)
    {
        int4 z = make_int4(0, 0, 0, 0);
        int4* d = reinterpret_cast<int4*>(smc + XH_B);
        for (int i = tid; i < (SCR_B - XH_B) / 16; i += 512) d[i] = z;
    }
    for (int i = tid; i < 84; i += 512) smf[F_BQKV + i] = in_proj_b[i];
    if (tid < 256) smf[F_B1 + tid] = lin1_b[tid];
    if (tid < 32) {
        smf[F_B2 + tid]  = (tid < 28) ? lin2_b[tid] : 0.0f;
        smf[F_G2 + tid]  = (tid < 28) ? ln2_g[tid]  : 0.0f;
        smf[F_B2L + tid] = (tid < 28) ? ln2_b[tid]  : 0.0f;
    }
    if (tid < 28) {
        smf[F_BO + tid]  = out_proj_b[tid];
        smf[F_G1 + tid]  = ln1_g[tid];
        smf[F_B1L + tid] = ln1_b[tid];
        smf[F_PAD + tid] = pad_token[tid];
    }
    __syncthreads();
    for (int i = tid; i < 7168; i += 512) {        // W1 [256 f][28 e] -> stride 36
        int f = i / 28, e = i % 28;
        __nv_bfloat16 hh; float lf; split_bf16(lin1_w[i], hh, lf);
        *reinterpret_cast<__nv_bfloat16*>(smc + W1H_B + (f * 36 + e) * 2) = hh;
        *reinterpret_cast<__nv_bfloat16*>(smc + W1L_B + (f * 36 + e) * 2) = __float2bfloat16(lf);
    }
    for (int i = tid; i < 2352; i += 512) {        // Wqkv [84 r][28 e] -> stride 36
        int r = i / 28, e = i % 28;
        __nv_bfloat16 hh; float lf; split_bf16(in_proj_w[i], hh, lf);
        *reinterpret_cast<__nv_bfloat16*>(smc + WQH_B + (r * 36 + e) * 2) = hh;
        *reinterpret_cast<__nv_bfloat16*>(smc + WQL_B + (r * 36 + e) * 2) = __float2bfloat16(lf);
    }
    for (int i = tid; i < 784; i += 512) {         // Wout [28 r][28 e] -> stride 36
        int r = i / 28, e = i % 28;
        __nv_bfloat16 hh; float lf; split_bf16(out_proj_w[i], hh, lf);
        *reinterpret_cast<__nv_bfloat16*>(smc + WOH_B + (r * 36 + e) * 2) = hh;
        *reinterpret_cast<__nv_bfloat16*>(smc + WOL_B + (r * 36 + e) * 2) = __float2bfloat16(lf);
    }
    for (int i = tid; i < 7168; i += 512) {        // W2 [28 e][256 f] -> stride 264
        int e = i / 256, f = i % 256;
        __nv_bfloat16 hh; float lf; split_bf16(lin2_w[i], hh, lf);
        *reinterpret_cast<__nv_bfloat16*>(smc + W2H_B + (e * 264 + f) * 2) = hh;
        *reinterpret_cast<__nv_bfloat16*>(smc + W2L_B + (e * 264 + f) * 2) = __float2bfloat16(lf);
    }
    __syncthreads();

    uint32_t* XHw  = reinterpret_cast<uint32_t*>(smc + XH_B);
    uint32_t* XLw  = reinterpret_cast<uint32_t*>(smc + XL_B);
    const uint32_t* W1Hw = reinterpret_cast<const uint32_t*>(smc + W1H_B);
    const uint32_t* W1Lw = reinterpret_cast<const uint32_t*>(smc + W1L_B);
    const uint32_t* W2Hw = reinterpret_cast<const uint32_t*>(smc + W2H_B);
    const uint32_t* W2Lw = reinterpret_cast<const uint32_t*>(smc + W2L_B);
    const uint32_t* WQHw = reinterpret_cast<const uint32_t*>(smc + WQH_B);
    const uint32_t* WQLw = reinterpret_cast<const uint32_t*>(smc + WQL_B);
    const uint32_t* WOHw = reinterpret_cast<const uint32_t*>(smc + WOH_B);
    const uint32_t* WOLw = reinterpret_cast<const uint32_t*>(smc + WOL_B);
    int* lens = reinterpret_cast<int*>(smf + I_LEN);
    int* vld  = reinterpret_cast<int*>(smf + I_VAL);

    const int l = lane & 7, h = lane >> 3, e0h = h * 7;
    const int gq = lane >> 2, tq = lane & 3;
    const int m0 = warp * 16;
    float* QW = smf + SCRF + warp * 1600;                 // [16 tok][100]: Q@0 K@32 V@64
    uint32_t* QWu = reinterpret_cast<uint32_t*>(QW);
    char* aobase = smc + SCR_B + warp * 6400;             // AO split lives in K slot

    for (int g = blockIdx.x; g < NG; g += gridDim.x) {
        // ---- (a) emb -> X bf16 hi/lo tiles (warp-private 16 tokens) ----
        {
            const float2* esrc = reinterpret_cast<const float2*>(emb + (g * 32 + warp * 2) * 224);
#pragma unroll
            for (int k2 = 0; k2 < 7; k2++) {
                const int idx2 = lane + k2 * 32;
                float2 v = esrc[idx2];
                const int fi = idx2 * 2;
                const int tok = fi / 28, e = fi % 28;
                __nv_bfloat16 h0, h1; float l0, l1;
                split_bf16(v.x, h0, l0);
                split_bf16(v.y, h1, l1);
                const int word = (m0 + tok) * 18 + e / 2;
                XHw[word] = pack_bf2(h0, h1);
                XLw[word] = pack_bf2(__float2bfloat16(l0), __float2bfloat16(l1));
            }
        }
        __syncwarp();

        // ---- (b) GEMM_QKV: [16 x 32] x Wqkv^T[88 x 32] ----
        {
            uint32_t ah[2][4], al[2][4];
#pragma unroll
            for (int kt = 0; kt < 2; kt++) {
                const int w0 = (m0 + gq) * 18 + kt * 8 + tq;
                ah[kt][0] = XHw[w0];       ah[kt][1] = XHw[w0 + 144];
                ah[kt][2] = XHw[w0 + 4];   ah[kt][3] = XHw[w0 + 148];
                al[kt][0] = XLw[w0];       al[kt][1] = XLw[w0 + 144];
                al[kt][2] = XLw[w0 + 4];   al[kt][3] = XLw[w0 + 148];
            }
#pragma unroll
            for (int nq = 0; nq < 11; nq++) {
                float d[4] = {0.0f, 0.0f, 0.0f, 0.0f};
#pragma unroll
                for (int kt = 0; kt < 2; kt++) {
                    const int w = (nq * 8 + gq) * 18 + kt * 8 + tq;
                    const uint32_t b0h = WQHw[w], b1h = WQHw[w + 4];
                    const uint32_t b0l = WQLw[w], b1l = WQLw[w + 4];
                    mma_bf16(d, ah[kt][0], ah[kt][1], ah[kt][2], ah[kt][3], b0h, b1h);
                    mma_bf16(d, al[kt][0], al[kt][1], al[kt][2], al[kt][3], b0h, b1h);
                    mma_bf16(d, ah[kt][0], ah[kt][1], ah[kt][2], ah[kt][3], b0l, b1l);
                }
                const int c0 = nq * 8 + 2 * tq;
                if (c0 < 84) {
                    const int qk = c0 / 28, r = c0 % 28;
                    const int off = qk * 32 + (r / 7) * 8 + (r % 7);
                    const float bz = smf[F_BQKV + c0];
                    QW[gq * 100 + off]       = d[0] + bz;
                    QW[(gq + 8) * 100 + off] = d[2] + bz;
                }
                const int c1 = c0 + 1;
                if (c1 < 84) {
                    const int qk = c1 / 28, r = c1 % 28;
                    const int off = qk * 32 + (r / 7) * 8 + (r % 7);
                    const float bz = smf[F_BQKV + c1];
                    QW[gq * 100 + off]       = d[1] + bz;
                    QW[(gq + 8) * 100 + off] = d[3] + bz;
                }
            }
        }
        __syncwarp();

        // ---- (c) attention per span; ao -> bf16 split into K slot ----
        for (int j = 0; j < 2; j++) {
            const int sl = warp * 2 + j;
            const int span = g * 32 + sl;
            const int b = span >> 9, t = span & (T_ - 1);
            const int tok = j * 8 + l;
            const int len = span_lengths[span];

            float q[7];
            {
                const float4 qa = *reinterpret_cast<const float4*>(QW + tok * 100 + h * 8);
                const float4 qb = *reinterpret_cast<const float4*>(QW + tok * 100 + h * 8 + 4);
                q[0] = qa.x; q[1] = qa.y; q[2] = qa.z; q[3] = qa.w;
                q[4] = qb.x; q[5] = qb.y; q[6] = qb.z;
            }
            float s[8];
#pragma unroll
            for (int kk = 0; kk < 8; kk++) {
                const float4 ka = *reinterpret_cast<const float4*>(QW + (j * 8 + kk) * 100 + 32 + h * 8);
                const float4 kb = *reinterpret_cast<const float4*>(QW + (j * 8 + kk) * 100 + 32 + h * 8 + 4);
                float acc = q[0] * ka.x + q[1] * ka.y + q[2] * ka.z + q[3] * ka.w
                          + q[4] * kb.x + q[5] * kb.y + q[6] * kb.z;
                s[kk] = (kk < len) ? acc * 0.3779644730092272f : -1e9f;
            }
            __syncwarp();   // all K reads done before K slot is reused for AO
            float mx = s[0];
#pragma unroll
            for (int kk = 1; kk < 8; kk++) mx = fmaxf(mx, s[kk]);
            float p[8], ps = 0.0f;
#pragma unroll
            for (int kk = 0; kk < 8; kk++) { p[kk] = __expf(s[kk] - mx); ps += p[kk]; }
            const float pinv = 1.0f / ps;
            float ao[7];
#pragma unroll
            for (int d = 0; d < 7; d++) ao[d] = 0.0f;
#pragma unroll
            for (int kk = 0; kk < 8; kk++) {
                const float4 va = *reinterpret_cast<const float4*>(QW + (j * 8 + kk) * 100 + 64 + h * 8);
                const float4 vb = *reinterpret_cast<const float4*>(QW + (j * 8 + kk) * 100 + 64 + h * 8 + 4);
                ao[0] = fmaf(p[kk], va.x, ao[0]); ao[1] = fmaf(p[kk], va.y, ao[1]);
                ao[2] = fmaf(p[kk], va.z, ao[2]); ao[3] = fmaf(p[kk], va.w, ao[3]);
                ao[4] = fmaf(p[kk], vb.x, ao[4]); ao[5] = fmaf(p[kk], vb.y, ao[5]);
                ao[6] = fmaf(p[kk], vb.z, ao[6]);
            }
            // AO split store: AOH halves at bytes tok*400+128+e*2, AOL at +192+e*2
#pragma unroll
            for (int d = 0; d < 7; d++) {
                const int e = e0h + d;
                __nv_bfloat16 hh; float lf; split_bf16(ao[d] * pinv, hh, lf);
                *reinterpret_cast<__nv_bfloat16*>(aobase + tok * 400 + 128 + e * 2) = hh;
                *reinterpret_cast<__nv_bfloat16*>(aobase + tok * 400 + 192 + e * 2) = __float2bfloat16(lf);
            }
            if (lane == 0) { lens[sl] = len; vld[sl] = (t < num_spans[b]) ? 1 : 0; }
            __syncwarp();
        }
        // zero AO pad cols 28-31 (stale K data): floats 46,47 (AOH) / 62,63 (AOL)
        QW[(lane >> 1) * 100 + 46 + (lane & 1)] = 0.0f;
        QW[(lane >> 1) * 100 + 62 + (lane & 1)] = 0.0f;
        __syncwarp();

        // ---- (d) GEMM_O: [16 x 32] x Wout^T[32 x 32]; +bias +residual +LN1 -> xn ----
        {
            uint32_t aoh[2][4], aol[2][4];
#pragma unroll
            for (int kt = 0; kt < 2; kt++) {
                const int w0 = gq * 100 + 32 + kt * 8 + tq;
                aoh[kt][0] = QWu[w0];        aoh[kt][1] = QWu[w0 + 800];
                aoh[kt][2] = QWu[w0 + 4];    aoh[kt][3] = QWu[w0 + 804];
                aol[kt][0] = QWu[w0 + 16];   aol[kt][1] = QWu[w0 + 816];
                aol[kt][2] = QWu[w0 + 20];   aol[kt][3] = QWu[w0 + 820];
            }
            float dy[4][4];
#pragma unroll
            for (int nt = 0; nt < 4; nt++)
#pragma unroll
                for (int r = 0; r < 4; r++) dy[nt][r] = 0.0f;
#pragma unroll
            for (int kt = 0; kt < 2; kt++)
#pragma unroll
                for (int nt = 0; nt < 4; nt++) {
                    const int w = (nt * 8 + gq) * 18 + kt * 8 + tq;
                    const uint32_t b0h = WOHw[w], b1h = WOHw[w + 4];
                    const uint32_t b0l = WOLw[w], b1l = WOLw[w + 4];
                    mma_bf16(dy[nt], aoh[kt][0], aoh[kt][1], aoh[kt][2], aoh[kt][3], b0h, b1h);
                    mma_bf16(dy[nt], aol[kt][0], aol[kt][1], aol[kt][2], aol[kt][3], b0h, b1h);
                    mma_bf16(dy[nt], aoh[kt][0], aoh[kt][1], aoh[kt][2], aoh[kt][3], b0l, b1l);
                }
            // bias + residual; LN1 stats for tokens gq (A) and gq+8 (B)
            const float* ebase = emb + (g * 32 + warp * 2) * 224;
            float yA[8], yB[8];
            float sA = 0.0f, qA2 = 0.0f, sB = 0.0f, qB2 = 0.0f;
#pragma unroll
            for (int nt = 0; nt < 4; nt++) {
                const int e0 = nt * 8 + 2 * tq;
                const bool ok = (nt < 3) || (tq < 2);
                float2 rA = make_float2(0.0f, 0.0f), rB = make_float2(0.0f, 0.0f);
                if (ok) {
                    rA = *reinterpret_cast<const float2*>(ebase + gq * 28 + e0);
                    rB = *reinterpret_cast<const float2*>(ebase + (gq + 8) * 28 + e0);
                }
                const float bo0 = smf[F_BO + ((e0 < 28) ? e0 : 0)];
                const float bo1 = smf[F_BO + ((e0 + 1 < 28) ? e0 + 1 : 0)];
                float a0 = ok ? (dy[nt][0] + bo0 + rA.x) : 0.0f;
                float a1 = ok ? (dy[nt][1] + bo1 + rA.y) : 0.0f;
                float b0 = ok ? (dy[nt][2] + bo0 + rB.x) : 0.0f;
                float b1 = ok ? (dy[nt][3] + bo1 + rB.y) : 0.0f;
                yA[nt * 2] = a0; yA[nt * 2 + 1] = a1;
                yB[nt * 2] = b0; yB[nt * 2 + 1] = b1;
                sA += a0 + a1; qA2 += a0 * a0 + a1 * a1;
                sB += b0 + b1; qB2 += b0 * b0 + b1 * b1;
            }
            sA += __shfl_xor_sync(0xffffffffu, sA, 1); qA2 += __shfl_xor_sync(0xffffffffu, qA2, 1);
            sA += __shfl_xor_sync(0xffffffffu, sA, 2); qA2 += __shfl_xor_sync(0xffffffffu, qA2, 2);
            sB += __shfl_xor_sync(0xffffffffu, sB, 1); qB2 += __shfl_xor_sync(0xffffffffu, qB2, 1);
            sB += __shfl_xor_sync(0xffffffffu, sB, 2); qB2 += __shfl_xor_sync(0xffffffffu, qB2, 2);
            const float muA = sA * (1.0f / 28.0f), muB = sB * (1.0f / 28.0f);
            const float rsA = rsqrtf(fmaxf(qA2 * (1.0f / 28.0f) - muA * muA, 0.0f) + 1e-5f);
            const float rsB = rsqrtf(fmaxf(qB2 * (1.0f / 28.0f) - muB * muB, 0.0f) + 1e-5f);
#pragma unroll
            for (int nt = 0; nt < 4; nt++) {
                const int e0 = nt * 8 + 2 * tq;
                const bool ok = (nt < 3) || (tq < 2);
                if (ok) {
                    const float g10 = smf[F_G1 + e0], g11 = smf[F_G1 + e0 + 1];
                    const float bl0 = smf[F_B1L + e0], bl1 = smf[F_B1L + e0 + 1];
                    float xA0 = (yA[nt * 2]     - muA) * rsA * g10 + bl0;
                    float xA1 = (yA[nt * 2 + 1] - muA) * rsA * g11 + bl1;
                    float xB0 = (yB[nt * 2]     - muB) * rsB * g10 + bl0;
                    float xB1 = (yB[nt * 2 + 1] - muB) * rsB * g11 + bl1;
                    __nv_bfloat16 hA0, hA1, hB0, hB1; float lA0, lA1, lB0, lB1;
                    split_bf16(xA0, hA0, lA0); split_bf16(xA1, hA1, lA1);
                    split_bf16(xB0, hB0, lB0); split_bf16(xB1, hB1, lB1);
                    const int wA = (m0 + gq) * 18 + nt * 4 + tq;
                    const int wB = (m0 + gq + 8) * 18 + nt * 4 + tq;
                    XHw[wA] = pack_bf2(hA0, hA1);
                    XLw[wA] = pack_bf2(__float2bfloat16(lA0), __float2bfloat16(lA1));
                    XHw[wB] = pack_bf2(hB0, hB1);
                    XLw[wB] = pack_bf2(__float2bfloat16(lB0), __float2bfloat16(lB1));
                }
            }
        }
        __syncwarp();

        // ---------------- PHASE 2: FFN via mma.sync (16 tokens per warp) ----------------
        uint32_t ah[2][4], al[2][4];
#pragma unroll
        for (int kt = 0; kt < 2; kt++) {
            const int w0 = (m0 + gq) * 18 + kt * 8 + tq;
            ah[kt][0] = XHw[w0];       ah[kt][1] = XHw[w0 + 144];
            ah[kt][2] = XHw[w0 + 4];   ah[kt][3] = XHw[w0 + 148];
            al[kt][0] = XLw[w0];       al[kt][1] = XLw[w0 + 144];
            al[kt][2] = XLw[w0 + 4];   al[kt][3] = XLw[w0 + 148];
        }

        float d2[4][4];
#pragma unroll
        for (int nt = 0; nt < 4; nt++)
#pragma unroll
            for (int r = 0; r < 4; r++) d2[nt][r] = 0.0f;

        for (int fc = 0; fc < 16; fc++) {
            float d1[2][4];
#pragma unroll
            for (int nt = 0; nt < 2; nt++)
#pragma unroll
                for (int r = 0; r < 4; r++) d1[nt][r] = 0.0f;
#pragma unroll
            for (int kt = 0; kt < 2; kt++)
#pragma unroll
                for (int nt = 0; nt < 2; nt++) {
                    const int w = (fc * 16 + nt * 8 + gq) * 18 + kt * 8 + tq;
                    const uint32_t b0h = W1Hw[w], b1h = W1Hw[w + 4];
                    const uint32_t b0l = W1Lw[w], b1l = W1Lw[w + 4];
                    mma_bf16(d1[nt], ah[kt][0], ah[kt][1], ah[kt][2], ah[kt][3], b0h, b1h);
                    mma_bf16(d1[nt], al[kt][0], al[kt][1], al[kt][2], al[kt][3], b0h, b1h);
                    mma_bf16(d1[nt], ah[kt][0], ah[kt][1], ah[kt][2], ah[kt][3], b0l, b1l);
                }
            uint32_t a2h[4], a2l[4];
#pragma unroll
            for (int nt = 0; nt < 2; nt++) {
                const int fe = fc * 16 + nt * 8 + 2 * tq;
                const float bz0 = smf[F_B1 + fe], bz1 = smf[F_B1 + fe + 1];
                float h0 = fmaxf(d1[nt][0] + bz0, 0.0f);
                float h1 = fmaxf(d1[nt][1] + bz1, 0.0f);
                float h2 = fmaxf(d1[nt][2] + bz0, 0.0f);
                float h3 = fmaxf(d1[nt][3] + bz1, 0.0f);
                __nv_bfloat16 q0, q1, q2, q3; float l0, l1, l2, l3;
                split_bf16(h0, q0, l0); split_bf16(h1, q1, l1);
                split_bf16(h2, q2, l2); split_bf16(h3, q3, l3);
                a2h[nt * 2 + 0] = pack_bf2(q0, q1);
                a2h[nt * 2 + 1] = pack_bf2(q2, q3);
                a2l[nt * 2 + 0] = pack_bf2(__float2bfloat16(l0), __float2bfloat16(l1));
                a2l[nt * 2 + 1] = pack_bf2(__float2bfloat16(l2), __float2bfloat16(l3));
            }
#pragma unroll
            for (int nt2 = 0; nt2 < 4; nt2++) {
                const int w2 = (nt2 * 8 + gq) * 132 + fc * 8 + tq;
                const uint32_t b0h = W2Hw[w2], b1h = W2Hw[w2 + 4];
                const uint32_t b0l = W2Lw[w2], b1l = W2Lw[w2 + 4];
                mma_bf16(d2[nt2], a2h[0], a2h[1], a2h[2], a2h[3], b0h, b1h);
                mma_bf16(d2[nt2], a2l[0], a2l[1], a2l[2], a2l[3], b0h, b1h);
                mma_bf16(d2[nt2], a2h[0], a2h[1], a2h[2], a2h[3], b0l, b1l);
            }
        }

        // ---------------- EPILOGUE: one span at a time ----------------
#pragma unroll
        for (int sp2 = 0; sp2 < 2; sp2++) {
            const int tok = m0 + gq + sp2 * 8;
            const int sl = warp * 2 + sp2;
            const int c0 = sp2 * 2;
            float v[8];
            float ssum = 0.0f, sq = 0.0f;
#pragma unroll
            for (int nt = 0; nt < 4; nt++) {
                const int e0 = nt * 8 + 2 * tq;
                const bool ok = (nt < 3) || (tq < 2);
                const uint32_t uh = XHw[tok * 18 + nt * 4 + tq];
                const uint32_t ul = XLw[tok * 18 + nt * 4 + tq];
                const __nv_bfloat162 bh = *reinterpret_cast<const __nv_bfloat162*>(&uh);
                const __nv_bfloat162 bl = *reinterpret_cast<const __nv_bfloat162*>(&ul);
                const float xn0 = __bfloat162float(bh.x) + __bfloat162float(bl.x);
                const float xn1 = __bfloat162float(bh.y) + __bfloat162float(bl.y);
                float a0 = ok ? (d2[nt][c0]     + smf[F_B2 + e0]     + xn0) : 0.0f;
                float a1 = ok ? (d2[nt][c0 + 1] + smf[F_B2 + e0 + 1] + xn1) : 0.0f;
                v[nt * 2] = a0; v[nt * 2 + 1] = a1;
                ssum += a0 + a1; sq += a0 * a0 + a1 * a1;
            }
            ssum += __shfl_xor_sync(0xffffffffu, ssum, 1); sq += __shfl_xor_sync(0xffffffffu, sq, 1);
            ssum += __shfl_xor_sync(0xffffffffu, ssum, 2); sq += __shfl_xor_sync(0xffffffffu, sq, 2);
            const float mu = ssum * (1.0f / 28.0f);
            const float rs = rsqrtf(fmaxf(sq * (1.0f / 28.0f) - mu * mu, 0.0f) + 1e-5f);
            const int len = lens[sl];
            const float m = (gq < len) ? 1.0f : 0.0f;
            float pz[8];
#pragma unroll
            for (int nt = 0; nt < 4; nt++) {
                const int e0 = nt * 8 + 2 * tq;
                const bool ok = (nt < 3) || (tq < 2);
                pz[nt * 2]     = ok ? ((v[nt * 2]     - mu) * rs * smf[F_G2 + e0]     + smf[F_B2L + e0])     * m : 0.0f;
                pz[nt * 2 + 1] = ok ? ((v[nt * 2 + 1] - mu) * rs * smf[F_G2 + e0 + 1] + smf[F_B2L + e0 + 1]) * m : 0.0f;
            }
#pragma unroll
            for (int i = 0; i < 8; i++) {
                float a = pz[i];
                a += __shfl_xor_sync(0xffffffffu, a, 4);
                a += __shfl_xor_sync(0xffffffffu, a, 8);
                a += __shfl_xor_sync(0xffffffffu, a, 16);
                pz[i] = a;
            }
            if (lane < 4) {
                const float il = 1.0f / (float)len;
                const int sp = g * 32 + sl;
                const int okv = vld[sl];
#pragma unroll
                for (int nt = 0; nt < 4; nt++) {
                    const int e0 = nt * 8 + 2 * tq;
                    if ((nt < 3) || (tq < 2)) {
                        outp[sp * 28 + e0]     = okv ? pz[nt * 2] * il     : smf[F_PAD + e0];
                        outp[sp * 28 + e0 + 1] = okv ? pz[nt * 2 + 1] * il : smf[F_PAD + e0 + 1];
                    }
                }
            }
        }
        __syncwarp();
    }
}

extern "C" void kernel_launch(void* const* d_in, const int* in_sizes, int n_in,
                              void* d_out, int out_size) {
    const float* emb          = (const float*)d_in[0];
    const int*   span_lengths = (const int*)  d_in[1];
    const int*   num_spans    = (const int*)  d_in[2];
    const float* in_proj_w    = (const float*)d_in[3];
    const float* in_proj_b    = (const float*)d_in[4];
    const float* out_proj_w   = (const float*)d_in[5];
    const float* out_proj_b   = (const float*)d_in[6];
    const float* ln1_g        = (const float*)d_in[7];
    const float* ln1_b        = (const float*)d_in[8];
    const float* lin1_w       = (const float*)d_in[9];
    const float* lin1_b       = (const float*)d_in[10];
    const float* lin2_w       = (const float*)d_in[11];
    const float* lin2_b       = (const float*)d_in[12];
    const float* ln2_g        = (const float*)d_in[13];
    const float* ln2_b        = (const float*)d_in[14];
    const float* pad_token    = (const float*)d_in[15];
    float* outp = (float*)d_out;

    cudaFuncSetAttribute(span_mma_kernel,
                         cudaFuncAttributeMaxDynamicSharedMemorySize, SMEM_END_B);

    span_mma_kernel<<<148, 512, SMEM_END_B>>>(
        emb, span_lengths, num_spans,
        in_proj_w, in_proj_b, out_proj_w, out_proj_b,
        ln1_g, ln1_b, lin1_w, lin1_b, lin2_w, lin2_b,
        ln2_g, ln2_b, pad_token, outp);
}

// round 14
// speedup vs baseline: 2.8451x; 1.0699x over previous
#include <cuda_runtime.h>
#include <cuda_bf16.h>
#include <cstdint>

#define T_ 512
#define NG 1024            // groups of 32 spans (256 tokens per block-group)

// ---------------- smem layout ----------------
// float indices
#define F_BQKV 0          // 84
#define F_BO   84
#define F_G1   112
#define F_B1L  140
#define F_B1   168        // 256
#define F_B2   424        // 32 (pad zero)
#define F_G2   456
#define F_B2L  488
#define F_PAD  520
#define I_LEN  548        // int[32]
#define I_VAL  580        // int[32]
// byte offsets (16B aligned)
#define XH_B   2560       // X hi [256 tok][36 halves]  (emb-split only)
#define XL_B   20992      // end 39424
#define W1F_B  39424      // W1 frags [16 fc][2 kt][2 nt][32 lane] uint4 = 32768
#define W2F_B  72192      // W2 frags [16 fc][4 nt2][32 lane] uint4 = 32768
#define WQF_B  104960     // Wqkv frags [11 nq][2 kt][32 lane] uint4 = 11264
#define WOF_B  116224     // Wout frags [2 kt][4 nt][32 lane] uint4 = 4096
#define SCR_B  120320     // 16 warps x 1600 floats (QKV scratch [16 tok][100])
#define SCRF   30080
#define SMEM_END_B 222720

__device__ __forceinline__ void mma_bf16(float* d, uint32_t a0, uint32_t a1,
                                         uint32_t a2, uint32_t a3,
                                         uint32_t b0, uint32_t b1) {
    asm volatile(
        "mma.sync.aligned.m16n8k16.row.col.f32.bf16.bf16.f32 "
        "{%0,%1,%2,%3}, {%4,%5,%6,%7}, {%8,%9}, {%0,%1,%2,%3};"
        : "+f"(d[0]), "+f"(d[1]), "+f"(d[2]), "+f"(d[3])
        : "r"(a0), "r"(a1), "r"(a2), "r"(a3), "r"(b0), "r"(b1));
}
__device__ __forceinline__ uint32_t pack_bf2(__nv_bfloat16 lo, __nv_bfloat16 hi) {
    __nv_bfloat162 t(lo, hi);
    return *reinterpret_cast<uint32_t*>(&t);
}
__device__ __forceinline__ void split_bf16(float v, __nv_bfloat16& hi, float& lo) {
    hi = __float2bfloat16(v);
    lo = v - __bfloat162float(hi);
}
// pack a (hi,lo) bf16 pair for elements (e0, e0+1) of row `row`
__device__ __forceinline__ uint2 pack_pair(const float* __restrict__ src, int row, int stride,
                                           int e0, int rmax, int emax) {
    float v0 = (row < rmax && e0     < emax) ? src[row * stride + e0]     : 0.0f;
    float v1 = (row < rmax && e0 + 1 < emax) ? src[row * stride + e0 + 1] : 0.0f;
    __nv_bfloat16 h0, h1; float l0, l1;
    split_bf16(v0, h0, l0); split_bf16(v1, h1, l1);
    uint2 r;
    r.x = pack_bf2(h0, h1);
    r.y = pack_bf2(__float2bfloat16(l0), __float2bfloat16(l1));
    return r;
}

__global__ __launch_bounds__(512, 1)
void span_mma_kernel(
    const float* __restrict__ emb,
    const int*   __restrict__ span_lengths,
    const int*   __restrict__ num_spans,
    const float* __restrict__ in_proj_w, const float* __restrict__ in_proj_b,
    const float* __restrict__ out_proj_w, const float* __restrict__ out_proj_b,
    const float* __restrict__ ln1_g, const float* __restrict__ ln1_b,
    const float* __restrict__ lin1_w, const float* __restrict__ lin1_b,
    const float* __restrict__ lin2_w, const float* __restrict__ lin2_b,
    const float* __restrict__ ln2_g, const float* __restrict__ ln2_b,
    const float* __restrict__ pad_token,
    float* __restrict__ outp)
{
    extern __shared__ char smc[];
    float* smf = reinterpret_cast<float*>(smc);
    const int tid = threadIdx.x, warp = tid >> 5, lane = tid & 31;

    // zero X tiles (pad cols must be 0)
    {
        int4 z = make_int4(0, 0, 0, 0);
        int4* d = reinterpret_cast<int4*>(smc + XH_B);
        for (int i = tid; i < (W1F_B - XH_B) / 16; i += 512) d[i] = z;
    }
    for (int i = tid; i < 84; i += 512) smf[F_BQKV + i] = in_proj_b[i];
    if (tid < 256) smf[F_B1 + tid] = lin1_b[tid];
    if (tid < 32) {
        smf[F_B2 + tid]  = (tid < 28) ? lin2_b[tid] : 0.0f;
        smf[F_G2 + tid]  = (tid < 28) ? ln2_g[tid]  : 0.0f;
        smf[F_B2L + tid] = (tid < 28) ? ln2_b[tid]  : 0.0f;
    }
    if (tid < 28) {
        smf[F_BO + tid]  = out_proj_b[tid];
        smf[F_G1 + tid]  = ln1_g[tid];
        smf[F_B1L + tid] = ln1_b[tid];
        smf[F_PAD + tid] = pad_token[tid];
    }
    // ---- stage weights in FRAGMENT order (uint4 = b0h,b1h,b0l,b1l) ----
    for (int idx = tid; idx < 2048; idx += 512) {        // W1 [256 f][28 e]
        const int ln = idx & 31, nt = (idx >> 5) & 1, kt = (idx >> 6) & 1, fc = idx >> 7;
        const int row = fc * 16 + nt * 8 + (ln >> 2);
        const int e0 = kt * 16 + 2 * (ln & 3);
        uint2 p0 = pack_pair(lin1_w, row, 28, e0, 256, 28);
        uint2 p1 = pack_pair(lin1_w, row, 28, e0 + 8, 256, 28);
        reinterpret_cast<uint4*>(smc + W1F_B)[idx] = make_uint4(p0.x, p1.x, p0.y, p1.y);
    }
    for (int idx = tid; idx < 2048; idx += 512) {        // W2 [28 e][256 f] (B rows = e)
        const int ln = idx & 31, nt2 = (idx >> 5) & 3, fc = idx >> 7;
        const int row = nt2 * 8 + (ln >> 2);
        const int f0 = fc * 16 + 2 * (ln & 3);
        uint2 p0 = pack_pair(lin2_w, row, 256, f0, 28, 256);
        uint2 p1 = pack_pair(lin2_w, row, 256, f0 + 8, 28, 256);
        reinterpret_cast<uint4*>(smc + W2F_B)[idx] = make_uint4(p0.x, p1.x, p0.y, p1.y);
    }
    for (int idx = tid; idx < 704; idx += 512) {         // Wqkv [84 r][28 e]
        const int ln = idx & 31, kt = (idx >> 5) & 1, nq = idx >> 6;
        const int row = nq * 8 + (ln >> 2);
        const int e0 = kt * 16 + 2 * (ln & 3);
        uint2 p0 = pack_pair(in_proj_w, row, 28, e0, 84, 28);
        uint2 p1 = pack_pair(in_proj_w, row, 28, e0 + 8, 84, 28);
        reinterpret_cast<uint4*>(smc + WQF_B)[idx] = make_uint4(p0.x, p1.x, p0.y, p1.y);
    }
    for (int idx = tid; idx < 256; idx += 512) {         // Wout [28 r][28 e]
        const int ln = idx & 31, nt = (idx >> 5) & 3, kt = idx >> 7;
        const int row = nt * 8 + (ln >> 2);
        const int e0 = kt * 16 + 2 * (ln & 3);
        uint2 p0 = pack_pair(out_proj_w, row, 28, e0, 28, 28);
        uint2 p1 = pack_pair(out_proj_w, row, 28, e0 + 8, 28, 28);
        reinterpret_cast<uint4*>(smc + WOF_B)[idx] = make_uint4(p0.x, p1.x, p0.y, p1.y);
    }
    __syncthreads();

    uint32_t* XHw = reinterpret_cast<uint32_t*>(smc + XH_B);
    uint32_t* XLw = reinterpret_cast<uint32_t*>(smc + XL_B);
    const uint4* W1F = reinterpret_cast<const uint4*>(smc + W1F_B);
    const uint4* W2F = reinterpret_cast<const uint4*>(smc + W2F_B);
    const uint4* WQF = reinterpret_cast<const uint4*>(smc + WQF_B);
    const uint4* WOF = reinterpret_cast<const uint4*>(smc + WOF_B);
    int* lens = reinterpret_cast<int*>(smf + I_LEN);
    int* vld  = reinterpret_cast<int*>(smf + I_VAL);

    const int l = lane & 7, h = lane >> 3, e0h = h * 7;
    const int gq = lane >> 2, tq = lane & 3;
    const int m0 = warp * 16;
    float* QW = smf + SCRF + warp * 1600;                 // [16 tok][100]: Q@0 K@32 V@64
    uint32_t* QWu = reinterpret_cast<uint32_t*>(QW);
    char* aobase = smc + SCR_B + warp * 6400;             // AO split lives in K slot

    for (int g = blockIdx.x; g < NG; g += gridDim.x) {
        // ---- (a) emb -> X bf16 hi/lo tiles (warp-private 16 tokens) ----
        {
            const float2* esrc = reinterpret_cast<const float2*>(emb + (g * 32 + warp * 2) * 224);
#pragma unroll
            for (int k2 = 0; k2 < 7; k2++) {
                const int idx2 = lane + k2 * 32;
                float2 v = esrc[idx2];
                const int fi = idx2 * 2;
                const int tok = fi / 28, e = fi % 28;
                __nv_bfloat16 h0, h1; float l0, l1;
                split_bf16(v.x, h0, l0);
                split_bf16(v.y, h1, l1);
                const int word = (m0 + tok) * 18 + e / 2;
                XHw[word] = pack_bf2(h0, h1);
                XLw[word] = pack_bf2(__float2bfloat16(l0), __float2bfloat16(l1));
            }
        }
        __syncwarp();

        // ---- (b) GEMM_QKV: [16 x 32] x Wqkv^T[88 x 32] ----
        {
            uint32_t ah[2][4], al[2][4];
#pragma unroll
            for (int kt = 0; kt < 2; kt++) {
                const int w0 = (m0 + gq) * 18 + kt * 8 + tq;
                ah[kt][0] = XHw[w0];       ah[kt][1] = XHw[w0 + 144];
                ah[kt][2] = XHw[w0 + 4];   ah[kt][3] = XHw[w0 + 148];
                al[kt][0] = XLw[w0];       al[kt][1] = XLw[w0 + 144];
                al[kt][2] = XLw[w0 + 4];   al[kt][3] = XLw[w0 + 148];
            }
#pragma unroll
            for (int nq = 0; nq < 11; nq++) {
                float d[4] = {0.0f, 0.0f, 0.0f, 0.0f};
#pragma unroll
                for (int kt = 0; kt < 2; kt++) {
                    const uint4 wf = WQF[(nq * 2 + kt) * 32 + lane];
                    mma_bf16(d, ah[kt][0], ah[kt][1], ah[kt][2], ah[kt][3], wf.x, wf.y);
                    mma_bf16(d, al[kt][0], al[kt][1], al[kt][2], al[kt][3], wf.x, wf.y);
                    mma_bf16(d, ah[kt][0], ah[kt][1], ah[kt][2], ah[kt][3], wf.z, wf.w);
                }
                const int c0 = nq * 8 + 2 * tq;
                if (c0 < 84) {
                    const int qk = c0 / 28, r = c0 % 28;
                    const int off = qk * 32 + (r / 7) * 8 + (r % 7);
                    const float bz = smf[F_BQKV + c0];
                    QW[gq * 100 + off]       = d[0] + bz;
                    QW[(gq + 8) * 100 + off] = d[2] + bz;
                }
                const int c1 = c0 + 1;
                if (c1 < 84) {
                    const int qk = c1 / 28, r = c1 % 28;
                    const int off = qk * 32 + (r / 7) * 8 + (r % 7);
                    const float bz = smf[F_BQKV + c1];
                    QW[gq * 100 + off]       = d[1] + bz;
                    QW[(gq + 8) * 100 + off] = d[3] + bz;
                }
            }
        }
        __syncwarp();

        // ---- (c) attention per span; ao -> bf16 split into K slot ----
        for (int j = 0; j < 2; j++) {
            const int sl = warp * 2 + j;
            const int span = g * 32 + sl;
            const int b = span >> 9, t = span & (T_ - 1);
            const int tok = j * 8 + l;
            const int len = span_lengths[span];

            float q[7];
            {
                const float4 qa = *reinterpret_cast<const float4*>(QW + tok * 100 + h * 8);
                const float4 qb = *reinterpret_cast<const float4*>(QW + tok * 100 + h * 8 + 4);
                q[0] = qa.x; q[1] = qa.y; q[2] = qa.z; q[3] = qa.w;
                q[4] = qb.x; q[5] = qb.y; q[6] = qb.z;
            }
            float s[8];
#pragma unroll
            for (int kk = 0; kk < 8; kk++) {
                const float4 ka = *reinterpret_cast<const float4*>(QW + (j * 8 + kk) * 100 + 32 + h * 8);
                const float4 kb = *reinterpret_cast<const float4*>(QW + (j * 8 + kk) * 100 + 32 + h * 8 + 4);
                float acc = q[0] * ka.x + q[1] * ka.y + q[2] * ka.z + q[3] * ka.w
                          + q[4] * kb.x + q[5] * kb.y + q[6] * kb.z;
                s[kk] = (kk < len) ? acc * 0.3779644730092272f : -1e9f;
            }
            __syncwarp();   // all K reads done before K slot is reused for AO
            float mx = s[0];
#pragma unroll
            for (int kk = 1; kk < 8; kk++) mx = fmaxf(mx, s[kk]);
            float p[8], ps = 0.0f;
#pragma unroll
            for (int kk = 0; kk < 8; kk++) { p[kk] = __expf(s[kk] - mx); ps += p[kk]; }
            const float pinv = 1.0f / ps;
            float ao[7];
#pragma unroll
            for (int d = 0; d < 7; d++) ao[d] = 0.0f;
#pragma unroll
            for (int kk = 0; kk < 8; kk++) {
                const float4 va = *reinterpret_cast<const float4*>(QW + (j * 8 + kk) * 100 + 64 + h * 8);
                const float4 vb = *reinterpret_cast<const float4*>(QW + (j * 8 + kk) * 100 + 64 + h * 8 + 4);
                ao[0] = fmaf(p[kk], va.x, ao[0]); ao[1] = fmaf(p[kk], va.y, ao[1]);
                ao[2] = fmaf(p[kk], va.z, ao[2]); ao[3] = fmaf(p[kk], va.w, ao[3]);
                ao[4] = fmaf(p[kk], vb.x, ao[4]); ao[5] = fmaf(p[kk], vb.y, ao[5]);
                ao[6] = fmaf(p[kk], vb.z, ao[6]);
            }
            // AO split store: AOH halves at bytes tok*400+128+e*2, AOL at +192+e*2
#pragma unroll
            for (int d = 0; d < 7; d++) {
                const int e = e0h + d;
                __nv_bfloat16 hh; float lf; split_bf16(ao[d] * pinv, hh, lf);
                *reinterpret_cast<__nv_bfloat16*>(aobase + tok * 400 + 128 + e * 2) = hh;
                *reinterpret_cast<__nv_bfloat16*>(aobase + tok * 400 + 192 + e * 2) = __float2bfloat16(lf);
            }
            if (lane == 0) { lens[sl] = len; vld[sl] = (t < num_spans[b]) ? 1 : 0; }
            __syncwarp();
        }
        // zero AO pad cols 28-31 (stale K data): floats 46,47 (AOH) / 62,63 (AOL)
        QW[(lane >> 1) * 100 + 46 + (lane & 1)] = 0.0f;
        QW[(lane >> 1) * 100 + 62 + (lane & 1)] = 0.0f;
        __syncwarp();

        // xn fragment registers (filled by GEMM_O, consumed by FFN + epilogue)
        uint32_t ah[2][4], al[2][4];

        // ---- (d) GEMM_O: [16 x 32] x Wout^T[32 x 32]; +bias +residual +LN1 -> ah/al regs ----
        {
            uint32_t aoh[2][4], aol[2][4];
#pragma unroll
            for (int kt = 0; kt < 2; kt++) {
                const int w0 = gq * 100 + 32 + kt * 8 + tq;
                aoh[kt][0] = QWu[w0];        aoh[kt][1] = QWu[w0 + 800];
                aoh[kt][2] = QWu[w0 + 4];    aoh[kt][3] = QWu[w0 + 804];
                aol[kt][0] = QWu[w0 + 16];   aol[kt][1] = QWu[w0 + 816];
                aol[kt][2] = QWu[w0 + 20];   aol[kt][3] = QWu[w0 + 820];
            }
            float dy[4][4];
#pragma unroll
            for (int nt = 0; nt < 4; nt++)
#pragma unroll
                for (int r = 0; r < 4; r++) dy[nt][r] = 0.0f;
#pragma unroll
            for (int kt = 0; kt < 2; kt++)
#pragma unroll
                for (int nt = 0; nt < 4; nt++) {
                    const uint4 wf = WOF[(kt * 4 + nt) * 32 + lane];
                    mma_bf16(dy[nt], aoh[kt][0], aoh[kt][1], aoh[kt][2], aoh[kt][3], wf.x, wf.y);
                    mma_bf16(dy[nt], aol[kt][0], aol[kt][1], aol[kt][2], aol[kt][3], wf.x, wf.y);
                    mma_bf16(dy[nt], aoh[kt][0], aoh[kt][1], aoh[kt][2], aoh[kt][3], wf.z, wf.w);
                }
            // bias + residual; LN1 stats for tokens gq (A) and gq+8 (B)
            const float* ebase = emb + (g * 32 + warp * 2) * 224;
            float yA[8], yB[8];
            float sA = 0.0f, qA2 = 0.0f, sB = 0.0f, qB2 = 0.0f;
#pragma unroll
            for (int nt = 0; nt < 4; nt++) {
                const int e0 = nt * 8 + 2 * tq;
                const bool ok = (nt < 3) || (tq < 2);
                float2 rA = make_float2(0.0f, 0.0f), rB = make_float2(0.0f, 0.0f);
                float bo0 = 0.0f, bo1 = 0.0f;
                if (ok) {
                    rA = *reinterpret_cast<const float2*>(ebase + gq * 28 + e0);
                    rB = *reinterpret_cast<const float2*>(ebase + (gq + 8) * 28 + e0);
                    bo0 = smf[F_BO + e0];
                    bo1 = smf[F_BO + e0 + 1];
                }
                float a0 = ok ? (dy[nt][0] + bo0 + rA.x) : 0.0f;
                float a1 = ok ? (dy[nt][1] + bo1 + rA.y) : 0.0f;
                float b0 = ok ? (dy[nt][2] + bo0 + rB.x) : 0.0f;
                float b1 = ok ? (dy[nt][3] + bo1 + rB.y) : 0.0f;
                yA[nt * 2] = a0; yA[nt * 2 + 1] = a1;
                yB[nt * 2] = b0; yB[nt * 2 + 1] = b1;
                sA += a0 + a1; qA2 += a0 * a0 + a1 * a1;
                sB += b0 + b1; qB2 += b0 * b0 + b1 * b1;
            }
            sA += __shfl_xor_sync(0xffffffffu, sA, 1); qA2 += __shfl_xor_sync(0xffffffffu, qA2, 1);
            sA += __shfl_xor_sync(0xffffffffu, sA, 2); qA2 += __shfl_xor_sync(0xffffffffu, qA2, 2);
            sB += __shfl_xor_sync(0xffffffffu, sB, 1); qB2 += __shfl_xor_sync(0xffffffffu, qB2, 1);
            sB += __shfl_xor_sync(0xffffffffu, sB, 2); qB2 += __shfl_xor_sync(0xffffffffu, qB2, 2);
            const float muA = sA * (1.0f / 28.0f), muB = sB * (1.0f / 28.0f);
            const float rsA = rsqrtf(fmaxf(qA2 * (1.0f / 28.0f) - muA * muA, 0.0f) + 1e-5f);
            const float rsB = rsqrtf(fmaxf(qB2 * (1.0f / 28.0f) - muB * muB, 0.0f) + 1e-5f);
#pragma unroll
            for (int nt = 0; nt < 4; nt++) {
                const int e0 = nt * 8 + 2 * tq;
                const bool ok = (nt < 3) || (tq < 2);
                const int ktX = nt >> 1, sl0 = (nt & 1) << 1;
                if (ok) {
                    const float g10 = smf[F_G1 + e0], g11 = smf[F_G1 + e0 + 1];
                    const float bl0 = smf[F_B1L + e0], bl1 = smf[F_B1L + e0 + 1];
                    float xA0 = (yA[nt * 2]     - muA) * rsA * g10 + bl0;
                    float xA1 = (yA[nt * 2 + 1] - muA) * rsA * g11 + bl1;
                    float xB0 = (yB[nt * 2]     - muB) * rsB * g10 + bl0;
                    float xB1 = (yB[nt * 2 + 1] - muB) * rsB * g11 + bl1;
                    __nv_bfloat16 hA0, hA1, hB0, hB1; float lA0, lA1, lB0, lB1;
                    split_bf16(xA0, hA0, lA0); split_bf16(xA1, hA1, lA1);
                    split_bf16(xB0, hB0, lB0); split_bf16(xB1, hB1, lB1);
                    ah[ktX][sl0]     = pack_bf2(hA0, hA1);
                    ah[ktX][sl0 + 1] = pack_bf2(hB0, hB1);
                    al[ktX][sl0]     = pack_bf2(__float2bfloat16(lA0), __float2bfloat16(lA1));
                    al[ktX][sl0 + 1] = pack_bf2(__float2bfloat16(lB0), __float2bfloat16(lB1));
                } else {
                    ah[ktX][sl0] = 0u; ah[ktX][sl0 + 1] = 0u;
                    al[ktX][sl0] = 0u; al[ktX][sl0 + 1] = 0u;
                }
            }
        }
        __syncwarp();   // QW reads complete before next group's scatter

        // ---------------- PHASE 2: FFN via mma.sync (A-frags already in ah/al) ----------------
        float d2[4][4];
#pragma unroll
        for (int nt = 0; nt < 4; nt++)
#pragma unroll
            for (int r = 0; r < 4; r++) d2[nt][r] = 0.0f;

        for (int fc = 0; fc < 16; fc++) {
            float d1[2][4];
#pragma unroll
            for (int nt = 0; nt < 2; nt++)
#pragma unroll
                for (int r = 0; r < 4; r++) d1[nt][r] = 0.0f;
#pragma unroll
            for (int kt = 0; kt < 2; kt++)
#pragma unroll
                for (int nt = 0; nt < 2; nt++) {
                    const uint4 wf = W1F[((fc * 2 + kt) * 2 + nt) * 32 + lane];
                    mma_bf16(d1[nt], ah[kt][0], ah[kt][1], ah[kt][2], ah[kt][3], wf.x, wf.y);
                    mma_bf16(d1[nt], al[kt][0], al[kt][1], al[kt][2], al[kt][3], wf.x, wf.y);
                    mma_bf16(d1[nt], ah[kt][0], ah[kt][1], ah[kt][2], ah[kt][3], wf.z, wf.w);
                }
            uint32_t a2h[4], a2l[4];
#pragma unroll
            for (int nt = 0; nt < 2; nt++) {
                const int fe = fc * 16 + nt * 8 + 2 * tq;
                const float bz0 = smf[F_B1 + fe], bz1 = smf[F_B1 + fe + 1];
                float h0 = fmaxf(d1[nt][0] + bz0, 0.0f);
                float h1 = fmaxf(d1[nt][1] + bz1, 0.0f);
                float h2 = fmaxf(d1[nt][2] + bz0, 0.0f);
                float h3 = fmaxf(d1[nt][3] + bz1, 0.0f);
                __nv_bfloat16 q0, q1, q2, q3; float l0, l1, l2, l3;
                split_bf16(h0, q0, l0); split_bf16(h1, q1, l1);
                split_bf16(h2, q2, l2); split_bf16(h3, q3, l3);
                a2h[nt * 2 + 0] = pack_bf2(q0, q1);
                a2h[nt * 2 + 1] = pack_bf2(q2, q3);
                a2l[nt * 2 + 0] = pack_bf2(__float2bfloat16(l0), __float2bfloat16(l1));
                a2l[nt * 2 + 1] = pack_bf2(__float2bfloat16(l2), __float2bfloat16(l3));
            }
#pragma unroll
            for (int nt2 = 0; nt2 < 4; nt2++) {
                const uint4 wf = W2F[(fc * 4 + nt2) * 32 + lane];
                mma_bf16(d2[nt2], a2h[0], a2h[1], a2h[2], a2h[3], wf.x, wf.y);
                mma_bf16(d2[nt2], a2l[0], a2l[1], a2l[2], a2l[3], wf.x, wf.y);
                mma_bf16(d2[nt2], a2h[0], a2h[1], a2h[2], a2h[3], wf.z, wf.w);
            }
        }

        // ---------------- EPILOGUE: one span at a time (xn from ah/al regs) -------------
#pragma unroll
        for (int sp2 = 0; sp2 < 2; sp2++) {
            const int sl = warp * 2 + sp2;
            const int c0 = sp2 * 2;
            float v[8];
            float ssum = 0.0f, sq = 0.0f;
#pragma unroll
            for (int nt = 0; nt < 4; nt++) {
                const int e0 = nt * 8 + 2 * tq;
                const bool ok = (nt < 3) || (tq < 2);
                const int ktE = nt >> 1, slot = ((nt & 1) << 1) + sp2;
                const uint32_t uh = ah[ktE][slot];
                const uint32_t ul = al[ktE][slot];
                const __nv_bfloat162 bh = *reinterpret_cast<const __nv_bfloat162*>(&uh);
                const __nv_bfloat162 bl = *reinterpret_cast<const __nv_bfloat162*>(&ul);
                const float xn0 = __bfloat162float(bh.x) + __bfloat162float(bl.x);
                const float xn1 = __bfloat162float(bh.y) + __bfloat162float(bl.y);
                float a0 = ok ? (d2[nt][c0]     + smf[F_B2 + e0]     + xn0) : 0.0f;
                float a1 = ok ? (d2[nt][c0 + 1] + smf[F_B2 + e0 + 1] + xn1) : 0.0f;
                v[nt * 2] = a0; v[nt * 2 + 1] = a1;
                ssum += a0 + a1; sq += a0 * a0 + a1 * a1;
            }
            ssum += __shfl_xor_sync(0xffffffffu, ssum, 1); sq += __shfl_xor_sync(0xffffffffu, sq, 1);
            ssum += __shfl_xor_sync(0xffffffffu, ssum, 2); sq += __shfl_xor_sync(0xffffffffu, sq, 2);
            const float mu = ssum * (1.0f / 28.0f);
            const float rs = rsqrtf(fmaxf(sq * (1.0f / 28.0f) - mu * mu, 0.0f) + 1e-5f);
            const int len = lens[sl];
            const float m = (gq < len) ? 1.0f : 0.0f;
            float pz[8];
#pragma unroll
            for (int nt = 0; nt < 4; nt++) {
                const int e0 = nt * 8 + 2 * tq;
                const bool ok = (nt < 3) || (tq < 2);
                pz[nt * 2]     = ok ? ((v[nt * 2]     - mu) * rs * smf[F_G2 + e0]     + smf[F_B2L + e0])     * m : 0.0f;
                pz[nt * 2 + 1] = ok ? ((v[nt * 2 + 1] - mu) * rs * smf[F_G2 + e0 + 1] + smf[F_B2L + e0 + 1]) * m : 0.0f;
            }
#pragma unroll
            for (int i = 0; i < 8; i++) {
                float a = pz[i];
                a += __shfl_xor_sync(0xffffffffu, a, 4);
                a += __shfl_xor_sync(0xffffffffu, a, 8);
                a += __shfl_xor_sync(0xffffffffu, a, 16);
                pz[i] = a;
            }
            if (lane < 4) {
                const float il = 1.0f / (float)len;
                const int sp = g * 32 + sl;
                const int okv = vld[sl];
#pragma unroll
                for (int nt = 0; nt < 4; nt++) {
                    const int e0 = nt * 8 + 2 * tq;
                    if ((nt < 3) || (tq < 2)) {
                        outp[sp * 28 + e0]     = okv ? pz[nt * 2] * il     : smf[F_PAD + e0];
                        outp[sp * 28 + e0 + 1] = okv ? pz[nt * 2 + 1] * il : smf[F_PAD + e0 + 1];
                    }
                }
            }
        }
        __syncwarp();
    }
}

extern "C" void kernel_launch(void* const* d_in, const int* in_sizes, int n_in,
                              void* d_out, int out_size) {
    const float* emb          = (const float*)d_in[0];
    const int*   span_lengths = (const int*)  d_in[1];
    const int*   num_spans    = (const int*)  d_in[2];
    const float* in_proj_w    = (const float*)d_in[3];
    const float* in_proj_b    = (const float*)d_in[4];
    const float* out_proj_w   = (const float*)d_in[5];
    const float* out_proj_b   = (const float*)d_in[6];
    const float* ln1_g        = (const float*)d_in[7];
    const float* ln1_b        = (const float*)d_in[8];
    const float* lin1_w       = (const float*)d_in[9];
    const float* lin1_b       = (const float*)d_in[10];
    const float* lin2_w       = (const float*)d_in[11];
    const float* lin2_b       = (const float*)d_in[12];
    const float* ln2_g        = (const float*)d_in[13];
    const float* ln2_b        = (const float*)d_in[14];
    const float* pad_token    = (const float*)d_in[15];
    float* outp = (float*)d_out;

    cudaFuncSetAttribute(span_mma_kernel,
                         cudaFuncAttributeMaxDynamicSharedMemorySize, SMEM_END_B);

    span_mma_kernel<<<148, 512, SMEM_END_B>>>(
        emb, span_lengths, num_spans,
        in_proj_w, in_proj_b, out_proj_w, out_proj_b,
        ln1_g, ln1_b, lin1_w, lin1_b, lin2_w, lin2_b,
        ln2_g, ln2_b, pad_token, outp);
}

// round 16
// speedup vs baseline: 2.8737x; 1.0101x over previous
#include <cuda_runtime.h>
#include <cuda_bf16.h>
#include <cstdint>

#define T_ 512
#define NG 1024            // groups of 32 spans (256 tokens per block-group)

// ---------------- smem layout ----------------
// float indices
#define F_BQKV 0          // 84
#define F_BO   84
#define F_G1   112
#define F_B1L  140
#define F_B1   168        // 256
#define F_B2   424        // 32 (pad zero)
#define F_G2   456
#define F_B2L  488
#define F_PAD  520
#define I_LEN  548        // int[32]
#define I_VAL  580        // int[32]
// byte offsets (16B aligned)
#define XH_B   2560       // X hi [256 tok][36 halves]  (emb-split only)
#define XL_B   20992      // end 39424
#define W1F_B  39424      // W1 frags [16 fc][2 kt][2 nt][32 lane] uint4 = 32768
#define W2F_B  72192      // W2 frags [16 fc][4 nt2][32 lane] uint4 = 32768
#define WQF_B  104960     // Wqkv frags [11 nq][2 kt][32 lane] uint4 = 11264
#define WOF_B  116224     // Wout frags [2 kt][4 nt][32 lane] uint4 = 4096
#define SCR_B  120320     // 16 warps x 1600 floats (QKV scratch [16 tok][100])
#define SCRF   30080
#define SMEM_END_B 222720

__device__ __forceinline__ void mma_bf16(float* d, uint32_t a0, uint32_t a1,
                                         uint32_t a2, uint32_t a3,
                                         uint32_t b0, uint32_t b1) {
    asm volatile(
        "mma.sync.aligned.m16n8k16.row.col.f32.bf16.bf16.f32 "
        "{%0,%1,%2,%3}, {%4,%5,%6,%7}, {%8,%9}, {%0,%1,%2,%3};"
        : "+f"(d[0]), "+f"(d[1]), "+f"(d[2]), "+f"(d[3])
        : "r"(a0), "r"(a1), "r"(a2), "r"(a3), "r"(b0), "r"(b1));
}
__device__ __forceinline__ uint32_t pack_bf2(__nv_bfloat16 lo, __nv_bfloat16 hi) {
    __nv_bfloat162 t(lo, hi);
    return *reinterpret_cast<uint32_t*>(&t);
}
__device__ __forceinline__ void split_bf16(float v, __nv_bfloat16& hi, float& lo) {
    hi = __float2bfloat16(v);
    lo = v - __bfloat162float(hi);
}
// packed split: hi2 = bf16x2(v0 lo-half, v1 hi-half); lo2 = residuals, same layout
__device__ __forceinline__ void split_pack2(float v0, float v1, uint32_t& hi2, uint32_t& lo2) {
    uint32_t hh;
    asm("cvt.rn.bf16x2.f32 %0, %1, %2;" : "=r"(hh) : "f"(v1), "f"(v0));
    const __nv_bfloat162 hb = *reinterpret_cast<const __nv_bfloat162*>(&hh);
    const float l0 = v0 - __bfloat162float(hb.x);
    const float l1 = v1 - __bfloat162float(hb.y);
    uint32_t ll;
    asm("cvt.rn.bf16x2.f32 %0, %1, %2;" : "=r"(ll) : "f"(l1), "f"(l0));
    hi2 = hh;
    lo2 = ll;
}
// pack a (hi,lo) bf16 pair for elements (e0, e0+1) of row `row`
__device__ __forceinline__ uint2 pack_pair(const float* __restrict__ src, int row, int stride,
                                           int e0, int rmax, int emax) {
    float v0 = (row < rmax && e0     < emax) ? src[row * stride + e0]     : 0.0f;
    float v1 = (row < rmax && e0 + 1 < emax) ? src[row * stride + e0 + 1] : 0.0f;
    uint2 r;
    split_pack2(v0, v1, r.x, r.y);
    return r;
}

__global__ __launch_bounds__(512, 1)
void span_mma_kernel(
    const float* __restrict__ emb,
    const int*   __restrict__ span_lengths,
    const int*   __restrict__ num_spans,
    const float* __restrict__ in_proj_w, const float* __restrict__ in_proj_b,
    const float* __restrict__ out_proj_w, const float* __restrict__ out_proj_b,
    const float* __restrict__ ln1_g, const float* __restrict__ ln1_b,
    const float* __restrict__ lin1_w, const float* __restrict__ lin1_b,
    const float* __restrict__ lin2_w, const float* __restrict__ lin2_b,
    const float* __restrict__ ln2_g, const float* __restrict__ ln2_b,
    const float* __restrict__ pad_token,
    float* __restrict__ outp)
{
    extern __shared__ char smc[];
    float* smf = reinterpret_cast<float*>(smc);
    const int tid = threadIdx.x, warp = tid >> 5, lane = tid & 31;

    // zero X tiles (pad cols must be 0)
    {
        int4 z = make_int4(0, 0, 0, 0);
        int4* d = reinterpret_cast<int4*>(smc + XH_B);
        for (int i = tid; i < (W1F_B - XH_B) / 16; i += 512) d[i] = z;
    }
    for (int i = tid; i < 84; i += 512) smf[F_BQKV + i] = in_proj_b[i];
    if (tid < 256) smf[F_B1 + tid] = lin1_b[tid];
    if (tid < 32) {
        smf[F_B2 + tid]  = (tid < 28) ? lin2_b[tid] : 0.0f;
        smf[F_G2 + tid]  = (tid < 28) ? ln2_g[tid]  : 0.0f;
        smf[F_B2L + tid] = (tid < 28) ? ln2_b[tid]  : 0.0f;
    }
    if (tid < 28) {
        smf[F_BO + tid]  = out_proj_b[tid];
        smf[F_G1 + tid]  = ln1_g[tid];
        smf[F_B1L + tid] = ln1_b[tid];
        smf[F_PAD + tid] = pad_token[tid];
    }
    // ---- stage weights in FRAGMENT order (uint4 = b0h,b1h,b0l,b1l) ----
    for (int idx = tid; idx < 2048; idx += 512) {        // W1 [256 f][28 e]
        const int ln = idx & 31, nt = (idx >> 5) & 1, kt = (idx >> 6) & 1, fc = idx >> 7;
        const int row = fc * 16 + nt * 8 + (ln >> 2);
        const int e0 = kt * 16 + 2 * (ln & 3);
        uint2 p0 = pack_pair(lin1_w, row, 28, e0, 256, 28);
        uint2 p1 = pack_pair(lin1_w, row, 28, e0 + 8, 256, 28);
        reinterpret_cast<uint4*>(smc + W1F_B)[idx] = make_uint4(p0.x, p1.x, p0.y, p1.y);
    }
    for (int idx = tid; idx < 2048; idx += 512) {        // W2 [28 e][256 f] (B rows = e)
        const int ln = idx & 31, nt2 = (idx >> 5) & 3, fc = idx >> 7;
        const int row = nt2 * 8 + (ln >> 2);
        const int f0 = fc * 16 + 2 * (ln & 3);
        uint2 p0 = pack_pair(lin2_w, row, 256, f0, 28, 256);
        uint2 p1 = pack_pair(lin2_w, row, 256, f0 + 8, 28, 256);
        reinterpret_cast<uint4*>(smc + W2F_B)[idx] = make_uint4(p0.x, p1.x, p0.y, p1.y);
    }
    for (int idx = tid; idx < 704; idx += 512) {         // Wqkv [84 r][28 e]
        const int ln = idx & 31, kt = (idx >> 5) & 1, nq = idx >> 6;
        const int row = nq * 8 + (ln >> 2);
        const int e0 = kt * 16 + 2 * (ln & 3);
        uint2 p0 = pack_pair(in_proj_w, row, 28, e0, 84, 28);
        uint2 p1 = pack_pair(in_proj_w, row, 28, e0 + 8, 84, 28);
        reinterpret_cast<uint4*>(smc + WQF_B)[idx] = make_uint4(p0.x, p1.x, p0.y, p1.y);
    }
    for (int idx = tid; idx < 256; idx += 512) {         // Wout [28 r][28 e]
        const int ln = idx & 31, nt = (idx >> 5) & 3, kt = idx >> 7;
        const int row = nt * 8 + (ln >> 2);
        const int e0 = kt * 16 + 2 * (ln & 3);
        uint2 p0 = pack_pair(out_proj_w, row, 28, e0, 28, 28);
        uint2 p1 = pack_pair(out_proj_w, row, 28, e0 + 8, 28, 28);
        reinterpret_cast<uint4*>(smc + WOF_B)[idx] = make_uint4(p0.x, p1.x, p0.y, p1.y);
    }
    __syncthreads();

    uint32_t* XHw = reinterpret_cast<uint32_t*>(smc + XH_B);
    uint32_t* XLw = reinterpret_cast<uint32_t*>(smc + XL_B);
    const uint4* W1F = reinterpret_cast<const uint4*>(smc + W1F_B);
    const uint4* W2F = reinterpret_cast<const uint4*>(smc + W2F_B);
    const uint4* WQF = reinterpret_cast<const uint4*>(smc + WQF_B);
    const uint4* WOF = reinterpret_cast<const uint4*>(smc + WOF_B);
    int* lens = reinterpret_cast<int*>(smf + I_LEN);
    int* vld  = reinterpret_cast<int*>(smf + I_VAL);

    const int l = lane & 7, h = lane >> 3, e0h = h * 7;
    const int gq = lane >> 2, tq = lane & 3;
    const int m0 = warp * 16;
    float* QW = smf + SCRF + warp * 1600;                 // [16 tok][100]: Q@0 K@32 V@64
    uint32_t* QWu = reinterpret_cast<uint32_t*>(QW);
    char* aobase = smc + SCR_B + warp * 6400;             // AO split lives in K slot

    for (int g = blockIdx.x; g < NG; g += gridDim.x) {
        // ---- (a) emb -> X bf16 hi/lo tiles (warp-private 16 tokens) ----
        {
            const float2* esrc = reinterpret_cast<const float2*>(emb + (g * 32 + warp * 2) * 224);
#pragma unroll
            for (int k2 = 0; k2 < 7; k2++) {
                const int idx2 = lane + k2 * 32;
                float2 v = esrc[idx2];
                const int fi = idx2 * 2;
                const int tok = fi / 28, e = fi % 28;
                const int word = (m0 + tok) * 18 + e / 2;
                split_pack2(v.x, v.y, XHw[word], XLw[word]);
            }
        }
        __syncwarp();

        // ---- (b) GEMM_QKV: [16 x 32] x Wqkv^T[88 x 32] ----
        {
            uint32_t ah[2][4], al[2][4];
#pragma unroll
            for (int kt = 0; kt < 2; kt++) {
                const int w0 = (m0 + gq) * 18 + kt * 8 + tq;
                ah[kt][0] = XHw[w0];       ah[kt][1] = XHw[w0 + 144];
                ah[kt][2] = XHw[w0 + 4];   ah[kt][3] = XHw[w0 + 148];
                al[kt][0] = XLw[w0];       al[kt][1] = XLw[w0 + 144];
                al[kt][2] = XLw[w0 + 4];   al[kt][3] = XLw[w0 + 148];
            }
#pragma unroll
            for (int nq = 0; nq < 11; nq++) {
                float d[4] = {0.0f, 0.0f, 0.0f, 0.0f};
#pragma unroll
                for (int kt = 0; kt < 2; kt++) {
                    const uint4 wf = WQF[(nq * 2 + kt) * 32 + lane];
                    mma_bf16(d, ah[kt][0], ah[kt][1], ah[kt][2], ah[kt][3], wf.x, wf.y);
                    mma_bf16(d, al[kt][0], al[kt][1], al[kt][2], al[kt][3], wf.x, wf.y);
                    mma_bf16(d, ah[kt][0], ah[kt][1], ah[kt][2], ah[kt][3], wf.z, wf.w);
                }
                const int c0 = nq * 8 + 2 * tq;
                if (c0 < 84) {
                    const int qk = c0 / 28, r = c0 % 28;
                    const int off = qk * 32 + (r / 7) * 8 + (r % 7);
                    const float bz = smf[F_BQKV + c0];
                    QW[gq * 100 + off]       = d[0] + bz;
                    QW[(gq + 8) * 100 + off] = d[2] + bz;
                }
                const int c1 = c0 + 1;
                if (c1 < 84) {
                    const int qk = c1 / 28, r = c1 % 28;
                    const int off = qk * 32 + (r / 7) * 8 + (r % 7);
                    const float bz = smf[F_BQKV + c1];
                    QW[gq * 100 + off]       = d[1] + bz;
                    QW[(gq + 8) * 100 + off] = d[3] + bz;
                }
            }
        }
        __syncwarp();

        // ---- (c) attention per span; ao -> bf16 split into K slot ----
        for (int j = 0; j < 2; j++) {
            const int sl = warp * 2 + j;
            const int span = g * 32 + sl;
            const int b = span >> 9, t = span & (T_ - 1);
            const int tok = j * 8 + l;
            const int len = span_lengths[span];

            float q[7];
            {
                const float4 qa = *reinterpret_cast<const float4*>(QW + tok * 100 + h * 8);
                const float4 qb = *reinterpret_cast<const float4*>(QW + tok * 100 + h * 8 + 4);
                q[0] = qa.x; q[1] = qa.y; q[2] = qa.z; q[3] = qa.w;
                q[4] = qb.x; q[5] = qb.y; q[6] = qb.z;
            }
            float s[8];
#pragma unroll
            for (int kk = 0; kk < 8; kk++) {
                const float4 ka = *reinterpret_cast<const float4*>(QW + (j * 8 + kk) * 100 + 32 + h * 8);
                const float4 kb = *reinterpret_cast<const float4*>(QW + (j * 8 + kk) * 100 + 32 + h * 8 + 4);
                float acc = q[0] * ka.x + q[1] * ka.y + q[2] * ka.z + q[3] * ka.w
                          + q[4] * kb.x + q[5] * kb.y + q[6] * kb.z;
                s[kk] = (kk < len) ? acc * 0.3779644730092272f : -1e9f;
            }
            __syncwarp();   // all K reads done before K slot is reused for AO
            float mx = s[0];
#pragma unroll
            for (int kk = 1; kk < 8; kk++) mx = fmaxf(mx, s[kk]);
            float p[8], ps = 0.0f;
#pragma unroll
            for (int kk = 0; kk < 8; kk++) { p[kk] = __expf(s[kk] - mx); ps += p[kk]; }
            const float pinv = 1.0f / ps;
            float ao[7];
#pragma unroll
            for (int d = 0; d < 7; d++) ao[d] = 0.0f;
#pragma unroll
            for (int kk = 0; kk < 8; kk++) {
                const float4 va = *reinterpret_cast<const float4*>(QW + (j * 8 + kk) * 100 + 64 + h * 8);
                const float4 vb = *reinterpret_cast<const float4*>(QW + (j * 8 + kk) * 100 + 64 + h * 8 + 4);
                ao[0] = fmaf(p[kk], va.x, ao[0]); ao[1] = fmaf(p[kk], va.y, ao[1]);
                ao[2] = fmaf(p[kk], va.z, ao[2]); ao[3] = fmaf(p[kk], va.w, ao[3]);
                ao[4] = fmaf(p[kk], vb.x, ao[4]); ao[5] = fmaf(p[kk], vb.y, ao[5]);
                ao[6] = fmaf(p[kk], vb.z, ao[6]);
            }
            // AO split store: AOH halves at bytes tok*400+128+e*2, AOL at +192+e*2
#pragma unroll
            for (int d = 0; d < 7; d++) {
                const int e = e0h + d;
                __nv_bfloat16 hh; float lf; split_bf16(ao[d] * pinv, hh, lf);
                *reinterpret_cast<__nv_bfloat16*>(aobase + tok * 400 + 128 + e * 2) = hh;
                *reinterpret_cast<__nv_bfloat16*>(aobase + tok * 400 + 192 + e * 2) = __float2bfloat16(lf);
            }
            if (lane == 0) { lens[sl] = len; vld[sl] = (t < num_spans[b]) ? 1 : 0; }
            __syncwarp();
        }
        // zero AO pad cols 28-31 (stale K data): floats 46,47 (AOH) / 62,63 (AOL)
        QW[(lane >> 1) * 100 + 46 + (lane & 1)] = 0.0f;
        QW[(lane >> 1) * 100 + 62 + (lane & 1)] = 0.0f;
        __syncwarp();

        // xn fragment registers (filled by GEMM_O, consumed by FFN + epilogue)
        uint32_t ah[2][4], al[2][4];

        // ---- (d) GEMM_O: [16 x 32] x Wout^T[32 x 32]; +bias +residual +LN1 -> ah/al regs ----
        {
            uint32_t aoh[2][4], aol[2][4];
#pragma unroll
            for (int kt = 0; kt < 2; kt++) {
                const int w0 = gq * 100 + 32 + kt * 8 + tq;
                aoh[kt][0] = QWu[w0];        aoh[kt][1] = QWu[w0 + 800];
                aoh[kt][2] = QWu[w0 + 4];    aoh[kt][3] = QWu[w0 + 804];
                aol[kt][0] = QWu[w0 + 16];   aol[kt][1] = QWu[w0 + 816];
                aol[kt][2] = QWu[w0 + 20];   aol[kt][3] = QWu[w0 + 820];
            }
            float dy[4][4];
#pragma unroll
            for (int nt = 0; nt < 4; nt++)
#pragma unroll
                for (int r = 0; r < 4; r++) dy[nt][r] = 0.0f;
#pragma unroll
            for (int kt = 0; kt < 2; kt++)
#pragma unroll
                for (int nt = 0; nt < 4; nt++) {
                    const uint4 wf = WOF[(kt * 4 + nt) * 32 + lane];
                    mma_bf16(dy[nt], aoh[kt][0], aoh[kt][1], aoh[kt][2], aoh[kt][3], wf.x, wf.y);
                    mma_bf16(dy[nt], aol[kt][0], aol[kt][1], aol[kt][2], aol[kt][3], wf.x, wf.y);
                    mma_bf16(dy[nt], aoh[kt][0], aoh[kt][1], aoh[kt][2], aoh[kt][3], wf.z, wf.w);
                }
            // bias + residual; LN1 stats for tokens gq (A) and gq+8 (B)
            const float* ebase = emb + (g * 32 + warp * 2) * 224;
            float yA[8], yB[8];
            float sA = 0.0f, qA2 = 0.0f, sB = 0.0f, qB2 = 0.0f;
#pragma unroll
            for (int nt = 0; nt < 4; nt++) {
                const int e0 = nt * 8 + 2 * tq;
                const bool ok = (nt < 3) || (tq < 2);
                float2 rA = make_float2(0.0f, 0.0f), rB = make_float2(0.0f, 0.0f);
                float bo0 = 0.0f, bo1 = 0.0f;
                if (ok) {
                    rA = *reinterpret_cast<const float2*>(ebase + gq * 28 + e0);
                    rB = *reinterpret_cast<const float2*>(ebase + (gq + 8) * 28 + e0);
                    bo0 = smf[F_BO + e0];
                    bo1 = smf[F_BO + e0 + 1];
                }
                float a0 = ok ? (dy[nt][0] + bo0 + rA.x) : 0.0f;
                float a1 = ok ? (dy[nt][1] + bo1 + rA.y) : 0.0f;
                float b0 = ok ? (dy[nt][2] + bo0 + rB.x) : 0.0f;
                float b1 = ok ? (dy[nt][3] + bo1 + rB.y) : 0.0f;
                yA[nt * 2] = a0; yA[nt * 2 + 1] = a1;
                yB[nt * 2] = b0; yB[nt * 2 + 1] = b1;
                sA += a0 + a1; qA2 += a0 * a0 + a1 * a1;
                sB += b0 + b1; qB2 += b0 * b0 + b1 * b1;
            }
            sA += __shfl_xor_sync(0xffffffffu, sA, 1); qA2 += __shfl_xor_sync(0xffffffffu, qA2, 1);
            sA += __shfl_xor_sync(0xffffffffu, sA, 2); qA2 += __shfl_xor_sync(0xffffffffu, qA2, 2);
            sB += __shfl_xor_sync(0xffffffffu, sB, 1); qB2 += __shfl_xor_sync(0xffffffffu, qB2, 1);
            sB += __shfl_xor_sync(0xffffffffu, sB, 2); qB2 += __shfl_xor_sync(0xffffffffu, qB2, 2);
            const float muA = sA * (1.0f / 28.0f), muB = sB * (1.0f / 28.0f);
            const float rsA = rsqrtf(fmaxf(qA2 * (1.0f / 28.0f) - muA * muA, 0.0f) + 1e-5f);
            const float rsB = rsqrtf(fmaxf(qB2 * (1.0f / 28.0f) - muB * muB, 0.0f) + 1e-5f);
#pragma unroll
            for (int nt = 0; nt < 4; nt++) {
                const int e0 = nt * 8 + 2 * tq;
                const bool ok = (nt < 3) || (tq < 2);
                const int ktX = nt >> 1, sl0 = (nt & 1) << 1;
                if (ok) {
                    const float g10 = smf[F_G1 + e0], g11 = smf[F_G1 + e0 + 1];
                    const float bl0 = smf[F_B1L + e0], bl1 = smf[F_B1L + e0 + 1];
                    float xA0 = (yA[nt * 2]     - muA) * rsA * g10 + bl0;
                    float xA1 = (yA[nt * 2 + 1] - muA) * rsA * g11 + bl1;
                    float xB0 = (yB[nt * 2]     - muB) * rsB * g10 + bl0;
                    float xB1 = (yB[nt * 2 + 1] - muB) * rsB * g11 + bl1;
                    split_pack2(xA0, xA1, ah[ktX][sl0],     al[ktX][sl0]);
                    split_pack2(xB0, xB1, ah[ktX][sl0 + 1], al[ktX][sl0 + 1]);
                } else {
                    ah[ktX][sl0] = 0u; ah[ktX][sl0 + 1] = 0u;
                    al[ktX][sl0] = 0u; al[ktX][sl0 + 1] = 0u;
                }
            }
        }
        __syncwarp();   // QW reads complete before next group's scatter

        // ---------------- PHASE 2: FFN via mma.sync (A-frags already in ah/al) ----------------
        float d2[4][4];
#pragma unroll
        for (int nt = 0; nt < 4; nt++)
#pragma unroll
            for (int r = 0; r < 4; r++) d2[nt][r] = 0.0f;

#pragma unroll 4
        for (int fc = 0; fc < 16; fc++) {
            float d1[2][4];
#pragma unroll
            for (int nt = 0; nt < 2; nt++)
#pragma unroll
                for (int r = 0; r < 4; r++) d1[nt][r] = 0.0f;
#pragma unroll
            for (int kt = 0; kt < 2; kt++)
#pragma unroll
                for (int nt = 0; nt < 2; nt++) {
                    const uint4 wf = W1F[((fc * 2 + kt) * 2 + nt) * 32 + lane];
                    mma_bf16(d1[nt], ah[kt][0], ah[kt][1], ah[kt][2], ah[kt][3], wf.x, wf.y);
                    mma_bf16(d1[nt], al[kt][0], al[kt][1], al[kt][2], al[kt][3], wf.x, wf.y);
                    mma_bf16(d1[nt], ah[kt][0], ah[kt][1], ah[kt][2], ah[kt][3], wf.z, wf.w);
                }
            uint32_t a2h[4], a2l[4];
#pragma unroll
            for (int nt = 0; nt < 2; nt++) {
                const int fe = fc * 16 + nt * 8 + 2 * tq;
                const float bz0 = smf[F_B1 + fe], bz1 = smf[F_B1 + fe + 1];
                float h0 = fmaxf(d1[nt][0] + bz0, 0.0f);
                float h1 = fmaxf(d1[nt][1] + bz1, 0.0f);
                float h2 = fmaxf(d1[nt][2] + bz0, 0.0f);
                float h3 = fmaxf(d1[nt][3] + bz1, 0.0f);
                split_pack2(h0, h1, a2h[nt * 2 + 0], a2l[nt * 2 + 0]);
                split_pack2(h2, h3, a2h[nt * 2 + 1], a2l[nt * 2 + 1]);
            }
#pragma unroll
            for (int nt2 = 0; nt2 < 4; nt2++) {
                const uint4 wf = W2F[(fc * 4 + nt2) * 32 + lane];
                mma_bf16(d2[nt2], a2h[0], a2h[1], a2h[2], a2h[3], wf.x, wf.y);
                mma_bf16(d2[nt2], a2l[0], a2l[1], a2l[2], a2l[3], wf.x, wf.y);
                mma_bf16(d2[nt2], a2h[0], a2h[1], a2h[2], a2h[3], wf.z, wf.w);
            }
        }

        // ---------------- EPILOGUE: one span at a time (xn from ah/al regs) -------------
#pragma unroll
        for (int sp2 = 0; sp2 < 2; sp2++) {
            const int sl = warp * 2 + sp2;
            const int c0 = sp2 * 2;
            float v[8];
            float ssum = 0.0f, sq = 0.0f;
#pragma unroll
            for (int nt = 0; nt < 4; nt++) {
                const int e0 = nt * 8 + 2 * tq;
                const bool ok = (nt < 3) || (tq < 2);
                const int ktE = nt >> 1, slot = ((nt & 1) << 1) + sp2;
                const uint32_t uh = ah[ktE][slot];
                const uint32_t ul = al[ktE][slot];
                const __nv_bfloat162 bh = *reinterpret_cast<const __nv_bfloat162*>(&uh);
                const __nv_bfloat162 bl = *reinterpret_cast<const __nv_bfloat162*>(&ul);
                const float xn0 = __bfloat162float(bh.x) + __bfloat162float(bl.x);
                const float xn1 = __bfloat162float(bh.y) + __bfloat162float(bl.y);
                float a0 = ok ? (d2[nt][c0]     + smf[F_B2 + e0]     + xn0) : 0.0f;
                float a1 = ok ? (d2[nt][c0 + 1] + smf[F_B2 + e0 + 1] + xn1) : 0.0f;
                v[nt * 2] = a0; v[nt * 2 + 1] = a1;
                ssum += a0 + a1; sq += a0 * a0 + a1 * a1;
            }
            ssum += __shfl_xor_sync(0xffffffffu, ssum, 1); sq += __shfl_xor_sync(0xffffffffu, sq, 1);
            ssum += __shfl_xor_sync(0xffffffffu, ssum, 2); sq += __shfl_xor_sync(0xffffffffu, sq, 2);
            const float mu = ssum * (1.0f / 28.0f);
            const float rs = rsqrtf(fmaxf(sq * (1.0f / 28.0f) - mu * mu, 0.0f) + 1e-5f);
            const int len = lens[sl];
            const float m = (gq < len) ? 1.0f : 0.0f;
            float pz[8];
#pragma unroll
            for (int nt = 0; nt < 4; nt++) {
                const int e0 = nt * 8 + 2 * tq;
                const bool ok = (nt < 3) || (tq < 2);
                pz[nt * 2]     = ok ? ((v[nt * 2]     - mu) * rs * smf[F_G2 + e0]     + smf[F_B2L + e0])     * m : 0.0f;
                pz[nt * 2 + 1] = ok ? ((v[nt * 2 + 1] - mu) * rs * smf[F_G2 + e0 + 1] + smf[F_B2L + e0 + 1]) * m : 0.0f;
            }
#pragma unroll
            for (int i = 0; i < 8; i++) {
                float a = pz[i];
                a += __shfl_xor_sync(0xffffffffu, a, 4);
                a += __shfl_xor_sync(0xffffffffu, a, 8);
                a += __shfl_xor_sync(0xffffffffu, a, 16);
                pz[i] = a;
            }
            if (lane < 4) {
                const float il = 1.0f / (float)len;
                const int sp = g * 32 + sl;
                const int okv = vld[sl];
#pragma unroll
                for (int nt = 0; nt < 4; nt++) {
                    const int e0 = nt * 8 + 2 * tq;
                    if ((nt < 3) || (tq < 2)) {
                        outp[sp * 28 + e0]     = okv ? pz[nt * 2] * il     : smf[F_PAD + e0];
                        outp[sp * 28 + e0 + 1] = okv ? pz[nt * 2 + 1] * il : smf[F_PAD + e0 + 1];
                    }
                }
            }
        }
        __syncwarp();
    }
}

extern "C" void kernel_launch(void* const* d_in, const int* in_sizes, int n_in,
                              void* d_out, int out_size) {
    const float* emb          = (const float*)d_in[0];
    const int*   span_lengths = (const int*)  d_in[1];
    const int*   num_spans    = (const int*)  d_in[2];
    const float* in_proj_w    = (const float*)d_in[3];
    const float* in_proj_b    = (const float*)d_in[4];
    const float* out_proj_w   = (const float*)d_in[5];
    const float* out_proj_b   = (const float*)d_in[6];
    const float* ln1_g        = (const float*)d_in[7];
    const float* ln1_b        = (const float*)d_in[8];
    const float* lin1_w       = (const float*)d_in[9];
    const float* lin1_b       = (const float*)d_in[10];
    const float* lin2_w       = (const float*)d_in[11];
    const float* lin2_b       = (const float*)d_in[12];
    const float* ln2_g        = (const float*)d_in[13];
    const float* ln2_b        = (const float*)d_in[14];
    const float* pad_token    = (const float*)d_in[15];
    float* outp = (float*)d_out;

    cudaFuncSetAttribute(span_mma_kernel,
                         cudaFuncAttributeMaxDynamicSharedMemorySize, SMEM_END_B);

    span_mma_kernel<<<148, 512, SMEM_END_B>>>(
        emb, span_lengths, num_spans,
        in_proj_w, in_proj_b, out_proj_w, out_proj_b,
        ln1_g, ln1_b, lin1_w, lin1_b, lin2_w, lin2_b,
        ln2_g, ln2_b, pad_token, outp);
}